// round 9
// baseline (speedup 1.0000x reference)
#include <cuda_runtime.h>
#include <cuda_bf16.h>
#include <math.h>
#include <cstdint>

#define HH   8
#define Dm   512
#define DFFm 2048
#define BB   8
#define TT   1024
#define BT   (BB*TT)
#define EPSv 1e-5f

typedef __nv_bfloat16 bf16;
typedef signed char i8;

// ---------------- scratch (static __device__, allocation-free) ----------------
// bf16 planes (only for tiny Mt/Nt precompute GEMMs)
__device__ bf16 g_Wqh[HH*Dm*Dm], g_Wql[HH*Dm*Dm];
__device__ bf16 g_Wkh[HH*Dm*Dm], g_Wkl[HH*Dm*Dm];
__device__ bf16 g_Wvh[HH*Dm*Dm], g_Wvl[HH*Dm*Dm];
__device__ bf16 g_WoTh[Dm*HH*Dm], g_WoTl[Dm*HH*Dm];
// fp32 intermediates
__device__ float g_Mtf[HH*Dm*Dm], g_Ntf[HH*Dm*Dm];
__device__ float g_w0[HH*Dm], g_ccp[HH*Dm];
__device__ float g_u[(size_t)HH*BT*Dm];
__device__ float g_zt[(size_t)HH*BT*Dm];           // [H,B,D,T]
__device__ float g_s[(size_t)HH*BB*TT*TT];         // 256 MB scores
__device__ float g_parts[(size_t)HH*BT*Dm];
__device__ float g_y1[BT*Dm];
__device__ float g_f1[(size_t)BT*DFFm];
__device__ float g_W1T[DFFm*Dm], g_W2T[Dm*DFFm];
__device__ float g_ff2[BT*Dm];
// int8 two-slice operands + per-row scales
__device__ i8 g_xqh[BT*Dm], g_xql[BT*Dm];           __device__ float g_sx[BT];
__device__ i8 g_Mtqh[HH*Dm*Dm], g_Mtql[HH*Dm*Dm];   __device__ float g_sMt[HH*Dm];
__device__ i8 g_uqh[(size_t)HH*BT*Dm], g_uql[(size_t)HH*BT*Dm]; __device__ float g_su[HH*BT];
__device__ i8 g_Ntqh[HH*Dm*Dm], g_Ntql[HH*Dm*Dm];   __device__ float g_sNt[HH*Dm];
__device__ i8 g_ztqh[(size_t)HH*BT*Dm], g_ztql[(size_t)HH*BT*Dm]; __device__ float g_szt[HH*BB*Dm];
__device__ i8 g_Pqh[(size_t)HH*BB*TT*TT], g_Pql[(size_t)HH*BB*TT*TT]; __device__ float g_sP[HH*BB*TT];
__device__ i8 g_y1qh[BT*Dm], g_y1ql[BT*Dm];         __device__ float g_sy1[BT];
__device__ i8 g_f1qh[(size_t)BT*DFFm], g_f1ql[(size_t)BT*DFFm]; __device__ float g_sf1[BT];
__device__ i8 g_W1Tqh[DFFm*Dm], g_W1Tql[DFFm*Dm];   __device__ float g_sW1[DFFm];
__device__ i8 g_W2Tqh[Dm*DFFm], g_W2Tql[Dm*DFFm];   __device__ float g_sW2[Dm];

// ---------------- common helpers ----------------
__device__ __forceinline__ uint32_t smem_u32(const void* p) {
    uint32_t a;
    asm("{ .reg .u64 t; cvta.to.shared.u64 t, %1; cvt.u32.u64 %0, t; }" : "=r"(a) : "l"(p));
    return a;
}
#define CPASYNC16(sa, ga) \
    asm volatile("cp.async.ca.shared.global [%0], [%1], 16;" :: "r"(sa), "l"(ga) : "memory")
#define CP_COMMIT() asm volatile("cp.async.commit_group;" ::: "memory")
#define CP_WAIT1()  asm volatile("cp.async.wait_group 1;" ::: "memory")
#define CP_WAIT0()  asm volatile("cp.async.wait_group 0;" ::: "memory")
#define LDSM4(r, addr) \
    asm volatile("ldmatrix.sync.aligned.m8n8.x4.shared.b16 {%0,%1,%2,%3}, [%4];" \
        : "=r"((r)[0]), "=r"((r)[1]), "=r"((r)[2]), "=r"((r)[3]) : "r"(addr))

__device__ __forceinline__ void mma16816(float* c, const uint32_t* a, const uint32_t* b) {
    asm volatile("mma.sync.aligned.m16n8k16.row.col.f32.bf16.bf16.f32 "
        "{%0,%1,%2,%3}, {%4,%5,%6,%7}, {%8,%9}, {%0,%1,%2,%3};"
        : "+f"(c[0]), "+f"(c[1]), "+f"(c[2]), "+f"(c[3])
        : "r"(a[0]), "r"(a[1]), "r"(a[2]), "r"(a[3]), "r"(b[0]), "r"(b[1]));
}
__device__ __forceinline__ void mma_i8(int32_t* c, const uint32_t* a, const uint32_t* b) {
    asm volatile("mma.sync.aligned.m16n8k32.row.col.s32.s8.s8.s32 "
        "{%0,%1,%2,%3}, {%4,%5,%6,%7}, {%8,%9}, {%0,%1,%2,%3};"
        : "+r"(c[0]), "+r"(c[1]), "+r"(c[2]), "+r"(c[3])
        : "r"(a[0]), "r"(a[1]), "r"(a[2]), "r"(a[3]), "r"(b[0]), "r"(b[1]));
}

#define STAGE_BYTES 24576
#define PLANE_BYTES 6144
#define ROW_BYTES   48
#define SMEM_BYTES  49152

// ============ bf16x3 GEMM (kept for tiny Mt/Nt precompute), fp32 out ============
__global__ void __launch_bounds__(256)
gemm_mma(const bf16* __restrict__ Ah, const bf16* __restrict__ Al,
         const bf16* __restrict__ Bh, const bf16* __restrict__ Bl,
         float* __restrict__ Cf,
         int K, int lda, int ldb, int ldc,
         long sA, long sB, long sC_outer)
{
    extern __shared__ char smem[];
    const uint32_t sb = smem_u32(smem);
    const int tid = threadIdx.x, lane = tid & 31, wid = tid >> 5;
    const int wm = wid >> 2, wn = wid & 3;
    const int z = blockIdx.z;
    const bf16* Abh = Ah + (long)z * sA;
    const bf16* Abl = Al + (long)z * sA;
    const bf16* Bbh = Bh + (long)z * sB;
    const bf16* Bbl = Bl + (long)z * sB;
    long coff = (long)z * sC_outer;
    const int mBase = blockIdx.y * 128;
    const int nBase = blockIdx.x * 128;

    const int lrow = tid >> 1;
    const int lco  = (tid & 1) * 8;
    const uint32_t ssub = (uint32_t)lrow * ROW_BYTES + (tid & 1) * 16;
    const long gA = (long)(mBase + lrow) * lda + lco;
    const long gB = (long)(nBase + lrow) * ldb + lco;

    float acc[4][4][4];
    #pragma unroll
    for (int i = 0; i < 4; i++)
        #pragma unroll
        for (int j = 0; j < 4; j++)
            #pragma unroll
            for (int r = 0; r < 4; r++) acc[i][j][r] = 0.f;

    const int nStages = K >> 4;
    {
        uint32_t base = sb;
        CPASYNC16(base + ssub,                   (const char*)(Abh + gA));
        CPASYNC16(base + PLANE_BYTES + ssub,     (const char*)(Abl + gA));
        CPASYNC16(base + 2*PLANE_BYTES + ssub,   (const char*)(Bbh + gB));
        CPASYNC16(base + 3*PLANE_BYTES + ssub,   (const char*)(Bbl + gB));
        CP_COMMIT();
    }
    const uint32_t aoff = (uint32_t)(lane & 15) * ROW_BYTES + (lane >> 4) * 16;
    const int nrow  = (lane & 7) + ((lane >> 4) << 3);
    const int khalf = (lane >> 3) & 1;
    const uint32_t boff = (uint32_t)nrow * ROW_BYTES + khalf * 16;

    for (int s = 0; s < nStages; s++) {
        if (s + 1 < nStages) {
            uint32_t base = sb + ((s + 1) & 1) * STAGE_BYTES;
            long k0 = (long)(s + 1) << 4;
            CPASYNC16(base + ssub,                 (const char*)(Abh + gA + k0));
            CPASYNC16(base + PLANE_BYTES + ssub,   (const char*)(Abl + gA + k0));
            CPASYNC16(base + 2*PLANE_BYTES + ssub, (const char*)(Bbh + gB + k0));
            CPASYNC16(base + 3*PLANE_BYTES + ssub, (const char*)(Bbl + gB + k0));
            CP_COMMIT();
            CP_WAIT1();
        } else {
            CP_WAIT0();
        }
        __syncthreads();
        const uint32_t base = sb + (s & 1) * STAGE_BYTES;
        uint32_t ah[4][4], al[4][4];
        #pragma unroll
        for (int mi = 0; mi < 4; mi++) {
            uint32_t o = base + (uint32_t)(wm * 64 + mi * 16) * ROW_BYTES + aoff;
            LDSM4(ah[mi], o);
            LDSM4(al[mi], o + PLANE_BYTES);
        }
        uint32_t bh[2][4], bl[2][4];
        #pragma unroll
        for (int p = 0; p < 2; p++) {
            uint32_t o = base + 2*PLANE_BYTES + (uint32_t)(wn * 32 + p * 16) * ROW_BYTES + boff;
            LDSM4(bh[p], o);
            LDSM4(bl[p], o + PLANE_BYTES);
        }
        #pragma unroll
        for (int mi = 0; mi < 4; mi++)
            #pragma unroll
            for (int p = 0; p < 2; p++)
                #pragma unroll
                for (int s2 = 0; s2 < 2; s2++) {
                    const int ni = p * 2 + s2;
                    mma16816(acc[mi][ni], ah[mi], &bh[p][s2 * 2]);
                    mma16816(acc[mi][ni], al[mi], &bh[p][s2 * 2]);
                    mma16816(acc[mi][ni], ah[mi], &bl[p][s2 * 2]);
                }
        __syncthreads();
    }
    const int er = mBase + wm * 64 + (lane >> 2);
    const int ec = nBase + wn * 32 + (lane & 3) * 2;
    #pragma unroll
    for (int mi = 0; mi < 4; mi++)
        #pragma unroll
        for (int ni = 0; ni < 4; ni++)
            #pragma unroll
            for (int half = 0; half < 2; half++) {
                const int gr = er + mi * 16 + half * 8;
                const int gc = ec + ni * 8;
                float2 f;
                f.x = acc[mi][ni][half * 2 + 0];
                f.y = acc[mi][ni][half * 2 + 1];
                *(float2*)(Cf + coff + (long)gr * ldc + gc) = f;
            }
}

// ============ int8 two-slice GEMM: C = alpha*sa*sb*(A@B^T) + bias ============
// A slices [M,K] (lda), B slices [N,K] (ldb), per-row scales Sa/Sb.
// EPI: 1 = fp32 C row-major; 4 = fp32 transposed write [z][b][d][t]
template<int EPI>
__global__ void __launch_bounds__(256)
gemm_i8(const i8* __restrict__ Ah, const i8* __restrict__ Al, const float* __restrict__ Sa,
        const i8* __restrict__ Bh, const i8* __restrict__ Bl, const float* __restrict__ Sb,
        const float* __restrict__ bias, float* __restrict__ Cf,
        int K, int lda, int ldb, int ldc,
        long sA, long sB, int modB, long sSA, long sSB, long sBias,
        long sC_outer, float alpha)
{
    extern __shared__ char smem[];
    const uint32_t sb = smem_u32(smem);
    const int tid = threadIdx.x, lane = tid & 31, wid = tid >> 5;
    const int wm = wid >> 2, wn = wid & 3;
    const int z = blockIdx.z;
    const int zb = (modB > 0) ? (z % modB) : z;

    const i8* Abh = Ah + (long)z * sA;
    const i8* Abl = Al + (long)z * sA;
    const i8* Bbh = Bh + (long)zb * sB;
    const i8* Bbl = Bl + (long)zb * sB;
    const float* biasb = bias ? (bias + (long)z * sBias) : nullptr;
    const long coff = (long)z * sC_outer;

    const int mBase = blockIdx.y * 128;
    const int nBase = blockIdx.x * 128;

    // loader: 32 payload bytes per 48-byte row, 2 chunks/row, 1 chunk/thread/plane
    const int lrow = tid >> 1;
    const int lco  = (tid & 1) * 16;
    const uint32_t ssub = (uint32_t)lrow * ROW_BYTES + lco;
    const long gA = (long)(mBase + lrow) * lda + lco;
    const long gB = (long)(nBase + lrow) * ldb + lco;

    int32_t ahh[4][4][4], acx[4][4][4];
    #pragma unroll
    for (int i = 0; i < 4; i++)
        #pragma unroll
        for (int j = 0; j < 4; j++)
            #pragma unroll
            for (int r = 0; r < 4; r++) { ahh[i][j][r] = 0; acx[i][j][r] = 0; }

    const int nStages = K >> 5;
    {
        uint32_t base = sb;
        CPASYNC16(base + ssub,                 (const char*)(Abh + gA));
        CPASYNC16(base + PLANE_BYTES + ssub,   (const char*)(Abl + gA));
        CPASYNC16(base + 2*PLANE_BYTES + ssub, (const char*)(Bbh + gB));
        CPASYNC16(base + 3*PLANE_BYTES + ssub, (const char*)(Bbl + gB));
        CP_COMMIT();
    }
    // ldmatrix lane maps (int8 k32 fragments via b16 ldmatrix)
    const uint32_t aoff = (uint32_t)((lane & 7) + 8 * ((lane >> 3) & 1)) * ROW_BYTES
                        + ((lane >> 4) * 16);
    const uint32_t boff = (uint32_t)((lane & 7) + 8 * ((lane >> 4) & 1)) * ROW_BYTES
                        + (((lane >> 3) & 1) * 16);

    for (int s = 0; s < nStages; s++) {
        if (s + 1 < nStages) {
            uint32_t base = sb + ((s + 1) & 1) * STAGE_BYTES;
            long k0 = (long)(s + 1) << 5;
            CPASYNC16(base + ssub,                 (const char*)(Abh + gA + k0));
            CPASYNC16(base + PLANE_BYTES + ssub,   (const char*)(Abl + gA + k0));
            CPASYNC16(base + 2*PLANE_BYTES + ssub, (const char*)(Bbh + gB + k0));
            CPASYNC16(base + 3*PLANE_BYTES + ssub, (const char*)(Bbl + gB + k0));
            CP_COMMIT();
            CP_WAIT1();
        } else {
            CP_WAIT0();
        }
        __syncthreads();

        const uint32_t base = sb + (s & 1) * STAGE_BYTES;
        uint32_t ah[4][4], al[4][4];
        #pragma unroll
        for (int mi = 0; mi < 4; mi++) {
            uint32_t o = base + (uint32_t)(wm * 64 + mi * 16) * ROW_BYTES + aoff;
            LDSM4(ah[mi], o);
            LDSM4(al[mi], o + PLANE_BYTES);
        }
        uint32_t bh[2][4], bl[2][4];
        #pragma unroll
        for (int p = 0; p < 2; p++) {
            uint32_t o = base + 2*PLANE_BYTES + (uint32_t)(wn * 32 + p * 16) * ROW_BYTES + boff;
            LDSM4(bh[p], o);
            LDSM4(bl[p], o + PLANE_BYTES);
        }
        // regs: [0]=(n0-7,k0-15) [1]=(n0-7,k16-31) [2]=(n8-15,k0) [3]=(n8-15,k16)
        #pragma unroll
        for (int mi = 0; mi < 4; mi++)
            #pragma unroll
            for (int p = 0; p < 2; p++)
                #pragma unroll
                for (int tt = 0; tt < 2; tt++) {
                    const int ni = p * 2 + tt;
                    mma_i8(ahh[mi][ni], ah[mi], &bh[p][tt * 2]);
                    mma_i8(acx[mi][ni], ah[mi], &bl[p][tt * 2]);
                    mma_i8(acx[mi][ni], al[mi], &bh[p][tt * 2]);
                }
        __syncthreads();
    }

    const int er = mBase + wm * 64 + (lane >> 2);
    const int ec = nBase + wn * 32 + (lane & 3) * 2;
    #pragma unroll
    for (int mi = 0; mi < 4; mi++) {
        #pragma unroll
        for (int half = 0; half < 2; half++) {
            const int gr = er + mi * 16 + half * 8;
            const float sa = __ldg(&Sa[(long)z * sSA + gr]) * alpha;
            #pragma unroll
            for (int ni = 0; ni < 4; ni++) {
                const int gc = ec + ni * 8;
                const float sb0 = __ldg(&Sb[(long)zb * sSB + gc]);
                const float sb1 = __ldg(&Sb[(long)zb * sSB + gc + 1]);
                float v0 = (16384.f * (float)ahh[mi][ni][half*2+0]
                           + 128.f * (float)acx[mi][ni][half*2+0]) * sa * sb0;
                float v1 = (16384.f * (float)ahh[mi][ni][half*2+1]
                           + 128.f * (float)acx[mi][ni][half*2+1]) * sa * sb1;
                if (biasb) { v0 += __ldg(&biasb[gc]); v1 += __ldg(&biasb[gc + 1]); }
                if (EPI == 4) {
                    const long zbse = (long)z * ((long)BB * Dm * TT)
                                    + (long)(gr >> 10) * ((long)Dm * TT);
                    const long t = gr & 1023;
                    Cf[zbse + (long)gc * TT + t] = v0;
                    Cf[zbse + (long)(gc + 1) * TT + t] = v1;
                } else {
                    float2 f; f.x = v0; f.y = v1;
                    *(float2*)(Cf + coff + (long)gr * ldc + gc) = f;
                }
            }
        }
    }
}

// ---------------- block reductions ----------------
__device__ __forceinline__ float block_sum(float v, float* sm) {
    #pragma unroll
    for (int o = 16; o; o >>= 1) v += __shfl_xor_sync(0xffffffffu, v, o);
    if ((threadIdx.x & 31) == 0) sm[threadIdx.x >> 5] = v;
    __syncthreads();
    if (threadIdx.x < 8) {
        float s = sm[threadIdx.x];
        #pragma unroll
        for (int o = 4; o; o >>= 1) s += __shfl_xor_sync(0xffu, s, o);
        if (threadIdx.x == 0) sm[0] = s;
    }
    __syncthreads();
    float r = sm[0];
    __syncthreads();
    return r;
}
__device__ __forceinline__ float block_max(float v, float* sm) {
    #pragma unroll
    for (int o = 16; o; o >>= 1) v = fmaxf(v, __shfl_xor_sync(0xffffffffu, v, o));
    if ((threadIdx.x & 31) == 0) sm[threadIdx.x >> 5] = v;
    __syncthreads();
    if (threadIdx.x < 8) {
        float s = sm[threadIdx.x];
        #pragma unroll
        for (int o = 4; o; o >>= 1) s = fmaxf(s, __shfl_xor_sync(0xffu, s, o));
        if (threadIdx.x == 0) sm[0] = s;
    }
    __syncthreads();
    float r = sm[0];
    __syncthreads();
    return r;
}

__device__ __forceinline__ void quant1(float v, float s, float inv128s, float invs,
                                       i8* qh, i8* ql, long idx) {
    int q = __float2int_rn(v * inv128s);
    q = max(-127, min(127, q));
    float rem = v - (float)q * (128.f * s);
    int r = __float2int_rn(rem * invs);
    r = max(-127, min(127, r));
    qh[idx] = (i8)q; ql[idx] = (i8)r;
}

// ---------------- rowquant: fp32 [rows, cols] -> int8 slices + scale ----------------
__global__ void __launch_bounds__(256)
rowquant(const float* __restrict__ in, i8* __restrict__ qh, i8* __restrict__ ql,
         float* __restrict__ sc, int cols)
{
    __shared__ float sm[8];
    const long row = blockIdx.x;
    const float* p = in + row * (long)cols;
    const int t = threadIdx.x;
    const int per = cols >> 8;
    float v[8];
    float m = 0.f;
    for (int i = 0; i < per; i++) { v[i] = p[t + i * 256]; m = fmaxf(m, fabsf(v[i])); }
    m = block_max(m, sm);
    float s = (m > 0.f) ? (m * (1.f / 16256.f)) : 1.f;
    if (t == 0) sc[row] = s;
    float invs = 1.f / s;
    float inv128s = invs * (1.f / 128.f);
    for (int i = 0; i < per; i++)
        quant1(v[i], s, inv128s, invs, qh, ql, row * (long)cols + t + i * 256);
}

// ---------------- fp32 transpose (for W1T / W2T) ----------------
__global__ void __launch_bounds__(256)
ttrans(const float* __restrict__ in, float* __restrict__ outp, int R, int C)
{
    __shared__ float tbuf[32][33];
    const int cb = blockIdx.x * 32, rb = blockIdx.y * 32;
    const int x = threadIdx.x & 31, y = threadIdx.x >> 5;
    #pragma unroll
    for (int i = 0; i < 32; i += 8)
        tbuf[y + i][x] = in[(long)(rb + y + i) * C + cb + x];
    __syncthreads();
    #pragma unroll
    for (int i = 0; i < 32; i += 8)
        outp[(long)(cb + y + i) * R + rb + x] = tbuf[x][y + i];
}

// ---------------- splits (bf16 planes for precompute GEMMs) ----------------
__global__ void __launch_bounds__(256)
esplit(const float* __restrict__ in, bf16* __restrict__ oh, bf16* __restrict__ ol, int n)
{
    int i = blockIdx.x * 256 + threadIdx.x;
    if (i < n) {
        float v = in[i];
        bf16 h = __float2bfloat16_rn(v);
        oh[i] = h;
        ol[i] = __float2bfloat16_rn(v - __bfloat162float(h));
    }
}
__global__ void __launch_bounds__(256)
tsplit(const float* __restrict__ in, bf16* __restrict__ oh, bf16* __restrict__ ol,
       int R, int C)
{
    __shared__ float t[32][33];
    const int cb = blockIdx.x * 32, rb = blockIdx.y * 32;
    const int x = threadIdx.x & 31, y = threadIdx.x >> 5;
    #pragma unroll
    for (int i = 0; i < 32; i += 8)
        t[y + i][x] = in[(long)(rb + y + i) * C + cb + x];
    __syncthreads();
    #pragma unroll
    for (int i = 0; i < 32; i += 8) {
        float v = t[x][y + i];
        bf16 h = __float2bfloat16_rn(v);
        long o = (long)(cb + y + i) * R + rb + x;
        oh[o] = h;
        ol[o] = __float2bfloat16_rn(v - __bfloat162float(h));
    }
}

// ---------------- vecprep: w0[h,d] = Wk_h[d,:]·bq_h ; ccp[h,e] = bv_h·Wo_h[:,e] ----------------
__global__ void __launch_bounds__(256)
vecprep(const float* __restrict__ Wk, const float* __restrict__ bq,
        const float* __restrict__ Wo, const float* __restrict__ bv,
        float* __restrict__ w0, float* __restrict__ ccp)
{
    const int bb = blockIdx.x;
    if (bb < 512) {
        const int wid = threadIdx.x >> 5, lane = threadIdx.x & 31;
        const int idx = bb * 8 + wid;
        const int h = idx >> 9, d = idx & 511;
        const float* wr = Wk + (long)h * Dm * Dm + (long)d * Dm;
        const float* bqr = bq + h * Dm;
        float s = 0.f;
        #pragma unroll
        for (int e = lane; e < Dm; e += 32) s += wr[e] * bqr[e];
        #pragma unroll
        for (int o = 16; o; o >>= 1) s += __shfl_xor_sync(0xffffffffu, s, o);
        if (lane == 0) w0[idx] = s;
    } else {
        // 64 blocks: (h, 64-wide e-chunk); 4 m-slices of 128 in parallel
        __shared__ float part[4][64];
        const int ib = bb - 512;
        const int h = ib >> 3, chunk = ib & 7;
        const int e = chunk * 64 + (threadIdx.x & 63);
        const int ms = threadIdx.x >> 6;
        const float* Woh = Wo + (long)h * Dm * Dm;
        const float* bvh = bv + h * Dm;
        float s = 0.f;
        for (int m = ms * 128; m < ms * 128 + 128; m++)
            s += bvh[m] * Woh[(long)m * Dm + e];
        part[ms][threadIdx.x & 63] = s;
        __syncthreads();
        if (threadIdx.x < 64)
            ccp[h * Dm + chunk * 64 + threadIdx.x] =
                part[0][threadIdx.x] + part[1][threadIdx.x] +
                part[2][threadIdx.x] + part[3][threadIdx.x];
    }
}

// ---------------- softmax (fp32 scores -> int8 prob slices, exact p_max scale) ----------------
__global__ void __launch_bounds__(256)
softmax_kernel(const float* __restrict__ S, i8* __restrict__ Ph, i8* __restrict__ Pl,
               float* __restrict__ sc)
{
    __shared__ float sm[8];
    const size_t base = (size_t)blockIdx.x * TT;
    const float* p = S + base;
    int t = threadIdx.x;
    float x0 = p[t], x1 = p[t + 256], x2 = p[t + 512], x3 = p[t + 768];
    float m = block_max(fmaxf(fmaxf(x0, x1), fmaxf(x2, x3)), sm);
    float e0 = __expf(x0 - m), e1 = __expf(x1 - m);
    float e2 = __expf(x2 - m), e3 = __expf(x3 - m);
    float Z = block_sum(e0 + e1 + e2 + e3, sm);
    float inv = 1.f / Z;
    if (t == 0) sc[blockIdx.x] = inv * (1.f / 16256.f);
    #pragma unroll
    for (int q = 0; q < 4; q++) {
        float e = (q == 0 ? e0 : q == 1 ? e1 : q == 2 ? e2 : e3);
        int qh = __float2int_rn(e * 127.f);
        int ql = __float2int_rn(e * 16256.f - (float)qh * 128.f);
        ql = max(-127, min(127, ql));
        size_t idx = base + t + q * 256;
        Ph[idx] = (i8)qh; Pl[idx] = (i8)ql;
    }
}

// ---------------- reduce heads + consts + residual + LN1 -> y1 fp32 + int8 ----------------
__global__ void __launch_bounds__(256)
reduce_ln1(const float* __restrict__ parts, const float* __restrict__ x,
           const float* __restrict__ ccp, const float* __restrict__ bo,
           const float* __restrict__ g, const float* __restrict__ be,
           float* __restrict__ out, i8* __restrict__ qh, i8* __restrict__ ql,
           float* __restrict__ sc)
{
    __shared__ float sm[8];
    const long row = blockIdx.x;
    const long b = row >> 10, t0 = row & 1023;
    const int t = threadIdx.x;
    float v0, v1;
    {
        float c0 = bo[t], c1 = bo[t + 256];
        #pragma unroll
        for (int h = 0; h < HH; h++) {
            c0 += ccp[h * Dm + t];
            c1 += ccp[h * Dm + t + 256];
        }
        v0 = x[row * Dm + t] + c0;
        v1 = x[row * Dm + t + 256] + c1;
        #pragma unroll
        for (int h = 0; h < HH; h++) {
            const long pr = (((long)h * BB + b) * TT + t0) * Dm;
            v0 += parts[pr + t];
            v1 += parts[pr + t + 256];
        }
    }
    float mean = block_sum(v0 + v1, sm) * (1.f / Dm);
    float d0 = v0 - mean, d1 = v1 - mean;
    float var = block_sum(d0 * d0 + d1 * d1, sm) * (1.f / Dm);
    float inv = rsqrtf(var + EPSv);
    float o0 = d0 * inv * g[t] + be[t];
    float o1 = d1 * inv * g[t + 256] + be[t + 256];
    out[row * Dm + t] = o0;
    out[row * Dm + t + 256] = o1;
    float m2 = block_max(fmaxf(fabsf(o0), fabsf(o1)), sm);
    float s = (m2 > 0.f) ? (m2 * (1.f / 16256.f)) : 1.f;
    if (t == 0) sc[row] = s;
    float invs = 1.f / s, inv128s = invs * (1.f / 128.f);
    quant1(o0, s, inv128s, invs, qh, ql, row * Dm + t);
    quant1(o1, s, inv128s, invs, qh, ql, row * Dm + t + 256);
}

// ---------------- relu + residual + LN2 ----------------
__global__ void __launch_bounds__(256)
add_ln2_kernel(const float* __restrict__ a, const float* __restrict__ res,
               const float* __restrict__ g, const float* __restrict__ be,
               float* __restrict__ out)
{
    __shared__ float sm[8];
    long row = blockIdx.x;
    const float* ap = a + row * Dm;
    const float* rp = res + row * Dm;
    int t = threadIdx.x;
    float v0 = fmaxf(ap[t], 0.f) + rp[t];
    float v1 = fmaxf(ap[t + 256], 0.f) + rp[t + 256];
    float mean = block_sum(v0 + v1, sm) * (1.f / Dm);
    float d0 = v0 - mean, d1 = v1 - mean;
    float var = block_sum(d0 * d0 + d1 * d1, sm) * (1.f / Dm);
    float inv = rsqrtf(var + EPSv);
    out[row * Dm + t]       = d0 * inv * g[t]       + be[t];
    out[row * Dm + t + 256] = d1 * inv * g[t + 256] + be[t + 256];
}

// ---------------- launch ----------------
extern "C" void kernel_launch(void* const* d_in, const int* in_sizes, int n_in,
                              void* d_out, int out_size)
{
    const float* x    = (const float*)d_in[0];
    const float* Wq   = (const float*)d_in[1];
    const float* bq   = (const float*)d_in[2];
    const float* Wk   = (const float*)d_in[3];
    const float* Wv   = (const float*)d_in[5];
    const float* bv   = (const float*)d_in[6];
    const float* Wo   = (const float*)d_in[7];
    const float* bo   = (const float*)d_in[8];
    const float* ln1g = (const float*)d_in[9];
    const float* ln1b = (const float*)d_in[10];
    const float* W1   = (const float*)d_in[11];
    const float* b1   = (const float*)d_in[12];
    const float* W2   = (const float*)d_in[13];
    const float* b2   = (const float*)d_in[14];
    const float* ln2g = (const float*)d_in[15];
    const float* ln2b = (const float*)d_in[16];
    float* out = (float*)d_out;

    bf16 *Wqh, *Wql, *Wkh, *Wkl, *Wvh, *Wvl, *WoTh, *WoTl;
    float *Mtf, *Ntf, *w0, *ccp, *u, *zt, *ps, *parts, *y1, *f1, *W1T, *W2T, *ff2;
    i8 *xqh, *xql, *Mtqh, *Mtql, *uqh, *uql, *Ntqh, *Ntql, *ztqh, *ztql;
    i8 *Pqh, *Pql, *y1qh, *y1ql, *f1qh, *f1ql, *W1Tqh, *W1Tql, *W2Tqh, *W2Tql;
    float *sx, *sMt, *su, *sNt, *szt, *sP, *sy1, *sf1, *sW1, *sW2;
    cudaGetSymbolAddress((void**)&Wqh, g_Wqh);   cudaGetSymbolAddress((void**)&Wql, g_Wql);
    cudaGetSymbolAddress((void**)&Wkh, g_Wkh);   cudaGetSymbolAddress((void**)&Wkl, g_Wkl);
    cudaGetSymbolAddress((void**)&Wvh, g_Wvh);   cudaGetSymbolAddress((void**)&Wvl, g_Wvl);
    cudaGetSymbolAddress((void**)&WoTh, g_WoTh); cudaGetSymbolAddress((void**)&WoTl, g_WoTl);
    cudaGetSymbolAddress((void**)&Mtf, g_Mtf);   cudaGetSymbolAddress((void**)&Ntf, g_Ntf);
    cudaGetSymbolAddress((void**)&w0, g_w0);     cudaGetSymbolAddress((void**)&ccp, g_ccp);
    cudaGetSymbolAddress((void**)&u, g_u);       cudaGetSymbolAddress((void**)&zt, g_zt);
    cudaGetSymbolAddress((void**)&ps, g_s);      cudaGetSymbolAddress((void**)&parts, g_parts);
    cudaGetSymbolAddress((void**)&y1, g_y1);     cudaGetSymbolAddress((void**)&f1, g_f1);
    cudaGetSymbolAddress((void**)&W1T, g_W1T);   cudaGetSymbolAddress((void**)&W2T, g_W2T);
    cudaGetSymbolAddress((void**)&ff2, g_ff2);
    cudaGetSymbolAddress((void**)&xqh, g_xqh);   cudaGetSymbolAddress((void**)&xql, g_xql);
    cudaGetSymbolAddress((void**)&Mtqh, g_Mtqh); cudaGetSymbolAddress((void**)&Mtql, g_Mtql);
    cudaGetSymbolAddress((void**)&uqh, g_uqh);   cudaGetSymbolAddress((void**)&uql, g_uql);
    cudaGetSymbolAddress((void**)&Ntqh, g_Ntqh); cudaGetSymbolAddress((void**)&Ntql, g_Ntql);
    cudaGetSymbolAddress((void**)&ztqh, g_ztqh); cudaGetSymbolAddress((void**)&ztql, g_ztql);
    cudaGetSymbolAddress((void**)&Pqh, g_Pqh);   cudaGetSymbolAddress((void**)&Pql, g_Pql);
    cudaGetSymbolAddress((void**)&y1qh, g_y1qh); cudaGetSymbolAddress((void**)&y1ql, g_y1ql);
    cudaGetSymbolAddress((void**)&f1qh, g_f1qh); cudaGetSymbolAddress((void**)&f1ql, g_f1ql);
    cudaGetSymbolAddress((void**)&W1Tqh, g_W1Tqh); cudaGetSymbolAddress((void**)&W1Tql, g_W1Tql);
    cudaGetSymbolAddress((void**)&W2Tqh, g_W2Tqh); cudaGetSymbolAddress((void**)&W2Tql, g_W2Tql);
    cudaGetSymbolAddress((void**)&sx, g_sx);     cudaGetSymbolAddress((void**)&sMt, g_sMt);
    cudaGetSymbolAddress((void**)&su, g_su);     cudaGetSymbolAddress((void**)&sNt, g_sNt);
    cudaGetSymbolAddress((void**)&szt, g_szt);   cudaGetSymbolAddress((void**)&sP, g_sP);
    cudaGetSymbolAddress((void**)&sy1, g_sy1);   cudaGetSymbolAddress((void**)&sf1, g_sf1);
    cudaGetSymbolAddress((void**)&sW1, g_sW1);   cudaGetSymbolAddress((void**)&sW2, g_sW2);

    const float inv_sqrt_d = 0.044194173824159216f;
    const long DD = (long)Dm * Dm;

    // prep: quantize x; bf16 planes for W; vecprep consts
    rowquant<<<BT, 256>>>(x, xqh, xql, sx, Dm);
    esplit<<<(HH * Dm * Dm + 255) / 256, 256>>>(Wq, Wqh, Wql, HH * Dm * Dm);
    esplit<<<(HH * Dm * Dm + 255) / 256, 256>>>(Wk, Wkh, Wkl, HH * Dm * Dm);
    esplit<<<(HH * Dm * Dm + 255) / 256, 256>>>(Wv, Wvh, Wvl, HH * Dm * Dm);
    tsplit<<<dim3(Dm / 32, (HH * Dm) / 32), 256>>>(Wo, WoTh, WoTl, HH * Dm, Dm);
    vecprep<<<576, 256>>>(Wk, bq, Wo, bv, w0, ccp);

    // Mt_h = Wk_h @ Wq_h^T (bf16x3, fp32 out), quantize
    gemm_mma<<<dim3(4, 4, HH), 256, SMEM_BYTES>>>(Wkh, Wkl, Wqh, Wql, Mtf,
        Dm, Dm, Dm, Dm, DD, DD, DD);
    rowquant<<<HH * Dm, 256>>>(Mtf, Mtqh, Mtql, sMt, Dm);

    // u = x @ M_h + w0 (int8) -> fp32, quantize
    gemm_i8<1><<<dim3(4, BT / 128, HH), 256, SMEM_BYTES>>>(xqh, xql, sx, Mtqh, Mtql, sMt,
        w0, u, Dm, Dm, Dm, Dm, 0L, DD, 0, 0L, (long)Dm, (long)Dm, (long)BT * Dm, 1.f);
    rowquant<<<HH * BT, 256>>>(u, uqh, uql, su, Dm);

    // Nt_h = WoT_h @ Wv_h^T (bf16x3), quantize
    gemm_mma<<<dim3(4, 4, HH), 256, SMEM_BYTES>>>(WoTh, WoTl, Wvh, Wvl, Ntf,
        Dm, HH * Dm, Dm, Dm, (long)Dm, DD, DD);
    rowquant<<<HH * Dm, 256>>>(Ntf, Ntqh, Ntql, sNt, Dm);

    // z^T = (x @ N_h)^T (int8, transposed fp32 out), quantize rows of z^T
    gemm_i8<4><<<dim3(4, BT / 128, HH), 256, SMEM_BYTES>>>(xqh, xql, sx, Ntqh, Ntql, sNt,
        nullptr, zt, Dm, Dm, Dm, 0, 0L, DD, 0, 0L, (long)Dm, 0L, 0L, 1.f);
    rowquant<<<HH * BB * Dm, 256>>>(zt, ztqh, ztql, szt, TT);

    // scores = u @ x^T * 1/sqrt(D)
    gemm_i8<1><<<dim3(TT / 128, TT / 128, HH * BB), 256, SMEM_BYTES>>>(uqh, uql, su,
        xqh, xql, sx, nullptr, ps, Dm, Dm, Dm, TT,
        (long)TT * Dm, (long)TT * Dm, BB, (long)TT, (long)TT, 0L,
        (long)TT * TT, inv_sqrt_d);

    // softmax -> int8 P
    softmax_kernel<<<HH * BB * TT, 256>>>(ps, Pqh, Pql, sP);

    // parts = P @ z (int8) -> fp32 [z][T][D]
    gemm_i8<1><<<dim3(Dm / 128, TT / 128, HH * BB), 256, SMEM_BYTES>>>(Pqh, Pql, sP,
        ztqh, ztql, szt, nullptr, parts, TT, TT, TT, Dm,
        (long)TT * TT, (long)Dm * TT, 0, (long)TT, (long)Dm, 0L,
        (long)TT * Dm, 1.f);

    // y1 = LN(sum_h parts + consts + x), fused quantize
    reduce_ln1<<<BT, 256>>>(parts, x, ccp, bo, ln1g, ln1b, y1, y1qh, y1ql, sy1);

    // FFN weights: transpose + quantize
    ttrans<<<dim3(DFFm / 32, Dm / 32), 256>>>(W1, W1T, Dm, DFFm);
    rowquant<<<DFFm, 256>>>(W1T, W1Tqh, W1Tql, sW1, Dm);
    ttrans<<<dim3(Dm / 32, DFFm / 32), 256>>>(W2, W2T, DFFm, Dm);
    rowquant<<<Dm, 256>>>(W2T, W2Tqh, W2Tql, sW2, DFFm);

    // FFN1 (int8) -> fp32, quantize
    gemm_i8<1><<<dim3(DFFm / 128, BT / 128, 1), 256, SMEM_BYTES>>>(y1qh, y1ql, sy1,
        W1Tqh, W1Tql, sW1, b1, f1, Dm, Dm, Dm, DFFm,
        0L, 0L, 0, 0L, 0L, 0L, 0L, 1.f);
    rowquant<<<BT, 256>>>(f1, f1qh, f1ql, sf1, DFFm);

    // FFN2 (int8) -> fp32
    gemm_i8<1><<<dim3(Dm / 128, BT / 128, 1), 256, SMEM_BYTES>>>(f1qh, f1ql, sf1,
        W2Tqh, W2Tql, sW2, b2, ff2, DFFm, DFFm, DFFm, Dm,
        0L, 0L, 0, 0L, 0L, 0L, 0L, 1.f);

    // out = LN(relu(ff2) + y1)
    add_ln2_kernel<<<BT, 256>>>(ff2, y1, ln2g, ln2b, out);
}

// round 10
// speedup vs baseline: 1.8549x; 1.8549x over previous
#include <cuda_runtime.h>
#include <cuda_bf16.h>
#include <math.h>
#include <cstdint>

#define HH   8
#define Dm   512
#define DFFm 2048
#define BB   8
#define TT   1024
#define BT   (BB*TT)
#define EPSv 1e-5f

typedef __nv_bfloat16 bf16;

// ---------------- scratch (static __device__, allocation-free) ----------------
__device__ bf16 g_xh[BT*Dm], g_xl[BT*Dm];
__device__ bf16 g_Wqh[HH*Dm*Dm], g_Wql[HH*Dm*Dm];
__device__ bf16 g_Wkh[HH*Dm*Dm], g_Wkl[HH*Dm*Dm];
__device__ bf16 g_Wvh[HH*Dm*Dm], g_Wvl[HH*Dm*Dm];
__device__ bf16 g_WoTh[Dm*HH*Dm], g_WoTl[Dm*HH*Dm];
__device__ bf16 g_W1Th[DFFm*Dm], g_W1Tl[DFFm*Dm];
__device__ bf16 g_W2Th[Dm*DFFm], g_W2Tl[Dm*DFFm];
__device__ bf16 g_Mth[HH*Dm*Dm], g_Mtl[HH*Dm*Dm];   // Mt[h][d'][d] = M_h[d,d']^T
__device__ bf16 g_Nth[HH*Dm*Dm], g_Ntl[HH*Dm*Dm];   // Nt[h][e][d]  = N_h[d,e]^T
__device__ float g_w0[HH*Dm];                        // Wk_h @ bq_h
__device__ float g_ccp[HH*Dm];                       // per-head bv_h @ Wo_h
__device__ bf16 g_uh[HH*BT*Dm], g_ul[HH*BT*Dm];      // u = x*M + w0
__device__ bf16 g_zth[HH*BT*Dm], g_ztl[HH*BT*Dm];    // z^T  [H,B,D,T]
__device__ float g_s[(size_t)HH*BB*TT*TT];           // 256 MB scores
__device__ bf16 g_ph[(size_t)HH*BB*TT*TT], g_pl[(size_t)HH*BB*TT*TT];
__device__ float g_parts[(size_t)HH*BT*Dm];          // per-head attn*z partials (fp32)
__device__ float g_y1[BT*Dm];
__device__ bf16 g_y1h[BT*Dm], g_y1l[BT*Dm];
__device__ bf16 g_f1h[BT*DFFm], g_f1l[BT*DFFm];
__device__ float g_ff2[BT*Dm];

// ---------------- helpers ----------------
__device__ __forceinline__ uint32_t smem_u32(const void* p) {
    uint32_t a;
    asm("{ .reg .u64 t; cvta.to.shared.u64 t, %1; cvt.u32.u64 %0, t; }" : "=r"(a) : "l"(p));
    return a;
}

#define CPASYNC16(sa, ga) \
    asm volatile("cp.async.ca.shared.global [%0], [%1], 16;" :: "r"(sa), "l"(ga) : "memory")
#define CP_COMMIT() asm volatile("cp.async.commit_group;" ::: "memory")
#define CP_WAIT1()  asm volatile("cp.async.wait_group 1;" ::: "memory")
#define CP_WAIT0()  asm volatile("cp.async.wait_group 0;" ::: "memory")

#define LDSM4(r, addr) \
    asm volatile("ldmatrix.sync.aligned.m8n8.x4.shared.b16 {%0,%1,%2,%3}, [%4];" \
        : "=r"((r)[0]), "=r"((r)[1]), "=r"((r)[2]), "=r"((r)[3]) : "r"(addr))

__device__ __forceinline__ void mma16816(float* c, const uint32_t* a, const uint32_t* b) {
    asm volatile("mma.sync.aligned.m16n8k16.row.col.f32.bf16.bf16.f32 "
        "{%0,%1,%2,%3}, {%4,%5,%6,%7}, {%8,%9}, {%0,%1,%2,%3};"
        : "+f"(c[0]), "+f"(c[1]), "+f"(c[2]), "+f"(c[3])
        : "r"(a[0]), "r"(a[1]), "r"(a[2]), "r"(a[3]), "r"(b[0]), "r"(b[1]));
}

#define STAGE_BYTES 24576
#define PLANE_BYTES 6144
#define ROW_BYTES   48
#define SMEM_BYTES  49152

// ============ universal bf16x3 mma.sync GEMM: C = alpha*(A @ B^T) + bias ============
// A planes [M,K] K-major (lda), B planes [N,K] K-major (ldb).
// B batch offset = ((modB>0) ? z%modB : z) * sB.
// EPI: 1 = write fp32 C, 2 = write bf16 hi/lo planes, 4 = transposed write [z,B,D,T]
template<int EPI>
__global__ void __launch_bounds__(256)
gemm_mma(const bf16* __restrict__ Ah, const bf16* __restrict__ Al,
         const bf16* __restrict__ Bh, const bf16* __restrict__ Bl,
         const float* __restrict__ bias,
         float* __restrict__ Cf, bf16* __restrict__ Ch, bf16* __restrict__ Cl,
         int K, int lda, int ldb, int ldc,
         long sA, long sB, int modB, long sBias,
         int innerB, long sC_outer, long sC_inner, float alpha)
{
    extern __shared__ char smem[];
    const uint32_t sb = smem_u32(smem);

    const int tid = threadIdx.x, lane = tid & 31, wid = tid >> 5;
    const int wm = wid >> 2, wn = wid & 3;
    const int z = blockIdx.z;

    const bf16* Abh = Ah + (long)z * sA;
    const bf16* Abl = Al + (long)z * sA;
    const long bOff = (modB > 0 ? (long)(z % modB) : (long)z) * sB;
    const bf16* Bbh = Bh + bOff;
    const bf16* Bbl = Bl + bOff;
    const float* biasb = bias ? (bias + (long)z * sBias) : nullptr;
    long coff = (innerB > 1) ? (long)(z / innerB) * sC_outer + (long)(z % innerB) * sC_inner
                             : (long)z * sC_outer;

    const int mBase = blockIdx.y * 128;
    const int nBase = blockIdx.x * 128;

    const int lrow = tid >> 1;
    const int lco  = (tid & 1) * 8;
    const uint32_t ssub = (uint32_t)lrow * ROW_BYTES + (tid & 1) * 16;
    const long gA = (long)(mBase + lrow) * lda + lco;
    const long gB = (long)(nBase + lrow) * ldb + lco;

    float acc[4][4][4];
    #pragma unroll
    for (int i = 0; i < 4; i++)
        #pragma unroll
        for (int j = 0; j < 4; j++)
            #pragma unroll
            for (int r = 0; r < 4; r++) acc[i][j][r] = 0.f;

    const int nStages = K >> 4;

    {
        uint32_t base = sb;
        CPASYNC16(base + ssub,                   (const char*)(Abh + gA));
        CPASYNC16(base + PLANE_BYTES + ssub,     (const char*)(Abl + gA));
        CPASYNC16(base + 2*PLANE_BYTES + ssub,   (const char*)(Bbh + gB));
        CPASYNC16(base + 3*PLANE_BYTES + ssub,   (const char*)(Bbl + gB));
        CP_COMMIT();
    }

    const uint32_t aoff = (uint32_t)(lane & 15) * ROW_BYTES + (lane >> 4) * 16;
    const int nrow  = (lane & 7) + ((lane >> 4) << 3);
    const int khalf = (lane >> 3) & 1;
    const uint32_t boff = (uint32_t)nrow * ROW_BYTES + khalf * 16;

    for (int s = 0; s < nStages; s++) {
        if (s + 1 < nStages) {
            uint32_t base = sb + ((s + 1) & 1) * STAGE_BYTES;
            long k0 = (long)(s + 1) << 4;
            CPASYNC16(base + ssub,                 (const char*)(Abh + gA + k0));
            CPASYNC16(base + PLANE_BYTES + ssub,   (const char*)(Abl + gA + k0));
            CPASYNC16(base + 2*PLANE_BYTES + ssub, (const char*)(Bbh + gB + k0));
            CPASYNC16(base + 3*PLANE_BYTES + ssub, (const char*)(Bbl + gB + k0));
            CP_COMMIT();
            CP_WAIT1();
        } else {
            CP_WAIT0();
        }
        __syncthreads();

        const uint32_t base = sb + (s & 1) * STAGE_BYTES;
        uint32_t ah[4][4], al[4][4];
        #pragma unroll
        for (int mi = 0; mi < 4; mi++) {
            uint32_t o = base + (uint32_t)(wm * 64 + mi * 16) * ROW_BYTES + aoff;
            LDSM4(ah[mi], o);
            LDSM4(al[mi], o + PLANE_BYTES);
        }
        uint32_t bh[2][4], bl[2][4];
        #pragma unroll
        for (int p = 0; p < 2; p++) {
            uint32_t o = base + 2*PLANE_BYTES + (uint32_t)(wn * 32 + p * 16) * ROW_BYTES + boff;
            LDSM4(bh[p], o);
            LDSM4(bl[p], o + PLANE_BYTES);
        }
        #pragma unroll
        for (int mi = 0; mi < 4; mi++)
            #pragma unroll
            for (int p = 0; p < 2; p++)
                #pragma unroll
                for (int s2 = 0; s2 < 2; s2++) {
                    const int ni = p * 2 + s2;
                    mma16816(acc[mi][ni], ah[mi], &bh[p][s2 * 2]);
                    mma16816(acc[mi][ni], al[mi], &bh[p][s2 * 2]);
                    mma16816(acc[mi][ni], ah[mi], &bl[p][s2 * 2]);
                }
        __syncthreads();
    }

    const int er = mBase + wm * 64 + (lane >> 2);
    const int ec = nBase + wn * 32 + (lane & 3) * 2;

    #pragma unroll
    for (int mi = 0; mi < 4; mi++) {
        #pragma unroll
        for (int ni = 0; ni < 4; ni++) {
            const int gc = ec + ni * 8;
            float b0 = 0.f, b1 = 0.f;
            if (biasb) { b0 = __ldg(&biasb[gc]); b1 = __ldg(&biasb[gc + 1]); }
            #pragma unroll
            for (int half = 0; half < 2; half++) {
                const int gr = er + mi * 16 + half * 8;
                float v0 = acc[mi][ni][half * 2 + 0] * alpha + b0;
                float v1 = acc[mi][ni][half * 2 + 1] * alpha + b1;
                if (EPI == 4) {
                    const long zb = (long)z * ((long)BB * Dm * TT)
                                  + (long)(gr >> 10) * ((long)Dm * TT);
                    const long t = gr & 1023;
                    long a0 = zb + (long)gc * TT + t;
                    long a1 = zb + (long)(gc + 1) * TT + t;
                    bf16 h0 = __float2bfloat16_rn(v0);
                    bf16 h1 = __float2bfloat16_rn(v1);
                    Ch[a0] = h0; Cl[a0] = __float2bfloat16_rn(v0 - __bfloat162float(h0));
                    Ch[a1] = h1; Cl[a1] = __float2bfloat16_rn(v1 - __bfloat162float(h1));
                } else {
                    const long baseo = coff + (long)gr * ldc + gc;
                    if (EPI & 1) {
                        float2 f; f.x = v0; f.y = v1;
                        *(float2*)(Cf + baseo) = f;
                    }
                    if (EPI & 2) {
                        bf16 h0 = __float2bfloat16_rn(v0);
                        bf16 h1 = __float2bfloat16_rn(v1);
                        bf16 l0 = __float2bfloat16_rn(v0 - __bfloat162float(h0));
                        bf16 l1 = __float2bfloat16_rn(v1 - __bfloat162float(h1));
                        uint16_t a16 = *(uint16_t*)&h0, b16v = *(uint16_t*)&h1;
                        uint16_t c16 = *(uint16_t*)&l0, d16 = *(uint16_t*)&l1;
                        *(uint32_t*)(Ch + baseo) = (uint32_t)a16 | ((uint32_t)b16v << 16);
                        *(uint32_t*)(Cl + baseo) = (uint32_t)c16 | ((uint32_t)d16 << 16);
                    }
                }
            }
        }
    }
}

// ============ HYBRID GEMM (fp32 out only): blocks x < nH use HMMA (tensor pipe),
// blocks x >= nH use SIMT FFMA (fma pipe) reconstructing fp32 = hi + lo.
// Both pipes run concurrently on co-resident CTAs of the same launch.
__global__ void __launch_bounds__(256, 2)
gemm_hyb(const bf16* __restrict__ Ah, const bf16* __restrict__ Al,
         const bf16* __restrict__ Bh, const bf16* __restrict__ Bl,
         float* __restrict__ Cf,
         int K, int lda, int ldb, int ldc,
         long sA, long sB, int modB, long sC, float alpha, int nH)
{
    extern __shared__ char smem[];
    const int tid = threadIdx.x;
    const int z = blockIdx.z;
    const bf16* Abh = Ah + (long)z * sA;
    const bf16* Abl = Al + (long)z * sA;
    const long bOff = (modB > 0 ? (long)(z % modB) : (long)z) * sB;
    const bf16* Bbh = Bh + bOff;
    const bf16* Bbl = Bl + bOff;
    const long coff = (long)z * sC;
    const int mBase = blockIdx.y * 128;
    const int nBase = blockIdx.x * 128;

    if (blockIdx.x < nH) {
        // ---------------- HMMA path (identical to gemm_mma mainloop, EPI=1) ----------------
        const uint32_t sb = smem_u32(smem);
        const int lane = tid & 31, wid = tid >> 5;
        const int wm = wid >> 2, wn = wid & 3;
        const int lrow = tid >> 1;
        const int lco  = (tid & 1) * 8;
        const uint32_t ssub = (uint32_t)lrow * ROW_BYTES + (tid & 1) * 16;
        const long gA = (long)(mBase + lrow) * lda + lco;
        const long gB = (long)(nBase + lrow) * ldb + lco;

        float acc[4][4][4];
        #pragma unroll
        for (int i = 0; i < 4; i++)
            #pragma unroll
            for (int j = 0; j < 4; j++)
                #pragma unroll
                for (int r = 0; r < 4; r++) acc[i][j][r] = 0.f;

        const int nStages = K >> 4;
        {
            uint32_t base = sb;
            CPASYNC16(base + ssub,                   (const char*)(Abh + gA));
            CPASYNC16(base + PLANE_BYTES + ssub,     (const char*)(Abl + gA));
            CPASYNC16(base + 2*PLANE_BYTES + ssub,   (const char*)(Bbh + gB));
            CPASYNC16(base + 3*PLANE_BYTES + ssub,   (const char*)(Bbl + gB));
            CP_COMMIT();
        }
        const uint32_t aoff = (uint32_t)(lane & 15) * ROW_BYTES + (lane >> 4) * 16;
        const int nrow  = (lane & 7) + ((lane >> 4) << 3);
        const int khalf = (lane >> 3) & 1;
        const uint32_t boff = (uint32_t)nrow * ROW_BYTES + khalf * 16;

        for (int s = 0; s < nStages; s++) {
            if (s + 1 < nStages) {
                uint32_t base = sb + ((s + 1) & 1) * STAGE_BYTES;
                long k0 = (long)(s + 1) << 4;
                CPASYNC16(base + ssub,                 (const char*)(Abh + gA + k0));
                CPASYNC16(base + PLANE_BYTES + ssub,   (const char*)(Abl + gA + k0));
                CPASYNC16(base + 2*PLANE_BYTES + ssub, (const char*)(Bbh + gB + k0));
                CPASYNC16(base + 3*PLANE_BYTES + ssub, (const char*)(Bbl + gB + k0));
                CP_COMMIT();
                CP_WAIT1();
            } else {
                CP_WAIT0();
            }
            __syncthreads();

            const uint32_t base = sb + (s & 1) * STAGE_BYTES;
            uint32_t ah[4][4], al[4][4];
            #pragma unroll
            for (int mi = 0; mi < 4; mi++) {
                uint32_t o = base + (uint32_t)(wm * 64 + mi * 16) * ROW_BYTES + aoff;
                LDSM4(ah[mi], o);
                LDSM4(al[mi], o + PLANE_BYTES);
            }
            uint32_t bh[2][4], bl[2][4];
            #pragma unroll
            for (int p = 0; p < 2; p++) {
                uint32_t o = base + 2*PLANE_BYTES + (uint32_t)(wn * 32 + p * 16) * ROW_BYTES + boff;
                LDSM4(bh[p], o);
                LDSM4(bl[p], o + PLANE_BYTES);
            }
            #pragma unroll
            for (int mi = 0; mi < 4; mi++)
                #pragma unroll
                for (int p = 0; p < 2; p++)
                    #pragma unroll
                    for (int s2 = 0; s2 < 2; s2++) {
                        const int ni = p * 2 + s2;
                        mma16816(acc[mi][ni], ah[mi], &bh[p][s2 * 2]);
                        mma16816(acc[mi][ni], al[mi], &bh[p][s2 * 2]);
                        mma16816(acc[mi][ni], ah[mi], &bl[p][s2 * 2]);
                    }
            __syncthreads();
        }
        const int er = mBase + wm * 64 + (lane >> 2);
        const int ec = nBase + wn * 32 + (lane & 3) * 2;
        #pragma unroll
        for (int mi = 0; mi < 4; mi++)
            #pragma unroll
            for (int ni = 0; ni < 4; ni++)
                #pragma unroll
                for (int half = 0; half < 2; half++) {
                    const int gr = er + mi * 16 + half * 8;
                    const int gc = ec + ni * 8;
                    float2 f;
                    f.x = acc[mi][ni][half * 2 + 0] * alpha;
                    f.y = acc[mi][ni][half * 2 + 1] * alpha;
                    *(float2*)(Cf + coff + (long)gr * ldc + gc) = f;
                }
    } else {
        // ---------------- SIMT FFMA path (R1-style 128x128x16, fp32 = hi+lo) ----------------
        float (*As)[132] = (float(*)[132])smem;                 // [16][132]
        float (*Bs)[132] = (float(*)[132])(smem + 16 * 132 * 4);
        const int m0 = (tid >> 4) << 3;
        const int n0 = (tid & 15) << 3;
        const int r  = tid >> 1;
        const int cg = (tid & 1) * 8;

        float acc[8][8];
        #pragma unroll
        for (int i = 0; i < 8; i++)
            #pragma unroll
            for (int j = 0; j < 8; j++) acc[i][j] = 0.f;

        for (int k0 = 0; k0 < K; k0 += 16) {
            {
                uint4 vh = *(const uint4*)(Abh + (long)(mBase + r) * lda + k0 + cg);
                uint4 vl = *(const uint4*)(Abl + (long)(mBase + r) * lda + k0 + cg);
                const bf16* phh = (const bf16*)&vh;
                const bf16* pll = (const bf16*)&vl;
                #pragma unroll
                for (int j = 0; j < 8; j++)
                    As[cg + j][r] = __bfloat162float(phh[j]) + __bfloat162float(pll[j]);
            }
            {
                uint4 vh = *(const uint4*)(Bbh + (long)(nBase + r) * ldb + k0 + cg);
                uint4 vl = *(const uint4*)(Bbl + (long)(nBase + r) * ldb + k0 + cg);
                const bf16* phh = (const bf16*)&vh;
                const bf16* pll = (const bf16*)&vl;
                #pragma unroll
                for (int j = 0; j < 8; j++)
                    Bs[cg + j][r] = __bfloat162float(phh[j]) + __bfloat162float(pll[j]);
            }
            __syncthreads();
            #pragma unroll
            for (int k = 0; k < 16; k++) {
                float a[8], b[8];
                *(float4*)(a)     = *(const float4*)&As[k][m0];
                *(float4*)(a + 4) = *(const float4*)&As[k][m0 + 4];
                *(float4*)(b)     = *(const float4*)&Bs[k][n0];
                *(float4*)(b + 4) = *(const float4*)&Bs[k][n0 + 4];
                #pragma unroll
                for (int i = 0; i < 8; i++)
                    #pragma unroll
                    for (int j = 0; j < 8; j++)
                        acc[i][j] += a[i] * b[j];
            }
            __syncthreads();
        }
        #pragma unroll
        for (int i = 0; i < 8; i++) {
            const long row = mBase + m0 + i;
            #pragma unroll
            for (int j = 0; j < 8; j += 4) {
                const int col = nBase + n0 + j;
                float4 f;
                f.x = acc[i][j + 0] * alpha;
                f.y = acc[i][j + 1] * alpha;
                f.z = acc[i][j + 2] * alpha;
                f.w = acc[i][j + 3] * alpha;
                *(float4*)(Cf + coff + row * ldc + col) = f;
            }
        }
    }
}

// ---------------- transpose + split ----------------
__global__ void __launch_bounds__(256)
tsplit(const float* __restrict__ in, bf16* __restrict__ oh, bf16* __restrict__ ol,
       int R, int C)
{
    __shared__ float t[32][33];
    const int cb = blockIdx.x * 32, rb = blockIdx.y * 32;
    const int x = threadIdx.x & 31, y = threadIdx.x >> 5;
    #pragma unroll
    for (int i = 0; i < 32; i += 8)
        t[y + i][x] = in[(long)(rb + y + i) * C + cb + x];
    __syncthreads();
    #pragma unroll
    for (int i = 0; i < 32; i += 8) {
        float v = t[x][y + i];
        bf16 h = __float2bfloat16_rn(v);
        long o = (long)(cb + y + i) * R + rb + x;
        oh[o] = h;
        ol[o] = __float2bfloat16_rn(v - __bfloat162float(h));
    }
}

// ---------------- elementwise split ----------------
__global__ void __launch_bounds__(256)
esplit(const float* __restrict__ in, bf16* __restrict__ oh, bf16* __restrict__ ol, int n)
{
    int i = blockIdx.x * 256 + threadIdx.x;
    if (i < n) {
        float v = in[i];
        bf16 h = __float2bfloat16_rn(v);
        oh[i] = h;
        ol[i] = __float2bfloat16_rn(v - __bfloat162float(h));
    }
}

// ---------------- vecprep: w0[h,d] = Wk_h[d,:]·bq_h ; ccp[h,e] = bv_h·Wo_h[:,e] ----------------
__global__ void __launch_bounds__(256)
vecprep(const float* __restrict__ Wk, const float* __restrict__ bq,
        const float* __restrict__ Wo, const float* __restrict__ bv,
        float* __restrict__ w0, float* __restrict__ ccp)
{
    const int bb = blockIdx.x;
    if (bb < 512) {
        const int wid = threadIdx.x >> 5, lane = threadIdx.x & 31;
        const int idx = bb * 8 + wid;
        const int h = idx >> 9, d = idx & 511;
        const float* wr = Wk + (long)h * Dm * Dm + (long)d * Dm;
        const float* bqr = bq + h * Dm;
        float s = 0.f;
        #pragma unroll
        for (int e = lane; e < Dm; e += 32) s += wr[e] * bqr[e];
        #pragma unroll
        for (int o = 16; o; o >>= 1) s += __shfl_xor_sync(0xffffffffu, s, o);
        if (lane == 0) w0[idx] = s;
    } else {
        __shared__ float part[4][64];
        const int ib = bb - 512;
        const int h = ib >> 3, chunk = ib & 7;
        const int e = chunk * 64 + (threadIdx.x & 63);
        const int ms = threadIdx.x >> 6;
        const float* Woh = Wo + (long)h * Dm * Dm;
        const float* bvh = bv + h * Dm;
        float s = 0.f;
        for (int m = ms * 128; m < ms * 128 + 128; m++)
            s += bvh[m] * Woh[(long)m * Dm + e];
        part[ms][threadIdx.x & 63] = s;
        __syncthreads();
        if (threadIdx.x < 64)
            ccp[h * Dm + chunk * 64 + threadIdx.x] =
                part[0][threadIdx.x] + part[1][threadIdx.x] +
                part[2][threadIdx.x] + part[3][threadIdx.x];
    }
}

// ---------------- block reductions ----------------
__device__ __forceinline__ float block_sum(float v, float* sm) {
    #pragma unroll
    for (int o = 16; o; o >>= 1) v += __shfl_xor_sync(0xffffffffu, v, o);
    if ((threadIdx.x & 31) == 0) sm[threadIdx.x >> 5] = v;
    __syncthreads();
    if (threadIdx.x < 8) {
        float s = sm[threadIdx.x];
        #pragma unroll
        for (int o = 4; o; o >>= 1) s += __shfl_xor_sync(0xffu, s, o);
        if (threadIdx.x == 0) sm[0] = s;
    }
    __syncthreads();
    float r = sm[0];
    __syncthreads();
    return r;
}
__device__ __forceinline__ float block_max(float v, float* sm) {
    #pragma unroll
    for (int o = 16; o; o >>= 1) v = fmaxf(v, __shfl_xor_sync(0xffffffffu, v, o));
    if ((threadIdx.x & 31) == 0) sm[threadIdx.x >> 5] = v;
    __syncthreads();
    if (threadIdx.x < 8) {
        float s = sm[threadIdx.x];
        #pragma unroll
        for (int o = 4; o; o >>= 1) s = fmaxf(s, __shfl_xor_sync(0xffu, s, o));
        if (threadIdx.x == 0) sm[0] = s;
    }
    __syncthreads();
    float r = sm[0];
    __syncthreads();
    return r;
}

// ---------------- softmax -> bf16 hi/lo probability planes ----------------
__global__ void __launch_bounds__(256)
softmax_kernel(const float* __restrict__ S, bf16* __restrict__ Ph, bf16* __restrict__ Pl)
{
    __shared__ float sm[8];
    const size_t base = (size_t)blockIdx.x * TT;
    const float* p = S + base;
    int t = threadIdx.x;
    float x0 = p[t], x1 = p[t + 256], x2 = p[t + 512], x3 = p[t + 768];
    float m = block_max(fmaxf(fmaxf(x0, x1), fmaxf(x2, x3)), sm);
    float e0 = __expf(x0 - m), e1 = __expf(x1 - m);
    float e2 = __expf(x2 - m), e3 = __expf(x3 - m);
    float s = block_sum(e0 + e1 + e2 + e3, sm);
    float inv = 1.f / s;
    #pragma unroll
    for (int q = 0; q < 4; q++) {
        float v = (q == 0 ? e0 : q == 1 ? e1 : q == 2 ? e2 : e3) * inv;
        bf16 h = __float2bfloat16_rn(v);
        size_t idx = base + t + q * 256;
        Ph[idx] = h;
        Pl[idx] = __float2bfloat16_rn(v - __bfloat162float(h));
    }
}

// ---------------- reduce heads + cc + residual + LN1 -> y1 (fp32 + planes) ----------------
__global__ void __launch_bounds__(256)
reduce_ln1(const float* __restrict__ parts, const float* __restrict__ x,
           const float* __restrict__ ccp, const float* __restrict__ bo,
           const float* __restrict__ g, const float* __restrict__ be,
           float* __restrict__ out, bf16* __restrict__ oh, bf16* __restrict__ ol)
{
    __shared__ float sm[8];
    const long row = blockIdx.x;
    const long b = row >> 10, t0 = row & 1023;
    const int t = threadIdx.x;
    float v0, v1;
    {
        float c0 = bo[t], c1 = bo[t + 256];
        #pragma unroll
        for (int h = 0; h < HH; h++) {
            c0 += ccp[h * Dm + t];
            c1 += ccp[h * Dm + t + 256];
        }
        v0 = x[row * Dm + t] + c0;
        v1 = x[row * Dm + t + 256] + c1;
        #pragma unroll
        for (int h = 0; h < HH; h++) {
            const long pr = (((long)h * BB + b) * TT + t0) * Dm;
            v0 += parts[pr + t];
            v1 += parts[pr + t + 256];
        }
    }
    float mean = block_sum(v0 + v1, sm) * (1.f / Dm);
    float d0 = v0 - mean, d1 = v1 - mean;
    float var = block_sum(d0 * d0 + d1 * d1, sm) * (1.f / Dm);
    float inv = rsqrtf(var + EPSv);
    float o0 = d0 * inv * g[t] + be[t];
    float o1 = d1 * inv * g[t + 256] + be[t + 256];
    out[row * Dm + t] = o0;
    out[row * Dm + t + 256] = o1;
    bf16 h0 = __float2bfloat16_rn(o0), h1 = __float2bfloat16_rn(o1);
    oh[row * Dm + t] = h0;
    oh[row * Dm + t + 256] = h1;
    ol[row * Dm + t] = __float2bfloat16_rn(o0 - __bfloat162float(h0));
    ol[row * Dm + t + 256] = __float2bfloat16_rn(o1 - __bfloat162float(h1));
}

// ---------------- relu + residual + LN2 ----------------
__global__ void __launch_bounds__(256)
add_ln2_kernel(const float* __restrict__ a, const float* __restrict__ res,
               const float* __restrict__ g, const float* __restrict__ be,
               float* __restrict__ out)
{
    __shared__ float sm[8];
    long row = blockIdx.x;
    const float* ap = a + row * Dm;
    const float* rp = res + row * Dm;
    int t = threadIdx.x;
    float v0 = fmaxf(ap[t], 0.f) + rp[t];
    float v1 = fmaxf(ap[t + 256], 0.f) + rp[t + 256];
    float mean = block_sum(v0 + v1, sm) * (1.f / Dm);
    float d0 = v0 - mean, d1 = v1 - mean;
    float var = block_sum(d0 * d0 + d1 * d1, sm) * (1.f / Dm);
    float inv = rsqrtf(var + EPSv);
    out[row * Dm + t]       = d0 * inv * g[t]       + be[t];
    out[row * Dm + t + 256] = d1 * inv * g[t + 256] + be[t + 256];
}

// ---------------- launch ----------------
extern "C" void kernel_launch(void* const* d_in, const int* in_sizes, int n_in,
                              void* d_out, int out_size)
{
    const float* x    = (const float*)d_in[0];
    const float* Wq   = (const float*)d_in[1];
    const float* bq   = (const float*)d_in[2];
    const float* Wk   = (const float*)d_in[3];
    const float* Wv   = (const float*)d_in[5];
    const float* bv   = (const float*)d_in[6];
    const float* Wo   = (const float*)d_in[7];
    const float* bo   = (const float*)d_in[8];
    const float* ln1g = (const float*)d_in[9];
    const float* ln1b = (const float*)d_in[10];
    const float* W1   = (const float*)d_in[11];
    const float* b1   = (const float*)d_in[12];
    const float* W2   = (const float*)d_in[13];
    const float* b2   = (const float*)d_in[14];
    const float* ln2g = (const float*)d_in[15];
    const float* ln2b = (const float*)d_in[16];
    float* out = (float*)d_out;

    bf16 *xh, *xl, *Wqh, *Wql, *Wkh, *Wkl, *Wvh, *Wvl, *WoTh, *WoTl;
    bf16 *W1Th, *W1Tl, *W2Th, *W2Tl, *Mth, *Mtl, *Nth, *Ntl;
    bf16 *uh, *ul, *zth, *ztl, *ph, *pl, *y1h, *y1l, *f1h, *f1l;
    float *w0, *ccp, *ps, *parts, *py1, *pff2;
    cudaGetSymbolAddress((void**)&xh, g_xh);     cudaGetSymbolAddress((void**)&xl, g_xl);
    cudaGetSymbolAddress((void**)&Wqh, g_Wqh);   cudaGetSymbolAddress((void**)&Wql, g_Wql);
    cudaGetSymbolAddress((void**)&Wkh, g_Wkh);   cudaGetSymbolAddress((void**)&Wkl, g_Wkl);
    cudaGetSymbolAddress((void**)&Wvh, g_Wvh);   cudaGetSymbolAddress((void**)&Wvl, g_Wvl);
    cudaGetSymbolAddress((void**)&WoTh, g_WoTh); cudaGetSymbolAddress((void**)&WoTl, g_WoTl);
    cudaGetSymbolAddress((void**)&W1Th, g_W1Th); cudaGetSymbolAddress((void**)&W1Tl, g_W1Tl);
    cudaGetSymbolAddress((void**)&W2Th, g_W2Th); cudaGetSymbolAddress((void**)&W2Tl, g_W2Tl);
    cudaGetSymbolAddress((void**)&Mth, g_Mth);   cudaGetSymbolAddress((void**)&Mtl, g_Mtl);
    cudaGetSymbolAddress((void**)&Nth, g_Nth);   cudaGetSymbolAddress((void**)&Ntl, g_Ntl);
    cudaGetSymbolAddress((void**)&w0, g_w0);     cudaGetSymbolAddress((void**)&ccp, g_ccp);
    cudaGetSymbolAddress((void**)&uh, g_uh);     cudaGetSymbolAddress((void**)&ul, g_ul);
    cudaGetSymbolAddress((void**)&zth, g_zth);   cudaGetSymbolAddress((void**)&ztl, g_ztl);
    cudaGetSymbolAddress((void**)&ps, g_s);
    cudaGetSymbolAddress((void**)&ph, g_ph);     cudaGetSymbolAddress((void**)&pl, g_pl);
    cudaGetSymbolAddress((void**)&parts, g_parts);
    cudaGetSymbolAddress((void**)&py1, g_y1);
    cudaGetSymbolAddress((void**)&y1h, g_y1h);   cudaGetSymbolAddress((void**)&y1l, g_y1l);
    cudaGetSymbolAddress((void**)&f1h, g_f1h);   cudaGetSymbolAddress((void**)&f1l, g_f1l);
    cudaGetSymbolAddress((void**)&pff2, g_ff2);

    const float inv_sqrt_d = 0.044194173824159216f;
    const long DD = (long)Dm * Dm;

    // 0-3: splits + vecprep
    esplit<<<(BT * Dm + 255) / 256, 256>>>(x, xh, xl, BT * Dm);
    esplit<<<(HH * Dm * Dm + 255) / 256, 256>>>(Wq, Wqh, Wql, HH * Dm * Dm);
    esplit<<<(HH * Dm * Dm + 255) / 256, 256>>>(Wk, Wkh, Wkl, HH * Dm * Dm);
    vecprep<<<576, 256>>>(Wk, bq, Wo, bv, w0, ccp);

    // 4: Mt_h = Wk_h @ Wq_h^T
    gemm_mma<2><<<dim3(4, 4, HH), 256, SMEM_BYTES>>>(Wkh, Wkl, Wqh, Wql, nullptr,
        nullptr, Mth, Mtl, Dm, Dm, Dm, Dm, DD, DD, 0, 0L, 1, DD, 0L, 1.f);

    // 5: u = x @ M_h + w0_h
    gemm_mma<2><<<dim3(4, BT / 128, HH), 256, SMEM_BYTES>>>(xh, xl, Mth, Mtl, w0,
        nullptr, uh, ul, Dm, Dm, Dm, Dm, 0L, DD, 0, (long)Dm, 1, (long)BT * Dm, 0L, 1.f);

    // 6-7: remaining splits
    esplit<<<(HH * Dm * Dm + 255) / 256, 256>>>(Wv, Wvh, Wvl, HH * Dm * Dm);
    tsplit<<<dim3(Dm / 32, (HH * Dm) / 32), 256>>>(Wo, WoTh, WoTl, HH * Dm, Dm);

    // 8: Nt_h = WoT_h @ Wv_h^T
    gemm_mma<2><<<dim3(4, 4, HH), 256, SMEM_BYTES>>>(WoTh, WoTl, Wvh, Wvl, nullptr,
        nullptr, Nth, Ntl, Dm, HH * Dm, Dm, Dm, (long)Dm, DD, 0, 0L, 1, DD, 0L, 1.f);

    // 9: z^T = (x @ N_h)^T -> [H,B,D,T] planes
    gemm_mma<4><<<dim3(4, BT / 128, HH), 256, SMEM_BYTES>>>(xh, xl, Nth, Ntl, nullptr,
        nullptr, zth, ztl, Dm, Dm, Dm, 0, 0L, DD, 0, 0L, 1, 0L, 0L, 1.f);

    // 10: scores = u @ x^T * 1/sqrt(D)  [HYBRID: 6/8 col-tiles HMMA + 2/8 FFMA]
    gemm_hyb<<<dim3(TT / 128, TT / 128, HH * BB), 256, SMEM_BYTES>>>(uh, ul, xh, xl,
        ps, Dm, Dm, Dm, TT, (long)TT * Dm, (long)TT * Dm, BB, (long)TT * TT,
        inv_sqrt_d, 6);

    // 11: softmax -> P planes
    softmax_kernel<<<HH * BB * TT, 256>>>(ps, ph, pl);

    // 12: parts = P @ z  [HYBRID: 3/4 col-tiles HMMA + 1/4 FFMA]
    gemm_hyb<<<dim3(Dm / 128, TT / 128, HH * BB), 256, SMEM_BYTES>>>(ph, pl, zth, ztl,
        parts, TT, TT, TT, Dm, (long)TT * TT, (long)Dm * TT, 0, (long)TT * Dm,
        1.f, 3);

    // 13: y1 = LN(sum_h parts + cc + bo + x)
    reduce_ln1<<<BT, 256>>>(parts, x, ccp, bo, ln1g, ln1b, py1, y1h, y1l);

    // 14-15: FFN weight splits
    tsplit<<<dim3(DFFm / 32, Dm / 32), 256>>>(W1, W1Th, W1Tl, Dm, DFFm);
    tsplit<<<dim3(Dm / 32, DFFm / 32), 256>>>(W2, W2Th, W2Tl, DFFm, Dm);

    // 16: FFN1 -> f1 planes
    gemm_mma<2><<<dim3(DFFm / 128, BT / 128, 1), 256, SMEM_BYTES>>>(y1h, y1l, W1Th, W1Tl,
        b1, nullptr, f1h, f1l, Dm, Dm, Dm, DFFm, 0L, 0L, 0, 0L, 1, 0L, 0L, 1.f);

    // 17: FFN2 -> ff2 fp32
    gemm_mma<1><<<dim3(Dm / 128, BT / 128, 1), 256, SMEM_BYTES>>>(f1h, f1l, W2Th, W2Tl,
        b2, pff2, nullptr, nullptr, DFFm, DFFm, DFFm, Dm, 0L, 0L, 0, 0L, 1, 0L, 0L, 1.f);

    // 18: out = LN(relu(ff2) + y1)
    add_ln2_kernel<<<BT, 256>>>(pff2, py1, ln2g, ln2b, out);
}

// round 11
// speedup vs baseline: 2.2392x; 1.2071x over previous
#include <cuda_runtime.h>
#include <cuda_bf16.h>
#include <math.h>
#include <cstdint>

#define HH   8
#define Dm   512
#define DFFm 2048
#define BB   8
#define TT   1024
#define BT   (BB*TT)
#define EPSv 1e-5f

typedef __nv_bfloat16 bf16;

// ---------------- scratch (static __device__, allocation-free) ----------------
__device__ bf16 g_xh[BT*Dm], g_xl[BT*Dm];
__device__ bf16 g_Wqh[HH*Dm*Dm], g_Wql[HH*Dm*Dm];
__device__ bf16 g_Wkh[HH*Dm*Dm], g_Wkl[HH*Dm*Dm];
__device__ bf16 g_Wvh[HH*Dm*Dm], g_Wvl[HH*Dm*Dm];
__device__ bf16 g_WoTh[Dm*HH*Dm], g_WoTl[Dm*HH*Dm];
__device__ bf16 g_W1Th[DFFm*Dm], g_W1Tl[DFFm*Dm];
__device__ bf16 g_W2Th[Dm*DFFm], g_W2Tl[Dm*DFFm];
__device__ bf16 g_Mth[HH*Dm*Dm], g_Mtl[HH*Dm*Dm];   // Mt[h][d'][d] = M_h[d,d']^T
__device__ bf16 g_Nth[HH*Dm*Dm], g_Ntl[HH*Dm*Dm];   // Nt[h][e][d]  = N_h[d,e]^T
__device__ float g_w0[HH*Dm];                        // Wk_h @ bq_h
__device__ float g_ccp[HH*Dm];                       // per-head bv_h @ Wo_h
__device__ bf16 g_uh[HH*BT*Dm], g_ul[HH*BT*Dm];      // u = x*M + w0
__device__ bf16 g_zth[HH*BT*Dm], g_ztl[HH*BT*Dm];    // z^T  [H,B,D,T]
__device__ float g_s[(size_t)HH*BB*TT*TT];           // 256 MB scores (fp32)
__device__ float g_rc[HH*BB*TT];                     // per-row softmax offset c = m + lnZ
__device__ float g_parts[(size_t)HH*BT*Dm];          // per-head attn*z partials (fp32)
__device__ float g_y1[BT*Dm];
__device__ bf16 g_y1h[BT*Dm], g_y1l[BT*Dm];
__device__ bf16 g_f1h[BT*DFFm], g_f1l[BT*DFFm];
__device__ float g_ff2[BT*Dm];

// ---------------- helpers ----------------
__device__ __forceinline__ uint32_t smem_u32(const void* p) {
    uint32_t a;
    asm("{ .reg .u64 t; cvta.to.shared.u64 t, %1; cvt.u32.u64 %0, t; }" : "=r"(a) : "l"(p));
    return a;
}

#define CPASYNC16(sa, ga) \
    asm volatile("cp.async.ca.shared.global [%0], [%1], 16;" :: "r"(sa), "l"(ga) : "memory")
#define CP_COMMIT() asm volatile("cp.async.commit_group;" ::: "memory")
#define CP_WAIT1()  asm volatile("cp.async.wait_group 1;" ::: "memory")
#define CP_WAIT0()  asm volatile("cp.async.wait_group 0;" ::: "memory")

#define LDSM4(r, addr) \
    asm volatile("ldmatrix.sync.aligned.m8n8.x4.shared.b16 {%0,%1,%2,%3}, [%4];" \
        : "=r"((r)[0]), "=r"((r)[1]), "=r"((r)[2]), "=r"((r)[3]) : "r"(addr))

__device__ __forceinline__ void mma16816(float* c, const uint32_t* a, const uint32_t* b) {
    asm volatile("mma.sync.aligned.m16n8k16.row.col.f32.bf16.bf16.f32 "
        "{%0,%1,%2,%3}, {%4,%5,%6,%7}, {%8,%9}, {%0,%1,%2,%3};"
        : "+f"(c[0]), "+f"(c[1]), "+f"(c[2]), "+f"(c[3])
        : "r"(a[0]), "r"(a[1]), "r"(a[2]), "r"(a[3]), "r"(b[0]), "r"(b[1]));
}

#define STAGE_BYTES 24576
#define PLANE_BYTES 6144
#define ROW_BYTES   48
#define SMEM_BYTES  49152

// ============ universal bf16x3 mma.sync GEMM: C = alpha*(A @ B^T) + bias ============
// EPI: 1 = fp32 C, 2 = bf16 hi/lo planes, 4 = transposed write [z,B,D,T]
template<int EPI>
__global__ void __launch_bounds__(256)
gemm_mma(const bf16* __restrict__ Ah, const bf16* __restrict__ Al,
         const bf16* __restrict__ Bh, const bf16* __restrict__ Bl,
         const float* __restrict__ bias,
         float* __restrict__ Cf, bf16* __restrict__ Ch, bf16* __restrict__ Cl,
         int K, int lda, int ldb, int ldc,
         long sA, long sB, int modB, long sBias,
         int innerB, long sC_outer, long sC_inner, float alpha)
{
    extern __shared__ char smem[];
    const uint32_t sb = smem_u32(smem);

    const int tid = threadIdx.x, lane = tid & 31, wid = tid >> 5;
    const int wm = wid >> 2, wn = wid & 3;
    const int z = blockIdx.z;

    const bf16* Abh = Ah + (long)z * sA;
    const bf16* Abl = Al + (long)z * sA;
    const long bOff = (modB > 0 ? (long)(z % modB) : (long)z) * sB;
    const bf16* Bbh = Bh + bOff;
    const bf16* Bbl = Bl + bOff;
    const float* biasb = bias ? (bias + (long)z * sBias) : nullptr;
    long coff = (innerB > 1) ? (long)(z / innerB) * sC_outer + (long)(z % innerB) * sC_inner
                             : (long)z * sC_outer;

    const int mBase = blockIdx.y * 128;
    const int nBase = blockIdx.x * 128;

    const int lrow = tid >> 1;
    const int lco  = (tid & 1) * 8;
    const uint32_t ssub = (uint32_t)lrow * ROW_BYTES + (tid & 1) * 16;
    const long gA = (long)(mBase + lrow) * lda + lco;
    const long gB = (long)(nBase + lrow) * ldb + lco;

    float acc[4][4][4];
    #pragma unroll
    for (int i = 0; i < 4; i++)
        #pragma unroll
        for (int j = 0; j < 4; j++)
            #pragma unroll
            for (int r = 0; r < 4; r++) acc[i][j][r] = 0.f;

    const int nStages = K >> 4;

    {
        uint32_t base = sb;
        CPASYNC16(base + ssub,                   (const char*)(Abh + gA));
        CPASYNC16(base + PLANE_BYTES + ssub,     (const char*)(Abl + gA));
        CPASYNC16(base + 2*PLANE_BYTES + ssub,   (const char*)(Bbh + gB));
        CPASYNC16(base + 3*PLANE_BYTES + ssub,   (const char*)(Bbl + gB));
        CP_COMMIT();
    }

    const uint32_t aoff = (uint32_t)(lane & 15) * ROW_BYTES + (lane >> 4) * 16;
    const int nrow  = (lane & 7) + ((lane >> 4) << 3);
    const int khalf = (lane >> 3) & 1;
    const uint32_t boff = (uint32_t)nrow * ROW_BYTES + khalf * 16;

    for (int s = 0; s < nStages; s++) {
        if (s + 1 < nStages) {
            uint32_t base = sb + ((s + 1) & 1) * STAGE_BYTES;
            long k0 = (long)(s + 1) << 4;
            CPASYNC16(base + ssub,                 (const char*)(Abh + gA + k0));
            CPASYNC16(base + PLANE_BYTES + ssub,   (const char*)(Abl + gA + k0));
            CPASYNC16(base + 2*PLANE_BYTES + ssub, (const char*)(Bbh + gB + k0));
            CPASYNC16(base + 3*PLANE_BYTES + ssub, (const char*)(Bbl + gB + k0));
            CP_COMMIT();
            CP_WAIT1();
        } else {
            CP_WAIT0();
        }
        __syncthreads();

        const uint32_t base = sb + (s & 1) * STAGE_BYTES;
        uint32_t ah[4][4], al[4][4];
        #pragma unroll
        for (int mi = 0; mi < 4; mi++) {
            uint32_t o = base + (uint32_t)(wm * 64 + mi * 16) * ROW_BYTES + aoff;
            LDSM4(ah[mi], o);
            LDSM4(al[mi], o + PLANE_BYTES);
        }
        uint32_t bh[2][4], bl[2][4];
        #pragma unroll
        for (int p = 0; p < 2; p++) {
            uint32_t o = base + 2*PLANE_BYTES + (uint32_t)(wn * 32 + p * 16) * ROW_BYTES + boff;
            LDSM4(bh[p], o);
            LDSM4(bl[p], o + PLANE_BYTES);
        }
        #pragma unroll
        for (int mi = 0; mi < 4; mi++)
            #pragma unroll
            for (int p = 0; p < 2; p++)
                #pragma unroll
                for (int s2 = 0; s2 < 2; s2++) {
                    const int ni = p * 2 + s2;
                    mma16816(acc[mi][ni], ah[mi], &bh[p][s2 * 2]);
                    mma16816(acc[mi][ni], al[mi], &bh[p][s2 * 2]);
                    mma16816(acc[mi][ni], ah[mi], &bl[p][s2 * 2]);
                }
        __syncthreads();
    }

    const int er = mBase + wm * 64 + (lane >> 2);
    const int ec = nBase + wn * 32 + (lane & 3) * 2;

    #pragma unroll
    for (int mi = 0; mi < 4; mi++) {
        #pragma unroll
        for (int ni = 0; ni < 4; ni++) {
            const int gc = ec + ni * 8;
            float b0 = 0.f, b1 = 0.f;
            if (biasb) { b0 = __ldg(&biasb[gc]); b1 = __ldg(&biasb[gc + 1]); }
            #pragma unroll
            for (int half = 0; half < 2; half++) {
                const int gr = er + mi * 16 + half * 8;
                float v0 = acc[mi][ni][half * 2 + 0] * alpha + b0;
                float v1 = acc[mi][ni][half * 2 + 1] * alpha + b1;
                if (EPI == 4) {
                    const long zb = (long)z * ((long)BB * Dm * TT)
                                  + (long)(gr >> 10) * ((long)Dm * TT);
                    const long t = gr & 1023;
                    long a0 = zb + (long)gc * TT + t;
                    long a1 = zb + (long)(gc + 1) * TT + t;
                    bf16 h0 = __float2bfloat16_rn(v0);
                    bf16 h1 = __float2bfloat16_rn(v1);
                    Ch[a0] = h0; Cl[a0] = __float2bfloat16_rn(v0 - __bfloat162float(h0));
                    Ch[a1] = h1; Cl[a1] = __float2bfloat16_rn(v1 - __bfloat162float(h1));
                } else {
                    const long baseo = coff + (long)gr * ldc + gc;
                    if (EPI & 1) {
                        float2 f; f.x = v0; f.y = v1;
                        *(float2*)(Cf + baseo) = f;
                    }
                    if (EPI & 2) {
                        bf16 h0 = __float2bfloat16_rn(v0);
                        bf16 h1 = __float2bfloat16_rn(v1);
                        bf16 l0 = __float2bfloat16_rn(v0 - __bfloat162float(h0));
                        bf16 l1 = __float2bfloat16_rn(v1 - __bfloat162float(h1));
                        uint16_t a16 = *(uint16_t*)&h0, b16v = *(uint16_t*)&h1;
                        uint16_t c16 = *(uint16_t*)&l0, d16 = *(uint16_t*)&l1;
                        *(uint32_t*)(Ch + baseo) = (uint32_t)a16 | ((uint32_t)b16v << 16);
                        *(uint32_t*)(Cl + baseo) = (uint32_t)c16 | ((uint32_t)d16 << 16);
                    }
                }
            }
        }
    }
}

// ============ fused softmax + P@z GEMM ============
// A = raw fp32 scores [z][T][T]; per-row offset rc (c = max + lnZ); P = exp(s - c)
// converted to bf16 hi/lo planes in-kernel (overlapped with MMA of previous stage).
// B = zt planes [z][D][T]. C = parts fp32 [z][T][D].
// smem: AF[2][128][16]f32 (16KB) | AH[2] | AL[2] | BH[2] | BL[2] (6KB each)
#define PZ_AF(s)   ((uint32_t)((s) * 8192))
#define PZ_AH(s)   ((uint32_t)(16384 + (s) * PLANE_BYTES))
#define PZ_AL(s)   ((uint32_t)(28672 + (s) * PLANE_BYTES))
#define PZ_BH(s)   ((uint32_t)(40960 + (s) * PLANE_BYTES))
#define PZ_BL(s)   ((uint32_t)(53248 + (s) * PLANE_BYTES))
#define PZ_SMEM    65536

__global__ void __launch_bounds__(256)
gemm_pz(const float* __restrict__ S, const float* __restrict__ rc,
        const bf16* __restrict__ Bh, const bf16* __restrict__ Bl,
        float* __restrict__ Cf)
{
    extern __shared__ char smem[];
    const uint32_t sb = smem_u32(smem);
    const int tid = threadIdx.x, lane = tid & 31, wid = tid >> 5;
    const int wm = wid >> 2, wn = wid & 3;
    const int z = blockIdx.z;

    const float* Ab = S + (long)z * TT * TT;
    const bf16* Bbh = Bh + (long)z * Dm * TT;
    const bf16* Bbl = Bl + (long)z * Dm * TT;
    const long coff = (long)z * TT * Dm;
    const int mBase = blockIdx.y * 128;
    const int nBase = blockIdx.x * 128;

    // loader indices
    const int lrow = tid >> 1;
    const uint32_t ssubB = (uint32_t)lrow * ROW_BYTES + (tid & 1) * 16;
    const long gB = (long)(nBase + lrow) * TT + (tid & 1) * 8;
    // A fp32: 2 chunks per thread (chunks tid and tid+256); chunk c -> row c>>2, 4 floats
    const int ar0 = tid >> 2, ac0 = (tid & 3) * 4;
    const int ar1 = (tid + 256) >> 2, ac1 = ((tid + 256) & 3) * 4;
    const long gA0 = (long)(mBase + ar0) * TT + ac0;
    const long gA1 = (long)(mBase + ar1) * TT + ac1;
    const uint32_t sA0 = (uint32_t)ar0 * 64 + (tid & 3) * 16;
    const uint32_t sA1 = (uint32_t)ar1 * 64 + ((tid + 256) & 3) * 16;

    // convert indices: thread handles row tid>>1, 8 k-elems
    const int crow = tid >> 1, ck = (tid & 1) * 8;
    const float crc = __ldg(&rc[(long)z * TT + mBase + crow]);

    float acc[4][4][4];
    #pragma unroll
    for (int i = 0; i < 4; i++)
        #pragma unroll
        for (int j = 0; j < 4; j++)
            #pragma unroll
            for (int r = 0; r < 4; r++) acc[i][j][r] = 0.f;

    const int nStages = TT >> 4;   // 64

    // issue cp for stage s into buffer s&1
    auto issue_cp = [&](int s) {
        const uint32_t bsel = (uint32_t)(s & 1);
        const long k0 = (long)s << 4;
        CPASYNC16(sb + PZ_AF(bsel) + sA0, (const char*)(Ab + gA0 + k0));
        CPASYNC16(sb + PZ_AF(bsel) + sA1, (const char*)(Ab + gA1 + k0));
        CPASYNC16(sb + PZ_BH(bsel) + ssubB, (const char*)(Bbh + gB + k0));
        CPASYNC16(sb + PZ_BL(bsel) + ssubB, (const char*)(Bbl + gB + k0));
        CP_COMMIT();
    };
    // convert AF[buf] -> AH/AL[buf]  (exp + hi/lo split)
    auto convert = [&](int s) {
        const uint32_t bsel = (uint32_t)(s & 1);
        const float* af = (const float*)(smem + PZ_AF(bsel) + (uint32_t)crow * 64);
        bf16* ahp = (bf16*)(smem + PZ_AH(bsel) + (uint32_t)crow * ROW_BYTES);
        bf16* alp = (bf16*)(smem + PZ_AL(bsel) + (uint32_t)crow * ROW_BYTES);
        #pragma unroll
        for (int j = 0; j < 8; j += 2) {
            float e0 = __expf(af[ck + j]     - crc);
            float e1 = __expf(af[ck + j + 1] - crc);
            bf16 h0 = __float2bfloat16_rn(e0);
            bf16 h1 = __float2bfloat16_rn(e1);
            bf16 l0 = __float2bfloat16_rn(e0 - __bfloat162float(h0));
            bf16 l1 = __float2bfloat16_rn(e1 - __bfloat162float(h1));
            uint16_t u0 = *(uint16_t*)&h0, u1 = *(uint16_t*)&h1;
            uint16_t v0 = *(uint16_t*)&l0, v1 = *(uint16_t*)&l1;
            *(uint32_t*)(ahp + ck + j) = (uint32_t)u0 | ((uint32_t)u1 << 16);
            *(uint32_t*)(alp + ck + j) = (uint32_t)v0 | ((uint32_t)v1 << 16);
        }
    };

    const uint32_t aoff = (uint32_t)(lane & 15) * ROW_BYTES + (lane >> 4) * 16;
    const int nrow  = (lane & 7) + ((lane >> 4) << 3);
    const int khalf = (lane >> 3) & 1;
    const uint32_t boff = (uint32_t)nrow * ROW_BYTES + khalf * 16;

    // prologue: stage 0 + 1 in flight; convert stage 0
    issue_cp(0);
    issue_cp(1);
    CP_WAIT1();            // stage 0 data ready
    __syncthreads();
    convert(0);
    __syncthreads();

    for (int s = 0; s < nStages; s++) {
        const uint32_t base = (uint32_t)(s & 1);
        // ldmatrix + MMA on stage s
        uint32_t ah[4][4], al[4][4];
        #pragma unroll
        for (int mi = 0; mi < 4; mi++) {
            uint32_t o = sb + PZ_AH(base) + (uint32_t)(wm * 64 + mi * 16) * ROW_BYTES + aoff;
            LDSM4(ah[mi], o);
            LDSM4(al[mi], o + (PZ_AL(0) - PZ_AH(0)));
        }
        uint32_t bh[2][4], bl[2][4];
        #pragma unroll
        for (int p = 0; p < 2; p++) {
            uint32_t o = sb + PZ_BH(base) + (uint32_t)(wn * 32 + p * 16) * ROW_BYTES + boff;
            LDSM4(bh[p], o);
            LDSM4(bl[p], o + (PZ_BL(0) - PZ_BH(0)));
        }
        #pragma unroll
        for (int mi = 0; mi < 4; mi++)
            #pragma unroll
            for (int p = 0; p < 2; p++)
                #pragma unroll
                for (int s2 = 0; s2 < 2; s2++) {
                    const int ni = p * 2 + s2;
                    mma16816(acc[mi][ni], ah[mi], &bh[p][s2 * 2]);
                    mma16816(acc[mi][ni], al[mi], &bh[p][s2 * 2]);
                    mma16816(acc[mi][ni], ah[mi], &bl[p][s2 * 2]);
                }
        // prefetch s+2 into buffer (s&1): AF[s&1] was consumed by convert(s);
        // BH/BL[s&1] were just read by ldmatrix above.
        if (s + 2 < nStages) issue_cp(s + 2);
        if (s + 1 < nStages) {
            if (s + 2 < nStages) { CP_WAIT1(); } else { CP_WAIT0(); }
            __syncthreads();       // all warps done reading buffers; cp (s+1) landed
            convert(s + 1);        // overlaps with tensor-pipe drain of stage s
            __syncthreads();
        }
    }

    const int er = mBase + wm * 64 + (lane >> 2);
    const int ec = nBase + wn * 32 + (lane & 3) * 2;
    #pragma unroll
    for (int mi = 0; mi < 4; mi++)
        #pragma unroll
        for (int ni = 0; ni < 4; ni++)
            #pragma unroll
            for (int half = 0; half < 2; half++) {
                const int gr = er + mi * 16 + half * 8;
                const int gc = ec + ni * 8;
                float2 f;
                f.x = acc[mi][ni][half * 2 + 0];
                f.y = acc[mi][ni][half * 2 + 1];
                *(float2*)(Cf + coff + (long)gr * Dm + gc) = f;
            }
}

// ---------------- transpose + split ----------------
__global__ void __launch_bounds__(256)
tsplit(const float* __restrict__ in, bf16* __restrict__ oh, bf16* __restrict__ ol,
       int R, int C)
{
    __shared__ float t[32][33];
    const int cb = blockIdx.x * 32, rb = blockIdx.y * 32;
    const int x = threadIdx.x & 31, y = threadIdx.x >> 5;
    #pragma unroll
    for (int i = 0; i < 32; i += 8)
        t[y + i][x] = in[(long)(rb + y + i) * C + cb + x];
    __syncthreads();
    #pragma unroll
    for (int i = 0; i < 32; i += 8) {
        float v = t[x][y + i];
        bf16 h = __float2bfloat16_rn(v);
        long o = (long)(cb + y + i) * R + rb + x;
        oh[o] = h;
        ol[o] = __float2bfloat16_rn(v - __bfloat162float(h));
    }
}

// ---------------- elementwise split ----------------
__global__ void __launch_bounds__(256)
esplit(const float* __restrict__ in, bf16* __restrict__ oh, bf16* __restrict__ ol, int n)
{
    int i = blockIdx.x * 256 + threadIdx.x;
    if (i < n) {
        float v = in[i];
        bf16 h = __float2bfloat16_rn(v);
        oh[i] = h;
        ol[i] = __float2bfloat16_rn(v - __bfloat162float(h));
    }
}

// ---------------- vecprep ----------------
__global__ void __launch_bounds__(256)
vecprep(const float* __restrict__ Wk, const float* __restrict__ bq,
        const float* __restrict__ Wo, const float* __restrict__ bv,
        float* __restrict__ w0, float* __restrict__ ccp)
{
    const int bb = blockIdx.x;
    if (bb < 512) {
        const int wid = threadIdx.x >> 5, lane = threadIdx.x & 31;
        const int idx = bb * 8 + wid;
        const int h = idx >> 9, d = idx & 511;
        const float* wr = Wk + (long)h * Dm * Dm + (long)d * Dm;
        const float* bqr = bq + h * Dm;
        float s = 0.f;
        #pragma unroll
        for (int e = lane; e < Dm; e += 32) s += wr[e] * bqr[e];
        #pragma unroll
        for (int o = 16; o; o >>= 1) s += __shfl_xor_sync(0xffffffffu, s, o);
        if (lane == 0) w0[idx] = s;
    } else {
        __shared__ float part[4][64];
        const int ib = bb - 512;
        const int h = ib >> 3, chunk = ib & 7;
        const int e = chunk * 64 + (threadIdx.x & 63);
        const int ms = threadIdx.x >> 6;
        const float* Woh = Wo + (long)h * Dm * Dm;
        const float* bvh = bv + h * Dm;
        float s = 0.f;
        for (int m = ms * 128; m < ms * 128 + 128; m++)
            s += bvh[m] * Woh[(long)m * Dm + e];
        part[ms][threadIdx.x & 63] = s;
        __syncthreads();
        if (threadIdx.x < 64)
            ccp[h * Dm + chunk * 64 + threadIdx.x] =
                part[0][threadIdx.x] + part[1][threadIdx.x] +
                part[2][threadIdx.x] + part[3][threadIdx.x];
    }
}

// ---------------- block reductions ----------------
__device__ __forceinline__ float block_sum(float v, float* sm) {
    #pragma unroll
    for (int o = 16; o; o >>= 1) v += __shfl_xor_sync(0xffffffffu, v, o);
    if ((threadIdx.x & 31) == 0) sm[threadIdx.x >> 5] = v;
    __syncthreads();
    if (threadIdx.x < 8) {
        float s = sm[threadIdx.x];
        #pragma unroll
        for (int o = 4; o; o >>= 1) s += __shfl_xor_sync(0xffu, s, o);
        if (threadIdx.x == 0) sm[0] = s;
    }
    __syncthreads();
    float r = sm[0];
    __syncthreads();
    return r;
}
__device__ __forceinline__ float block_max(float v, float* sm) {
    #pragma unroll
    for (int o = 16; o; o >>= 1) v = fmaxf(v, __shfl_xor_sync(0xffffffffu, v, o));
    if ((threadIdx.x & 31) == 0) sm[threadIdx.x >> 5] = v;
    __syncthreads();
    if (threadIdx.x < 8) {
        float s = sm[threadIdx.x];
        #pragma unroll
        for (int o = 4; o; o >>= 1) s = fmaxf(s, __shfl_xor_sync(0xffu, s, o));
        if (threadIdx.x == 0) sm[0] = s;
    }
    __syncthreads();
    float r = sm[0];
    __syncthreads();
    return r;
}

// ---------------- rowstat: c = rowmax + ln(sum exp(s - rowmax)) ----------------
__global__ void __launch_bounds__(256)
rowstat(const float* __restrict__ S, float* __restrict__ rc)
{
    __shared__ float sm[8];
    const size_t base = (size_t)blockIdx.x * TT;
    const float* p = S + base;
    int t = threadIdx.x;
    float x0 = p[t], x1 = p[t + 256], x2 = p[t + 512], x3 = p[t + 768];
    float m = block_max(fmaxf(fmaxf(x0, x1), fmaxf(x2, x3)), sm);
    float e = __expf(x0 - m) + __expf(x1 - m) + __expf(x2 - m) + __expf(x3 - m);
    float Z = block_sum(e, sm);
    if (t == 0) rc[blockIdx.x] = m + __logf(Z);
}

// ---------------- reduce heads + cc + residual + LN1 -> y1 (fp32 + planes) ----------------
__global__ void __launch_bounds__(256)
reduce_ln1(const float* __restrict__ parts, const float* __restrict__ x,
           const float* __restrict__ ccp, const float* __restrict__ bo,
           const float* __restrict__ g, const float* __restrict__ be,
           float* __restrict__ out, bf16* __restrict__ oh, bf16* __restrict__ ol)
{
    __shared__ float sm[8];
    const long row = blockIdx.x;
    const long b = row >> 10, t0 = row & 1023;
    const int t = threadIdx.x;
    float v0, v1;
    {
        float c0 = bo[t], c1 = bo[t + 256];
        #pragma unroll
        for (int h = 0; h < HH; h++) {
            c0 += ccp[h * Dm + t];
            c1 += ccp[h * Dm + t + 256];
        }
        v0 = x[row * Dm + t] + c0;
        v1 = x[row * Dm + t + 256] + c1;
        #pragma unroll
        for (int h = 0; h < HH; h++) {
            const long pr = (((long)h * BB + b) * TT + t0) * Dm;
            v0 += parts[pr + t];
            v1 += parts[pr + t + 256];
        }
    }
    float mean = block_sum(v0 + v1, sm) * (1.f / Dm);
    float d0 = v0 - mean, d1 = v1 - mean;
    float var = block_sum(d0 * d0 + d1 * d1, sm) * (1.f / Dm);
    float inv = rsqrtf(var + EPSv);
    float o0 = d0 * inv * g[t] + be[t];
    float o1 = d1 * inv * g[t + 256] + be[t + 256];
    out[row * Dm + t] = o0;
    out[row * Dm + t + 256] = o1;
    bf16 h0 = __float2bfloat16_rn(o0), h1 = __float2bfloat16_rn(o1);
    oh[row * Dm + t] = h0;
    oh[row * Dm + t + 256] = h1;
    ol[row * Dm + t] = __float2bfloat16_rn(o0 - __bfloat162float(h0));
    ol[row * Dm + t + 256] = __float2bfloat16_rn(o1 - __bfloat162float(h1));
}

// ---------------- relu + residual + LN2 ----------------
__global__ void __launch_bounds__(256)
add_ln2_kernel(const float* __restrict__ a, const float* __restrict__ res,
               const float* __restrict__ g, const float* __restrict__ be,
               float* __restrict__ out)
{
    __shared__ float sm[8];
    long row = blockIdx.x;
    const float* ap = a + row * Dm;
    const float* rp = res + row * Dm;
    int t = threadIdx.x;
    float v0 = fmaxf(ap[t], 0.f) + rp[t];
    float v1 = fmaxf(ap[t + 256], 0.f) + rp[t + 256];
    float mean = block_sum(v0 + v1, sm) * (1.f / Dm);
    float d0 = v0 - mean, d1 = v1 - mean;
    float var = block_sum(d0 * d0 + d1 * d1, sm) * (1.f / Dm);
    float inv = rsqrtf(var + EPSv);
    out[row * Dm + t]       = d0 * inv * g[t]       + be[t];
    out[row * Dm + t + 256] = d1 * inv * g[t + 256] + be[t + 256];
}

// ---------------- launch ----------------
extern "C" void kernel_launch(void* const* d_in, const int* in_sizes, int n_in,
                              void* d_out, int out_size)
{
    const float* x    = (const float*)d_in[0];
    const float* Wq   = (const float*)d_in[1];
    const float* bq   = (const float*)d_in[2];
    const float* Wk   = (const float*)d_in[3];
    const float* Wv   = (const float*)d_in[5];
    const float* bv   = (const float*)d_in[6];
    const float* Wo   = (const float*)d_in[7];
    const float* bo   = (const float*)d_in[8];
    const float* ln1g = (const float*)d_in[9];
    const float* ln1b = (const float*)d_in[10];
    const float* W1   = (const float*)d_in[11];
    const float* b1   = (const float*)d_in[12];
    const float* W2   = (const float*)d_in[13];
    const float* b2   = (const float*)d_in[14];
    const float* ln2g = (const float*)d_in[15];
    const float* ln2b = (const float*)d_in[16];
    float* out = (float*)d_out;

    bf16 *xh, *xl, *Wqh, *Wql, *Wkh, *Wkl, *Wvh, *Wvl, *WoTh, *WoTl;
    bf16 *W1Th, *W1Tl, *W2Th, *W2Tl, *Mth, *Mtl, *Nth, *Ntl;
    bf16 *uh, *ul, *zth, *ztl, *y1h, *y1l, *f1h, *f1l;
    float *w0, *ccp, *ps, *rc, *parts, *py1, *pff2;
    cudaGetSymbolAddress((void**)&xh, g_xh);     cudaGetSymbolAddress((void**)&xl, g_xl);
    cudaGetSymbolAddress((void**)&Wqh, g_Wqh);   cudaGetSymbolAddress((void**)&Wql, g_Wql);
    cudaGetSymbolAddress((void**)&Wkh, g_Wkh);   cudaGetSymbolAddress((void**)&Wkl, g_Wkl);
    cudaGetSymbolAddress((void**)&Wvh, g_Wvh);   cudaGetSymbolAddress((void**)&Wvl, g_Wvl);
    cudaGetSymbolAddress((void**)&WoTh, g_WoTh); cudaGetSymbolAddress((void**)&WoTl, g_WoTl);
    cudaGetSymbolAddress((void**)&W1Th, g_W1Th); cudaGetSymbolAddress((void**)&W1Tl, g_W1Tl);
    cudaGetSymbolAddress((void**)&W2Th, g_W2Th); cudaGetSymbolAddress((void**)&W2Tl, g_W2Tl);
    cudaGetSymbolAddress((void**)&Mth, g_Mth);   cudaGetSymbolAddress((void**)&Mtl, g_Mtl);
    cudaGetSymbolAddress((void**)&Nth, g_Nth);   cudaGetSymbolAddress((void**)&Ntl, g_Ntl);
    cudaGetSymbolAddress((void**)&w0, g_w0);     cudaGetSymbolAddress((void**)&ccp, g_ccp);
    cudaGetSymbolAddress((void**)&uh, g_uh);     cudaGetSymbolAddress((void**)&ul, g_ul);
    cudaGetSymbolAddress((void**)&zth, g_zth);   cudaGetSymbolAddress((void**)&ztl, g_ztl);
    cudaGetSymbolAddress((void**)&ps, g_s);      cudaGetSymbolAddress((void**)&rc, g_rc);
    cudaGetSymbolAddress((void**)&parts, g_parts);
    cudaGetSymbolAddress((void**)&py1, g_y1);
    cudaGetSymbolAddress((void**)&y1h, g_y1h);   cudaGetSymbolAddress((void**)&y1l, g_y1l);
    cudaGetSymbolAddress((void**)&f1h, g_f1h);   cudaGetSymbolAddress((void**)&f1l, g_f1l);
    cudaGetSymbolAddress((void**)&pff2, g_ff2);

    cudaFuncSetAttribute(gemm_pz, cudaFuncAttributeMaxDynamicSharedMemorySize, PZ_SMEM);

    const float inv_sqrt_d = 0.044194173824159216f;
    const long DD = (long)Dm * Dm;

    // 0-3: splits + vecprep
    esplit<<<(BT * Dm + 255) / 256, 256>>>(x, xh, xl, BT * Dm);
    esplit<<<(HH * Dm * Dm + 255) / 256, 256>>>(Wq, Wqh, Wql, HH * Dm * Dm);
    esplit<<<(HH * Dm * Dm + 255) / 256, 256>>>(Wk, Wkh, Wkl, HH * Dm * Dm);
    vecprep<<<576, 256>>>(Wk, bq, Wo, bv, w0, ccp);

    // 4: Mt_h = Wk_h @ Wq_h^T
    gemm_mma<2><<<dim3(4, 4, HH), 256, SMEM_BYTES>>>(Wkh, Wkl, Wqh, Wql, nullptr,
        nullptr, Mth, Mtl, Dm, Dm, Dm, Dm, DD, DD, 0, 0L, 1, DD, 0L, 1.f);

    // 5: u = x @ M_h + w0_h
    gemm_mma<2><<<dim3(4, BT / 128, HH), 256, SMEM_BYTES>>>(xh, xl, Mth, Mtl, w0,
        nullptr, uh, ul, Dm, Dm, Dm, Dm, 0L, DD, 0, (long)Dm, 1, (long)BT * Dm, 0L, 1.f);

    // 6-7: remaining splits
    esplit<<<(HH * Dm * Dm + 255) / 256, 256>>>(Wv, Wvh, Wvl, HH * Dm * Dm);
    tsplit<<<dim3(Dm / 32, (HH * Dm) / 32), 256>>>(Wo, WoTh, WoTl, HH * Dm, Dm);

    // 8: Nt_h = WoT_h @ Wv_h^T
    gemm_mma<2><<<dim3(4, 4, HH), 256, SMEM_BYTES>>>(WoTh, WoTl, Wvh, Wvl, nullptr,
        nullptr, Nth, Ntl, Dm, HH * Dm, Dm, Dm, (long)Dm, DD, 0, 0L, 1, DD, 0L, 1.f);

    // 9: z^T = (x @ N_h)^T -> [H,B,D,T] planes
    gemm_mma<4><<<dim3(4, BT / 128, HH), 256, SMEM_BYTES>>>(xh, xl, Nth, Ntl, nullptr,
        nullptr, zth, ztl, Dm, Dm, Dm, 0, 0L, DD, 0, 0L, 1, 0L, 0L, 1.f);

    // 10: scores = u @ x^T * 1/sqrt(D)  (fp32)
    gemm_mma<1><<<dim3(TT / 128, TT / 128, HH * BB), 256, SMEM_BYTES>>>(uh, ul, xh, xl,
        nullptr, ps, nullptr, nullptr, Dm, Dm, Dm, TT,
        (long)TT * Dm, (long)TT * Dm, BB, 0L, 1, (long)TT * TT, 0L, inv_sqrt_d);

    // 11: row stats c = m + lnZ  (read-only pass, replaces full softmax)
    rowstat<<<HH * BB * TT, 256>>>(ps, rc);

    // 12: parts = softmax(scores) @ z  (fused exp + split + GEMM)
    gemm_pz<<<dim3(Dm / 128, TT / 128, HH * BB), 256, PZ_SMEM>>>(ps, rc, zth, ztl, parts);

    // 13: y1 = LN(sum_h parts + cc + bo + x)
    reduce_ln1<<<BT, 256>>>(parts, x, ccp, bo, ln1g, ln1b, py1, y1h, y1l);

    // 14-15: FFN weight splits
    tsplit<<<dim3(DFFm / 32, Dm / 32), 256>>>(W1, W1Th, W1Tl, Dm, DFFm);
    tsplit<<<dim3(Dm / 32, DFFm / 32), 256>>>(W2, W2Th, W2Tl, DFFm, Dm);

    // 16: FFN1 -> f1 planes
    gemm_mma<2><<<dim3(DFFm / 128, BT / 128, 1), 256, SMEM_BYTES>>>(y1h, y1l, W1Th, W1Tl,
        b1, nullptr, f1h, f1l, Dm, Dm, Dm, DFFm, 0L, 0L, 0, 0L, 1, 0L, 0L, 1.f);

    // 17: FFN2 -> ff2 fp32
    gemm_mma<1><<<dim3(Dm / 128, BT / 128, 1), 256, SMEM_BYTES>>>(f1h, f1l, W2Th, W2Tl,
        b2, pff2, nullptr, nullptr, DFFm, DFFm, DFFm, Dm, 0L, 0L, 0, 0L, 1, 0L, 0L, 1.f);

    // 18: out = LN(relu(ff2) + y1)
    add_ln2_kernel<<<BT, 256>>>(pff2, py1, ln2g, ln2b, out);
}

// round 13
// speedup vs baseline: 2.3131x; 1.0330x over previous
#include <cuda_runtime.h>
#include <cuda_bf16.h>
#include <math.h>
#include <cstdint>

#define HH   8
#define Dm   512
#define DFFm 2048
#define BB   8
#define TT   1024
#define BT   (BB*TT)
#define EPSv 1e-5f

typedef __nv_bfloat16 bf16;

// ---------------- scratch (static __device__, allocation-free) ----------------
__device__ bf16 g_xh[BT*Dm], g_xl[BT*Dm];
__device__ bf16 g_Wqh[HH*Dm*Dm], g_Wql[HH*Dm*Dm];
__device__ bf16 g_Wkh[HH*Dm*Dm], g_Wkl[HH*Dm*Dm];
__device__ bf16 g_Wvh[HH*Dm*Dm], g_Wvl[HH*Dm*Dm];
__device__ bf16 g_WoTh[Dm*HH*Dm], g_WoTl[Dm*HH*Dm];
__device__ bf16 g_W1Th[DFFm*Dm], g_W1Tl[DFFm*Dm];
__device__ bf16 g_W2Th[Dm*DFFm], g_W2Tl[Dm*DFFm];
__device__ bf16 g_Mth[HH*Dm*Dm], g_Mtl[HH*Dm*Dm];
__device__ bf16 g_Nth[HH*Dm*Dm], g_Ntl[HH*Dm*Dm];
__device__ float g_w0[HH*Dm];
__device__ float g_ccp[HH*Dm];
__device__ bf16 g_uh[HH*BT*Dm], g_ul[HH*BT*Dm];
__device__ bf16 g_zth[HH*BT*Dm], g_ztl[HH*BT*Dm];     // [H,B,D,T]
__device__ float g_s[(size_t)HH*BB*TT*TT];            // 256 MB scores (fp32)
__device__ float g_rc[HH*BB*TT];                      // per-row Z = sum exp(s)
__device__ float g_parts[(size_t)HH*BT*Dm];
__device__ float g_y1[BT*Dm];
__device__ bf16 g_y1h[BT*Dm], g_y1l[BT*Dm];
__device__ bf16 g_f1h[BT*DFFm], g_f1l[BT*DFFm];
__device__ float g_ff2[BT*Dm];

// ---------------- helpers ----------------
__device__ __forceinline__ uint32_t smem_u32(const void* p) {
    uint32_t a;
    asm("{ .reg .u64 t; cvta.to.shared.u64 t, %1; cvt.u32.u64 %0, t; }" : "=r"(a) : "l"(p));
    return a;
}

#define CPASYNC16(sa, ga) \
    asm volatile("cp.async.ca.shared.global [%0], [%1], 16;" :: "r"(sa), "l"(ga) : "memory")
#define CP_COMMIT() asm volatile("cp.async.commit_group;" ::: "memory")
#define CP_WAIT1()  asm volatile("cp.async.wait_group 1;" ::: "memory")
#define CP_WAIT0()  asm volatile("cp.async.wait_group 0;" ::: "memory")

#define LDSM4(r, addr) \
    asm volatile("ldmatrix.sync.aligned.m8n8.x4.shared.b16 {%0,%1,%2,%3}, [%4];" \
        : "=r"((r)[0]), "=r"((r)[1]), "=r"((r)[2]), "=r"((r)[3]) : "r"(addr))

__device__ __forceinline__ void mma16816(float* c, const uint32_t* a, const uint32_t* b) {
    asm volatile("mma.sync.aligned.m16n8k16.row.col.f32.bf16.bf16.f32 "
        "{%0,%1,%2,%3}, {%4,%5,%6,%7}, {%8,%9}, {%0,%1,%2,%3};"
        : "+f"(c[0]), "+f"(c[1]), "+f"(c[2]), "+f"(c[3])
        : "r"(a[0]), "r"(a[1]), "r"(a[2]), "r"(a[3]), "r"(b[0]), "r"(b[1]));
}

#define STAGE_BYTES 24576
#define PLANE_BYTES 6144
#define ROW_BYTES   48
#define SMEM_BYTES  49152

// ============ universal bf16x3 mma.sync GEMM: C = alpha*(A @ B^T) + bias ============
// EPI: 1 = fp32 C (optional fused per-row sum of exp via rowZ), 2 = bf16 hi/lo planes,
//      4 = transposed write [z,B,D,T]
template<int EPI>
__global__ void __launch_bounds__(256)
gemm_mma(const bf16* __restrict__ Ah, const bf16* __restrict__ Al,
         const bf16* __restrict__ Bh, const bf16* __restrict__ Bl,
         const float* __restrict__ bias,
         float* __restrict__ Cf, bf16* __restrict__ Ch, bf16* __restrict__ Cl,
         int K, int lda, int ldb, int ldc,
         long sA, long sB, int modB, long sBias,
         int innerB, long sC_outer, long sC_inner, float alpha,
         float* __restrict__ rowZ, long sZ)
{
    extern __shared__ char smem[];
    const uint32_t sb = smem_u32(smem);

    const int tid = threadIdx.x, lane = tid & 31, wid = tid >> 5;
    const int wm = wid >> 2, wn = wid & 3;
    const int z = blockIdx.z;

    const bf16* Abh = Ah + (long)z * sA;
    const bf16* Abl = Al + (long)z * sA;
    const long bOff = (modB > 0 ? (long)(z % modB) : (long)z) * sB;
    const bf16* Bbh = Bh + bOff;
    const bf16* Bbl = Bl + bOff;
    const float* biasb = bias ? (bias + (long)z * sBias) : nullptr;
    long coff = (innerB > 1) ? (long)(z / innerB) * sC_outer + (long)(z % innerB) * sC_inner
                             : (long)z * sC_outer;

    const int mBase = blockIdx.y * 128;
    const int nBase = blockIdx.x * 128;

    const int lrow = tid >> 1;
    const int lco  = (tid & 1) * 8;
    const uint32_t ssub = (uint32_t)lrow * ROW_BYTES + (tid & 1) * 16;
    const long gA = (long)(mBase + lrow) * lda + lco;
    const long gB = (long)(nBase + lrow) * ldb + lco;

    float acc[4][4][4];
    #pragma unroll
    for (int i = 0; i < 4; i++)
        #pragma unroll
        for (int j = 0; j < 4; j++)
            #pragma unroll
            for (int r = 0; r < 4; r++) acc[i][j][r] = 0.f;

    const int nStages = K >> 4;

    {
        uint32_t base = sb;
        CPASYNC16(base + ssub,                   (const char*)(Abh + gA));
        CPASYNC16(base + PLANE_BYTES + ssub,     (const char*)(Abl + gA));
        CPASYNC16(base + 2*PLANE_BYTES + ssub,   (const char*)(Bbh + gB));
        CPASYNC16(base + 3*PLANE_BYTES + ssub,   (const char*)(Bbl + gB));
        CP_COMMIT();
    }

    const uint32_t aoff = (uint32_t)(lane & 15) * ROW_BYTES + (lane >> 4) * 16;
    const int nrow  = (lane & 7) + ((lane >> 4) << 3);
    const int khalf = (lane >> 3) & 1;
    const uint32_t boff = (uint32_t)nrow * ROW_BYTES + khalf * 16;

    for (int s = 0; s < nStages; s++) {
        if (s + 1 < nStages) {
            uint32_t base = sb + ((s + 1) & 1) * STAGE_BYTES;
            long k0 = (long)(s + 1) << 4;
            CPASYNC16(base + ssub,                 (const char*)(Abh + gA + k0));
            CPASYNC16(base + PLANE_BYTES + ssub,   (const char*)(Abl + gA + k0));
            CPASYNC16(base + 2*PLANE_BYTES + ssub, (const char*)(Bbh + gB + k0));
            CPASYNC16(base + 3*PLANE_BYTES + ssub, (const char*)(Bbl + gB + k0));
            CP_COMMIT();
            CP_WAIT1();
        } else {
            CP_WAIT0();
        }
        __syncthreads();

        const uint32_t base = sb + (s & 1) * STAGE_BYTES;
        uint32_t ah[4][4], al[4][4];
        #pragma unroll
        for (int mi = 0; mi < 4; mi++) {
            uint32_t o = base + (uint32_t)(wm * 64 + mi * 16) * ROW_BYTES + aoff;
            LDSM4(ah[mi], o);
            LDSM4(al[mi], o + PLANE_BYTES);
        }
        uint32_t bh[2][4], bl[2][4];
        #pragma unroll
        for (int p = 0; p < 2; p++) {
            uint32_t o = base + 2*PLANE_BYTES + (uint32_t)(wn * 32 + p * 16) * ROW_BYTES + boff;
            LDSM4(bh[p], o);
            LDSM4(bl[p], o + PLANE_BYTES);
        }
        #pragma unroll
        for (int mi = 0; mi < 4; mi++)
            #pragma unroll
            for (int p = 0; p < 2; p++)
                #pragma unroll
                for (int s2 = 0; s2 < 2; s2++) {
                    const int ni = p * 2 + s2;
                    mma16816(acc[mi][ni], ah[mi], &bh[p][s2 * 2]);
                    mma16816(acc[mi][ni], al[mi], &bh[p][s2 * 2]);
                    mma16816(acc[mi][ni], ah[mi], &bl[p][s2 * 2]);
                }
        __syncthreads();
    }

    const int er = mBase + wm * 64 + (lane >> 2);
    const int ec = nBase + wn * 32 + (lane & 3) * 2;

    float zac[4][2];
    if (EPI == 1 && rowZ) {
        #pragma unroll
        for (int mi = 0; mi < 4; mi++) { zac[mi][0] = 0.f; zac[mi][1] = 0.f; }
    }

    #pragma unroll
    for (int mi = 0; mi < 4; mi++) {
        #pragma unroll
        for (int ni = 0; ni < 4; ni++) {
            const int gc = ec + ni * 8;
            float b0 = 0.f, b1 = 0.f;
            if (biasb) { b0 = __ldg(&biasb[gc]); b1 = __ldg(&biasb[gc + 1]); }
            #pragma unroll
            for (int half = 0; half < 2; half++) {
                const int gr = er + mi * 16 + half * 8;
                float v0 = acc[mi][ni][half * 2 + 0] * alpha + b0;
                float v1 = acc[mi][ni][half * 2 + 1] * alpha + b1;
                if (EPI == 4) {
                    const long zb = (long)z * ((long)BB * Dm * TT)
                                  + (long)(gr >> 10) * ((long)Dm * TT);
                    const long t = gr & 1023;
                    long a0 = zb + (long)gc * TT + t;
                    long a1 = zb + (long)(gc + 1) * TT + t;
                    bf16 h0 = __float2bfloat16_rn(v0);
                    bf16 h1 = __float2bfloat16_rn(v1);
                    Ch[a0] = h0; Cl[a0] = __float2bfloat16_rn(v0 - __bfloat162float(h0));
                    Ch[a1] = h1; Cl[a1] = __float2bfloat16_rn(v1 - __bfloat162float(h1));
                } else {
                    const long baseo = coff + (long)gr * ldc + gc;
                    if (EPI & 1) {
                        float2 f; f.x = v0; f.y = v1;
                        *(float2*)(Cf + baseo) = f;
                        if (rowZ) zac[mi][half] += __expf(v0) + __expf(v1);
                    }
                    if (EPI & 2) {
                        bf16 h0 = __float2bfloat16_rn(v0);
                        bf16 h1 = __float2bfloat16_rn(v1);
                        bf16 l0 = __float2bfloat16_rn(v0 - __bfloat162float(h0));
                        bf16 l1 = __float2bfloat16_rn(v1 - __bfloat162float(h1));
                        uint16_t a16 = *(uint16_t*)&h0, b16v = *(uint16_t*)&h1;
                        uint16_t c16 = *(uint16_t*)&l0, d16 = *(uint16_t*)&l1;
                        *(uint32_t*)(Ch + baseo) = (uint32_t)a16 | ((uint32_t)b16v << 16);
                        *(uint32_t*)(Cl + baseo) = (uint32_t)c16 | ((uint32_t)d16 << 16);
                    }
                }
            }
        }
    }

    if (EPI == 1 && rowZ) {
        #pragma unroll
        for (int mi = 0; mi < 4; mi++)
            #pragma unroll
            for (int half = 0; half < 2; half++) {
                float ssum = zac[mi][half];
                ssum += __shfl_xor_sync(0xffffffffu, ssum, 1);
                ssum += __shfl_xor_sync(0xffffffffu, ssum, 2);
                if ((lane & 3) == 0)
                    atomicAdd(&rowZ[(long)z * sZ + er + mi * 16 + half * 8], ssum);
            }
    }
}

// ============ fused softmax + P@z GEMM (P = exp(s)/Z built in-kernel) ============
#define PZ_AF(s)   ((uint32_t)((s) * 8192))
#define PZ_AH(s)   ((uint32_t)(16384 + (s) * PLANE_BYTES))
#define PZ_AL(s)   ((uint32_t)(28672 + (s) * PLANE_BYTES))
#define PZ_BH(s)   ((uint32_t)(40960 + (s) * PLANE_BYTES))
#define PZ_BL(s)   ((uint32_t)(53248 + (s) * PLANE_BYTES))
#define PZ_SMEM    65536

__global__ void __launch_bounds__(256)
gemm_pz(const float* __restrict__ S, const float* __restrict__ rc,
        const bf16* __restrict__ Bh, const bf16* __restrict__ Bl,
        float* __restrict__ Cf)
{
    extern __shared__ char smem[];
    const uint32_t sb = smem_u32(smem);
    const int tid = threadIdx.x, lane = tid & 31, wid = tid >> 5;
    const int wm = wid >> 2, wn = wid & 3;
    const int z = blockIdx.z;

    const float* Ab = S + (long)z * TT * TT;
    const bf16* Bbh = Bh + (long)z * Dm * TT;
    const bf16* Bbl = Bl + (long)z * Dm * TT;
    const long coff = (long)z * TT * Dm;
    const int mBase = blockIdx.y * 128;
    const int nBase = blockIdx.x * 128;

    const int lrow = tid >> 1;
    const uint32_t ssubB = (uint32_t)lrow * ROW_BYTES + (tid & 1) * 16;
    const long gB = (long)(nBase + lrow) * TT + (tid & 1) * 8;
    const int ar0 = tid >> 2, ac0 = (tid & 3) * 4;
    const int ar1 = (tid + 256) >> 2, ac1 = ((tid + 256) & 3) * 4;
    const long gA0 = (long)(mBase + ar0) * TT + ac0;
    const long gA1 = (long)(mBase + ar1) * TT + ac1;
    const uint32_t sA0 = (uint32_t)ar0 * 64 + (tid & 3) * 16;
    const uint32_t sA1 = (uint32_t)ar1 * 64 + ((tid + 256) & 3) * 16;

    const int crow = tid >> 1, ck = (tid & 1) * 8;
    const float cinv = 1.f / __ldg(&rc[(long)z * TT + mBase + crow]);

    float acc[4][4][4];
    #pragma unroll
    for (int i = 0; i < 4; i++)
        #pragma unroll
        for (int j = 0; j < 4; j++)
            #pragma unroll
            for (int r = 0; r < 4; r++) acc[i][j][r] = 0.f;

    const int nStages = TT >> 4;

    auto issue_cp = [&](int s) {
        const uint32_t bsel = (uint32_t)(s & 1);
        const long k0 = (long)s << 4;
        CPASYNC16(sb + PZ_AF(bsel) + sA0, (const char*)(Ab + gA0 + k0));
        CPASYNC16(sb + PZ_AF(bsel) + sA1, (const char*)(Ab + gA1 + k0));
        CPASYNC16(sb + PZ_BH(bsel) + ssubB, (const char*)(Bbh + gB + k0));
        CPASYNC16(sb + PZ_BL(bsel) + ssubB, (const char*)(Bbl + gB + k0));
        CP_COMMIT();
    };
    auto convert = [&](int s) {
        const uint32_t bsel = (uint32_t)(s & 1);
        const float* af = (const float*)(smem + PZ_AF(bsel) + (uint32_t)crow * 64);
        bf16* ahp = (bf16*)(smem + PZ_AH(bsel) + (uint32_t)crow * ROW_BYTES);
        bf16* alp = (bf16*)(smem + PZ_AL(bsel) + (uint32_t)crow * ROW_BYTES);
        #pragma unroll
        for (int j = 0; j < 8; j += 2) {
            float e0 = __expf(af[ck + j])     * cinv;
            float e1 = __expf(af[ck + j + 1]) * cinv;
            bf16 h0 = __float2bfloat16_rn(e0);
            bf16 h1 = __float2bfloat16_rn(e1);
            bf16 l0 = __float2bfloat16_rn(e0 - __bfloat162float(h0));
            bf16 l1 = __float2bfloat16_rn(e1 - __bfloat162float(h1));
            uint16_t u0 = *(uint16_t*)&h0, u1 = *(uint16_t*)&h1;
            uint16_t v0 = *(uint16_t*)&l0, v1 = *(uint16_t*)&l1;
            *(uint32_t*)(ahp + ck + j) = (uint32_t)u0 | ((uint32_t)u1 << 16);
            *(uint32_t*)(alp + ck + j) = (uint32_t)v0 | ((uint32_t)v1 << 16);
        }
    };

    const uint32_t aoff = (uint32_t)(lane & 15) * ROW_BYTES + (lane >> 4) * 16;
    const int nrow  = (lane & 7) + ((lane >> 4) << 3);
    const int khalf = (lane >> 3) & 1;
    const uint32_t boff = (uint32_t)nrow * ROW_BYTES + khalf * 16;

    issue_cp(0);
    issue_cp(1);
    CP_WAIT1();
    __syncthreads();
    convert(0);
    __syncthreads();

    for (int s = 0; s < nStages; s++) {
        const uint32_t base = (uint32_t)(s & 1);
        uint32_t ah[4][4], al[4][4];
        #pragma unroll
        for (int mi = 0; mi < 4; mi++) {
            uint32_t o = sb + PZ_AH(base) + (uint32_t)(wm * 64 + mi * 16) * ROW_BYTES + aoff;
            LDSM4(ah[mi], o);
            LDSM4(al[mi], o + (PZ_AL(0) - PZ_AH(0)));
        }
        uint32_t bh[2][4], bl[2][4];
        #pragma unroll
        for (int p = 0; p < 2; p++) {
            uint32_t o = sb + PZ_BH(base) + (uint32_t)(wn * 32 + p * 16) * ROW_BYTES + boff;
            LDSM4(bh[p], o);
            LDSM4(bl[p], o + (PZ_BL(0) - PZ_BH(0)));
        }
        #pragma unroll
        for (int mi = 0; mi < 4; mi++)
            #pragma unroll
            for (int p = 0; p < 2; p++)
                #pragma unroll
                for (int s2 = 0; s2 < 2; s2++) {
                    const int ni = p * 2 + s2;
                    mma16816(acc[mi][ni], ah[mi], &bh[p][s2 * 2]);
                    mma16816(acc[mi][ni], al[mi], &bh[p][s2 * 2]);
                    mma16816(acc[mi][ni], ah[mi], &bl[p][s2 * 2]);
                }
        if (s + 2 < nStages) issue_cp(s + 2);
        if (s + 1 < nStages) {
            if (s + 2 < nStages) { CP_WAIT1(); } else { CP_WAIT0(); }
            __syncthreads();
            convert(s + 1);
            __syncthreads();
        }
    }

    const int er = mBase + wm * 64 + (lane >> 2);
    const int ec = nBase + wn * 32 + (lane & 3) * 2;
    #pragma unroll
    for (int mi = 0; mi < 4; mi++)
        #pragma unroll
        for (int ni = 0; ni < 4; ni++)
            #pragma unroll
            for (int half = 0; half < 2; half++) {
                const int gr = er + mi * 16 + half * 8;
                const int gc = ec + ni * 8;
                float2 f;
                f.x = acc[mi][ni][half * 2 + 0];
                f.y = acc[mi][ni][half * 2 + 1];
                *(float2*)(Cf + coff + (long)gr * Dm + gc) = f;
            }
}

// ---------------- transpose + split ----------------
__global__ void __launch_bounds__(256)
tsplit(const float* __restrict__ in, bf16* __restrict__ oh, bf16* __restrict__ ol,
       int R, int C)
{
    __shared__ float t[32][33];
    const int cb = blockIdx.x * 32, rb = blockIdx.y * 32;
    const int x = threadIdx.x & 31, y = threadIdx.x >> 5;
    #pragma unroll
    for (int i = 0; i < 32; i += 8)
        t[y + i][x] = in[(long)(rb + y + i) * C + cb + x];
    __syncthreads();
    #pragma unroll
    for (int i = 0; i < 32; i += 8) {
        float v = t[x][y + i];
        bf16 h = __float2bfloat16_rn(v);
        long o = (long)(cb + y + i) * R + rb + x;
        oh[o] = h;
        ol[o] = __float2bfloat16_rn(v - __bfloat162float(h));
    }
}

// ---------------- elementwise split ----------------
__global__ void __launch_bounds__(256)
esplit(const float* __restrict__ in, bf16* __restrict__ oh, bf16* __restrict__ ol, int n)
{
    int i = blockIdx.x * 256 + threadIdx.x;
    if (i < n) {
        float v = in[i];
        bf16 h = __float2bfloat16_rn(v);
        oh[i] = h;
        ol[i] = __float2bfloat16_rn(v - __bfloat162float(h));
    }
}

// ---------------- zero kernel ----------------
__global__ void __launch_bounds__(256)
zerok(float* __restrict__ p, int n)
{
    int i = blockIdx.x * 256 + threadIdx.x;
    if (i < n) p[i] = 0.f;
}

// ---------------- vecprep ----------------
__global__ void __launch_bounds__(256)
vecprep(const float* __restrict__ Wk, const float* __restrict__ bq,
        const float* __restrict__ Wo, const float* __restrict__ bv,
        float* __restrict__ w0, float* __restrict__ ccp)
{
    const int bb = blockIdx.x;
    if (bb < 512) {
        const int wid = threadIdx.x >> 5, lane = threadIdx.x & 31;
        const int idx = bb * 8 + wid;
        const int h = idx >> 9, d = idx & 511;
        const float* wr = Wk + (long)h * Dm * Dm + (long)d * Dm;
        const float* bqr = bq + h * Dm;
        float s = 0.f;
        #pragma unroll
        for (int e = lane; e < Dm; e += 32) s += wr[e] * bqr[e];
        #pragma unroll
        for (int o = 16; o; o >>= 1) s += __shfl_xor_sync(0xffffffffu, s, o);
        if (lane == 0) w0[idx] = s;
    } else {
        __shared__ float part[4][64];
        const int ib = bb - 512;
        const int h = ib >> 3, chunk = ib & 7;
        const int e = chunk * 64 + (threadIdx.x & 63);
        const int ms = threadIdx.x >> 6;
        const float* Woh = Wo + (long)h * Dm * Dm;
        const float* bvh = bv + h * Dm;
        float s = 0.f;
        for (int m = ms * 128; m < ms * 128 + 128; m++)
            s += bvh[m] * Woh[(long)m * Dm + e];
        part[ms][threadIdx.x & 63] = s;
        __syncthreads();
        if (threadIdx.x < 64)
            ccp[h * Dm + chunk * 64 + threadIdx.x] =
                part[0][threadIdx.x] + part[1][threadIdx.x] +
                part[2][threadIdx.x] + part[3][threadIdx.x];
    }
}

// ---------------- block reductions ----------------
__device__ __forceinline__ float block_sum(float v, float* sm) {
    #pragma unroll
    for (int o = 16; o; o >>= 1) v += __shfl_xor_sync(0xffffffffu, v, o);
    if ((threadIdx.x & 31) == 0) sm[threadIdx.x >> 5] = v;
    __syncthreads();
    if (threadIdx.x < 8) {
        float s = sm[threadIdx.x];
        #pragma unroll
        for (int o = 4; o; o >>= 1) s += __shfl_xor_sync(0xffu, s, o);
        if (threadIdx.x == 0) sm[0] = s;
    }
    __syncthreads();
    float r = sm[0];
    __syncthreads();
    return r;
}

// ---------------- reduce heads + cc + residual + LN1 -> y1 (fp32 + planes) ----------------
__global__ void __launch_bounds__(256)
reduce_ln1(const float* __restrict__ parts, const float* __restrict__ x,
           const float* __restrict__ ccp, const float* __restrict__ bo,
           const float* __restrict__ g, const float* __restrict__ be,
           float* __restrict__ out, bf16* __restrict__ oh, bf16* __restrict__ ol)
{
    __shared__ float sm[8];
    const long row = blockIdx.x;
    const long b = row >> 10, t0 = row & 1023;
    const int t = threadIdx.x;
    float v0, v1;
    {
        float c0 = bo[t], c1 = bo[t + 256];
        #pragma unroll
        for (int h = 0; h < HH; h++) {
            c0 += ccp[h * Dm + t];
            c1 += ccp[h * Dm + t + 256];
        }
        v0 = x[row * Dm + t] + c0;
        v1 = x[row * Dm + t + 256] + c1;
        #pragma unroll
        for (int h = 0; h < HH; h++) {
            const long pr = (((long)h * BB + b) * TT + t0) * Dm;
            v0 += parts[pr + t];
            v1 += parts[pr + t + 256];
        }
    }
    float mean = block_sum(v0 + v1, sm) * (1.f / Dm);
    float d0 = v0 - mean, d1 = v1 - mean;
    float var = block_sum(d0 * d0 + d1 * d1, sm) * (1.f / Dm);
    float inv = rsqrtf(var + EPSv);
    float o0 = d0 * inv * g[t] + be[t];
    float o1 = d1 * inv * g[t + 256] + be[t + 256];
    out[row * Dm + t] = o0;
    out[row * Dm + t + 256] = o1;
    bf16 h0 = __float2bfloat16_rn(o0), h1 = __float2bfloat16_rn(o1);
    oh[row * Dm + t] = h0;
    oh[row * Dm + t + 256] = h1;
    ol[row * Dm + t] = __float2bfloat16_rn(o0 - __bfloat162float(h0));
    ol[row * Dm + t + 256] = __float2bfloat16_rn(o1 - __bfloat162float(h1));
}

// ---------------- relu + residual + LN2 ----------------
__global__ void __launch_bounds__(256)
add_ln2_kernel(const float* __restrict__ a, const float* __restrict__ res,
               const float* __restrict__ g, const float* __restrict__ be,
               float* __restrict__ out)
{
    __shared__ float sm[8];
    long row = blockIdx.x;
    const float* ap = a + row * Dm;
    const float* rp = res + row * Dm;
    int t = threadIdx.x;
    float v0 = fmaxf(ap[t], 0.f) + rp[t];
    float v1 = fmaxf(ap[t + 256], 0.f) + rp[t + 256];
    float mean = block_sum(v0 + v1, sm) * (1.f / Dm);
    float d0 = v0 - mean, d1 = v1 - mean;
    float var = block_sum(d0 * d0 + d1 * d1, sm) * (1.f / Dm);
    float inv = rsqrtf(var + EPSv);
    out[row * Dm + t]       = d0 * inv * g[t]       + be[t];
    out[row * Dm + t + 256] = d1 * inv * g[t + 256] + be[t + 256];
}

// ---------------- stream / event resources (created at load, before checkpoints) ----------------
struct StreamInit {
    cudaStream_t s1;
    cudaEvent_t eF, eM, eB;
    StreamInit() {
        cudaStreamCreateWithFlags(&s1, cudaStreamNonBlocking);
        cudaEventCreateWithFlags(&eF, cudaEventDisableTiming);
        cudaEventCreateWithFlags(&eM, cudaEventDisableTiming);
        cudaEventCreateWithFlags(&eB, cudaEventDisableTiming);
    }
};
static StreamInit g_si;

// ---------------- launch ----------------
extern "C" void kernel_launch(void* const* d_in, const int* in_sizes, int n_in,
                              void* d_out, int out_size)
{
    const float* x    = (const float*)d_in[0];
    const float* Wq   = (const float*)d_in[1];
    const float* bq   = (const float*)d_in[2];
    const float* Wk   = (const float*)d_in[3];
    const float* Wv   = (const float*)d_in[5];
    const float* bv   = (const float*)d_in[6];
    const float* Wo   = (const float*)d_in[7];
    const float* bo   = (const float*)d_in[8];
    const float* ln1g = (const float*)d_in[9];
    const float* ln1b = (const float*)d_in[10];
    const float* W1   = (const float*)d_in[11];
    const float* b1   = (const float*)d_in[12];
    const float* W2   = (const float*)d_in[13];
    const float* b2   = (const float*)d_in[14];
    const float* ln2g = (const float*)d_in[15];
    const float* ln2b = (const float*)d_in[16];
    float* out = (float*)d_out;

    bf16 *xh, *xl, *Wqh, *Wql, *Wkh, *Wkl, *Wvh, *Wvl, *WoTh, *WoTl;
    bf16 *W1Th, *W1Tl, *W2Th, *W2Tl, *Mth, *Mtl, *Nth, *Ntl;
    bf16 *uh, *ul, *zth, *ztl, *y1h, *y1l, *f1h, *f1l;
    float *w0, *ccp, *ps, *rc, *parts, *py1, *pff2;
    cudaGetSymbolAddress((void**)&xh, g_xh);     cudaGetSymbolAddress((void**)&xl, g_xl);
    cudaGetSymbolAddress((void**)&Wqh, g_Wqh);   cudaGetSymbolAddress((void**)&Wql, g_Wql);
    cudaGetSymbolAddress((void**)&Wkh, g_Wkh);   cudaGetSymbolAddress((void**)&Wkl, g_Wkl);
    cudaGetSymbolAddress((void**)&Wvh, g_Wvh);   cudaGetSymbolAddress((void**)&Wvl, g_Wvl);
    cudaGetSymbolAddress((void**)&WoTh, g_WoTh); cudaGetSymbolAddress((void**)&WoTl, g_WoTl);
    cudaGetSymbolAddress((void**)&W1Th, g_W1Th); cudaGetSymbolAddress((void**)&W1Tl, g_W1Tl);
    cudaGetSymbolAddress((void**)&W2Th, g_W2Th); cudaGetSymbolAddress((void**)&W2Tl, g_W2Tl);
    cudaGetSymbolAddress((void**)&Mth, g_Mth);   cudaGetSymbolAddress((void**)&Mtl, g_Mtl);
    cudaGetSymbolAddress((void**)&Nth, g_Nth);   cudaGetSymbolAddress((void**)&Ntl, g_Ntl);
    cudaGetSymbolAddress((void**)&w0, g_w0);     cudaGetSymbolAddress((void**)&ccp, g_ccp);
    cudaGetSymbolAddress((void**)&uh, g_uh);     cudaGetSymbolAddress((void**)&ul, g_ul);
    cudaGetSymbolAddress((void**)&zth, g_zth);   cudaGetSymbolAddress((void**)&ztl, g_ztl);
    cudaGetSymbolAddress((void**)&ps, g_s);      cudaGetSymbolAddress((void**)&rc, g_rc);
    cudaGetSymbolAddress((void**)&parts, g_parts);
    cudaGetSymbolAddress((void**)&py1, g_y1);
    cudaGetSymbolAddress((void**)&y1h, g_y1h);   cudaGetSymbolAddress((void**)&y1l, g_y1l);
    cudaGetSymbolAddress((void**)&f1h, g_f1h);   cudaGetSymbolAddress((void**)&f1l, g_f1l);
    cudaGetSymbolAddress((void**)&pff2, g_ff2);

    cudaFuncSetAttribute(gemm_pz, cudaFuncAttributeMaxDynamicSharedMemorySize, PZ_SMEM);

    const float inv_sqrt_d = 0.044194173824159216f;
    const long DD = (long)Dm * Dm;

    // detect the capturing (or main) stream
    cudaStream_t cap = cudaStreamLegacy;
    {
        cudaStreamCaptureStatus st = cudaStreamCaptureStatusNone;
        cudaStreamIsCapturing(cudaStreamPerThread, &st);
        if (st == cudaStreamCaptureStatusActive) cap = cudaStreamPerThread;
    }
    cudaStream_t s1 = g_si.s1;

    // ---- fork: weight-prep chain on s1, x chain on cap ----
    cudaEventRecord(g_si.eF, cap);
    cudaStreamWaitEvent(s1, g_si.eF, 0);

    // s1: everything needed for u-GEMM first
    vecprep<<<576, 256, 0, s1>>>(Wk, bq, Wo, bv, w0, ccp);
    esplit<<<(HH * Dm * Dm + 255) / 256, 256, 0, s1>>>(Wq, Wqh, Wql, HH * Dm * Dm);
    esplit<<<(HH * Dm * Dm + 255) / 256, 256, 0, s1>>>(Wk, Wkh, Wkl, HH * Dm * Dm);
    gemm_mma<2><<<dim3(4, 4, HH), 256, SMEM_BYTES, s1>>>(Wkh, Wkl, Wqh, Wql, nullptr,
        nullptr, Mth, Mtl, Dm, Dm, Dm, Dm, DD, DD, 0, 0L, 1, DD, 0L, 1.f, nullptr, 0L);
    cudaEventRecord(g_si.eM, s1);
    // s1: remaining weight prep
    esplit<<<(HH * Dm * Dm + 255) / 256, 256, 0, s1>>>(Wv, Wvh, Wvl, HH * Dm * Dm);
    tsplit<<<dim3(Dm / 32, (HH * Dm) / 32), 256, 0, s1>>>(Wo, WoTh, WoTl, HH * Dm, Dm);
    gemm_mma<2><<<dim3(4, 4, HH), 256, SMEM_BYTES, s1>>>(WoTh, WoTl, Wvh, Wvl, nullptr,
        nullptr, Nth, Ntl, Dm, HH * Dm, Dm, Dm, (long)Dm, DD, 0, 0L, 1, DD, 0L, 1.f, nullptr, 0L);
    tsplit<<<dim3(DFFm / 32, Dm / 32), 256, 0, s1>>>(W1, W1Th, W1Tl, Dm, DFFm);
    tsplit<<<dim3(Dm / 32, DFFm / 32), 256, 0, s1>>>(W2, W2Th, W2Tl, DFFm, Dm);
    zerok<<<(HH * BB * TT + 255) / 256, 256, 0, s1>>>(rc, HH * BB * TT);
    cudaEventRecord(g_si.eB, s1);

    // cap: x chain
    esplit<<<(BT * Dm + 255) / 256, 256, 0, cap>>>(x, xh, xl, BT * Dm);
    cudaStreamWaitEvent(cap, g_si.eM, 0);

    // u = x @ M_h + w0_h
    gemm_mma<2><<<dim3(4, BT / 128, HH), 256, SMEM_BYTES, cap>>>(xh, xl, Mth, Mtl, w0,
        nullptr, uh, ul, Dm, Dm, Dm, Dm, 0L, DD, 0, (long)Dm, 1, (long)BT * Dm, 0L, 1.f,
        nullptr, 0L);

    cudaStreamWaitEvent(cap, g_si.eB, 0);

    // z^T = (x @ N_h)^T -> [H,B,D,T] planes
    gemm_mma<4><<<dim3(4, BT / 128, HH), 256, SMEM_BYTES, cap>>>(xh, xl, Nth, Ntl, nullptr,
        nullptr, zth, ztl, Dm, Dm, Dm, 0, 0L, DD, 0, 0L, 1, 0L, 0L, 1.f, nullptr, 0L);

    // scores = u @ x^T * 1/sqrt(D)  (fp32) + fused per-row sum of exp -> rc
    gemm_mma<1><<<dim3(TT / 128, TT / 128, HH * BB), 256, SMEM_BYTES, cap>>>(uh, ul, xh, xl,
        nullptr, ps, nullptr, nullptr, Dm, Dm, Dm, TT,
        (long)TT * Dm, (long)TT * Dm, BB, 0L, 1, (long)TT * TT, 0L, inv_sqrt_d,
        rc, (long)TT);

    // parts = softmax(scores) @ z  (fused exp/Z + split + GEMM)
    gemm_pz<<<dim3(Dm / 128, TT / 128, HH * BB), 256, PZ_SMEM, cap>>>(ps, rc, zth, ztl, parts);

    // y1 = LN(sum_h parts + cc + bo + x)
    reduce_ln1<<<BT, 256, 0, cap>>>(parts, x, ccp, bo, ln1g, ln1b, py1, y1h, y1l);

    // FFN1 -> f1 planes
    gemm_mma<2><<<dim3(DFFm / 128, BT / 128, 1), 256, SMEM_BYTES, cap>>>(y1h, y1l, W1Th, W1Tl,
        b1, nullptr, f1h, f1l, Dm, Dm, Dm, DFFm, 0L, 0L, 0, 0L, 1, 0L, 0L, 1.f, nullptr, 0L);

    // FFN2 -> ff2 fp32
    gemm_mma<1><<<dim3(Dm / 128, BT / 128, 1), 256, SMEM_BYTES, cap>>>(f1h, f1l, W2Th, W2Tl,
        b2, pff2, nullptr, nullptr, DFFm, DFFm, DFFm, Dm, 0L, 0L, 0, 0L, 1, 0L, 0L, 1.f,
        nullptr, 0L);

    // out = LN(relu(ff2) + y1)
    add_ln2_kernel<<<BT, 256, 0, cap>>>(pff2, py1, ln2g, ln2b, out);
}

// round 14
// speedup vs baseline: 2.5829x; 1.1166x over previous
#include <cuda_runtime.h>
#include <cuda_bf16.h>
#include <math.h>
#include <cstdint>

#define HH   8
#define Dm   512
#define DFFm 2048
#define BB   8
#define TT   1024
#define BT   (BB*TT)
#define EPSv 1e-5f

typedef __nv_bfloat16 bf16;

// ---------------- scratch (static __device__, allocation-free) ----------------
__device__ bf16 g_xh[BT*Dm], g_xl[BT*Dm];
__device__ bf16 g_Wqh[HH*Dm*Dm], g_Wql[HH*Dm*Dm];
__device__ bf16 g_Wkh[HH*Dm*Dm], g_Wkl[HH*Dm*Dm];
__device__ bf16 g_Wvh[HH*Dm*Dm], g_Wvl[HH*Dm*Dm];
__device__ bf16 g_WoTh[Dm*HH*Dm], g_WoTl[Dm*HH*Dm];
__device__ bf16 g_W1Th[DFFm*Dm], g_W1Tl[DFFm*Dm];
__device__ bf16 g_W2Th[Dm*DFFm], g_W2Tl[Dm*DFFm];
__device__ bf16 g_Mth[HH*Dm*Dm], g_Mtl[HH*Dm*Dm];
__device__ bf16 g_Nth[HH*Dm*Dm], g_Ntl[HH*Dm*Dm];
__device__ float g_w0[HH*Dm];
__device__ float g_ccp[HH*Dm];
__device__ bf16 g_uh[HH*BT*Dm], g_ul[HH*BT*Dm];
__device__ bf16 g_zth[HH*BT*Dm], g_ztl[HH*BT*Dm];     // [H,B,D,T]
__device__ float g_s[(size_t)HH*BB*TT*TT];            // 256 MB scores (fp32)
__device__ float g_rc[HH*BB*TT];                      // per-row Z = sum exp(s)
__device__ float g_parts[(size_t)HH*BT*Dm];
__device__ float g_y1[BT*Dm];
__device__ bf16 g_y1h[BT*Dm], g_y1l[BT*Dm];
__device__ bf16 g_f1h[BT*DFFm], g_f1l[BT*DFFm];
__device__ float g_ff2[BT*Dm];

// ---------------- helpers ----------------
__device__ __forceinline__ uint32_t smem_u32(const void* p) {
    uint32_t a;
    asm("{ .reg .u64 t; cvta.to.shared.u64 t, %1; cvt.u32.u64 %0, t; }" : "=r"(a) : "l"(p));
    return a;
}

#define CPASYNC16(sa, ga) \
    asm volatile("cp.async.ca.shared.global [%0], [%1], 16;" :: "r"(sa), "l"(ga) : "memory")
#define CP_COMMIT() asm volatile("cp.async.commit_group;" ::: "memory")
#define CP_WAIT1()  asm volatile("cp.async.wait_group 1;" ::: "memory")
#define CP_WAIT0()  asm volatile("cp.async.wait_group 0;" ::: "memory")

#define LDSM4(r, addr) \
    asm volatile("ldmatrix.sync.aligned.m8n8.x4.shared.b16 {%0,%1,%2,%3}, [%4];" \
        : "=r"((r)[0]), "=r"((r)[1]), "=r"((r)[2]), "=r"((r)[3]) : "r"(addr))

__device__ __forceinline__ void mma16816(float* c, const uint32_t* a, const uint32_t* b) {
    asm volatile("mma.sync.aligned.m16n8k16.row.col.f32.bf16.bf16.f32 "
        "{%0,%1,%2,%3}, {%4,%5,%6,%7}, {%8,%9}, {%0,%1,%2,%3};"
        : "+f"(c[0]), "+f"(c[1]), "+f"(c[2]), "+f"(c[3])
        : "r"(a[0]), "r"(a[1]), "r"(a[2]), "r"(a[3]), "r"(b[0]), "r"(b[1]));
}

#define STAGE_BYTES 24576
#define PLANE_BYTES 6144
#define ROW_BYTES   48
#define SMEM_BYTES  49152

// ============ universal bf16x3 mma.sync GEMM: C = alpha*(A @ B^T) + bias ============
// EPI: 1 = fp32 C (optional fused per-row sum of exp via rowZ), 2 = bf16 hi/lo planes,
//      4 = transposed write [z,B,D,T]
// DROPBL: 1 = skip B-lo plane (2 MMAs: ah*bh + al*bh) for precision-diluted GEMMs.
template<int EPI, int DROPBL>
__global__ void __launch_bounds__(256)
gemm_mma(const bf16* __restrict__ Ah, const bf16* __restrict__ Al,
         const bf16* __restrict__ Bh, const bf16* __restrict__ Bl,
         const float* __restrict__ bias,
         float* __restrict__ Cf, bf16* __restrict__ Ch, bf16* __restrict__ Cl,
         int K, int lda, int ldb, int ldc,
         long sA, long sB, int modB, long sBias,
         int innerB, long sC_outer, long sC_inner, float alpha,
         float* __restrict__ rowZ, long sZ)
{
    extern __shared__ char smem[];
    const uint32_t sb = smem_u32(smem);

    const int tid = threadIdx.x, lane = tid & 31, wid = tid >> 5;
    const int wm = wid >> 2, wn = wid & 3;
    const int z = blockIdx.z;

    const bf16* Abh = Ah + (long)z * sA;
    const bf16* Abl = Al + (long)z * sA;
    const long bOff = (modB > 0 ? (long)(z % modB) : (long)z) * sB;
    const bf16* Bbh = Bh + bOff;
    const bf16* Bbl = Bl + bOff;
    const float* biasb = bias ? (bias + (long)z * sBias) : nullptr;
    long coff = (innerB > 1) ? (long)(z / innerB) * sC_outer + (long)(z % innerB) * sC_inner
                             : (long)z * sC_outer;

    const int mBase = blockIdx.y * 128;
    const int nBase = blockIdx.x * 128;

    const int lrow = tid >> 1;
    const int lco  = (tid & 1) * 8;
    const uint32_t ssub = (uint32_t)lrow * ROW_BYTES + (tid & 1) * 16;
    const long gA = (long)(mBase + lrow) * lda + lco;
    const long gB = (long)(nBase + lrow) * ldb + lco;

    float acc[4][4][4];
    #pragma unroll
    for (int i = 0; i < 4; i++)
        #pragma unroll
        for (int j = 0; j < 4; j++)
            #pragma unroll
            for (int r = 0; r < 4; r++) acc[i][j][r] = 0.f;

    const int nStages = K >> 4;

    {
        uint32_t base = sb;
        CPASYNC16(base + ssub,                   (const char*)(Abh + gA));
        CPASYNC16(base + PLANE_BYTES + ssub,     (const char*)(Abl + gA));
        CPASYNC16(base + 2*PLANE_BYTES + ssub,   (const char*)(Bbh + gB));
        if (!DROPBL) CPASYNC16(base + 3*PLANE_BYTES + ssub, (const char*)(Bbl + gB));
        CP_COMMIT();
    }

    const uint32_t aoff = (uint32_t)(lane & 15) * ROW_BYTES + (lane >> 4) * 16;
    const int nrow  = (lane & 7) + ((lane >> 4) << 3);
    const int khalf = (lane >> 3) & 1;
    const uint32_t boff = (uint32_t)nrow * ROW_BYTES + khalf * 16;

    for (int s = 0; s < nStages; s++) {
        if (s + 1 < nStages) {
            uint32_t base = sb + ((s + 1) & 1) * STAGE_BYTES;
            long k0 = (long)(s + 1) << 4;
            CPASYNC16(base + ssub,                 (const char*)(Abh + gA + k0));
            CPASYNC16(base + PLANE_BYTES + ssub,   (const char*)(Abl + gA + k0));
            CPASYNC16(base + 2*PLANE_BYTES + ssub, (const char*)(Bbh + gB + k0));
            if (!DROPBL) CPASYNC16(base + 3*PLANE_BYTES + ssub, (const char*)(Bbl + gB + k0));
            CP_COMMIT();
            CP_WAIT1();
        } else {
            CP_WAIT0();
        }
        __syncthreads();

        const uint32_t base = sb + (s & 1) * STAGE_BYTES;
        uint32_t ah[4][4], al[4][4];
        #pragma unroll
        for (int mi = 0; mi < 4; mi++) {
            uint32_t o = base + (uint32_t)(wm * 64 + mi * 16) * ROW_BYTES + aoff;
            LDSM4(ah[mi], o);
            LDSM4(al[mi], o + PLANE_BYTES);
        }
        uint32_t bh[2][4], bl[2][4];
        #pragma unroll
        for (int p = 0; p < 2; p++) {
            uint32_t o = base + 2*PLANE_BYTES + (uint32_t)(wn * 32 + p * 16) * ROW_BYTES + boff;
            LDSM4(bh[p], o);
            if (!DROPBL) LDSM4(bl[p], o + PLANE_BYTES);
        }
        #pragma unroll
        for (int mi = 0; mi < 4; mi++)
            #pragma unroll
            for (int p = 0; p < 2; p++)
                #pragma unroll
                for (int s2 = 0; s2 < 2; s2++) {
                    const int ni = p * 2 + s2;
                    mma16816(acc[mi][ni], ah[mi], &bh[p][s2 * 2]);
                    mma16816(acc[mi][ni], al[mi], &bh[p][s2 * 2]);
                    if (!DROPBL) mma16816(acc[mi][ni], ah[mi], &bl[p][s2 * 2]);
                }
        __syncthreads();
    }

    const int er = mBase + wm * 64 + (lane >> 2);
    const int ec = nBase + wn * 32 + (lane & 3) * 2;

    float zac[4][2];
    if (EPI == 1 && rowZ) {
        #pragma unroll
        for (int mi = 0; mi < 4; mi++) { zac[mi][0] = 0.f; zac[mi][1] = 0.f; }
    }

    #pragma unroll
    for (int mi = 0; mi < 4; mi++) {
        #pragma unroll
        for (int ni = 0; ni < 4; ni++) {
            const int gc = ec + ni * 8;
            float b0 = 0.f, b1 = 0.f;
            if (biasb) { b0 = __ldg(&biasb[gc]); b1 = __ldg(&biasb[gc + 1]); }
            #pragma unroll
            for (int half = 0; half < 2; half++) {
                const int gr = er + mi * 16 + half * 8;
                float v0 = acc[mi][ni][half * 2 + 0] * alpha + b0;
                float v1 = acc[mi][ni][half * 2 + 1] * alpha + b1;
                if (EPI == 4) {
                    const long zb = (long)z * ((long)BB * Dm * TT)
                                  + (long)(gr >> 10) * ((long)Dm * TT);
                    const long t = gr & 1023;
                    long a0 = zb + (long)gc * TT + t;
                    long a1 = zb + (long)(gc + 1) * TT + t;
                    bf16 h0 = __float2bfloat16_rn(v0);
                    bf16 h1 = __float2bfloat16_rn(v1);
                    Ch[a0] = h0; Cl[a0] = __float2bfloat16_rn(v0 - __bfloat162float(h0));
                    Ch[a1] = h1; Cl[a1] = __float2bfloat16_rn(v1 - __bfloat162float(h1));
                } else {
                    const long baseo = coff + (long)gr * ldc + gc;
                    if (EPI & 1) {
                        float2 f; f.x = v0; f.y = v1;
                        *(float2*)(Cf + baseo) = f;
                        if (rowZ) zac[mi][half] += __expf(v0) + __expf(v1);
                    }
                    if (EPI & 2) {
                        bf16 h0 = __float2bfloat16_rn(v0);
                        bf16 h1 = __float2bfloat16_rn(v1);
                        bf16 l0 = __float2bfloat16_rn(v0 - __bfloat162float(h0));
                        bf16 l1 = __float2bfloat16_rn(v1 - __bfloat162float(h1));
                        uint16_t a16 = *(uint16_t*)&h0, b16v = *(uint16_t*)&h1;
                        uint16_t c16 = *(uint16_t*)&l0, d16 = *(uint16_t*)&l1;
                        *(uint32_t*)(Ch + baseo) = (uint32_t)a16 | ((uint32_t)b16v << 16);
                        *(uint32_t*)(Cl + baseo) = (uint32_t)c16 | ((uint32_t)d16 << 16);
                    }
                }
            }
        }
    }

    if (EPI == 1 && rowZ) {
        #pragma unroll
        for (int mi = 0; mi < 4; mi++)
            #pragma unroll
            for (int half = 0; half < 2; half++) {
                float ssum = zac[mi][half];
                ssum += __shfl_xor_sync(0xffffffffu, ssum, 1);
                ssum += __shfl_xor_sync(0xffffffffu, ssum, 2);
                if ((lane & 3) == 0)
                    atomicAdd(&rowZ[(long)z * sZ + er + mi * 16 + half * 8], ssum);
            }
    }
}

// ============ fused softmax + P@z GEMM (P = exp(s)/Z built in-kernel) ============
// 2-term product: ph*zh + pl*zh  (z-lo dropped; diluted by mha/x ratio)
#define PZ_AF(s)   ((uint32_t)((s) * 8192))
#define PZ_AH(s)   ((uint32_t)(16384 + (s) * PLANE_BYTES))
#define PZ_AL(s)   ((uint32_t)(28672 + (s) * PLANE_BYTES))
#define PZ_BH(s)   ((uint32_t)(40960 + (s) * PLANE_BYTES))
#define PZ_SMEM    53248

__global__ void __launch_bounds__(256)
gemm_pz(const float* __restrict__ S, const float* __restrict__ rc,
        const bf16* __restrict__ Bh,
        float* __restrict__ Cf)
{
    extern __shared__ char smem[];
    const uint32_t sb = smem_u32(smem);
    const int tid = threadIdx.x, lane = tid & 31, wid = tid >> 5;
    const int wm = wid >> 2, wn = wid & 3;
    const int z = blockIdx.z;

    const float* Ab = S + (long)z * TT * TT;
    const bf16* Bbh = Bh + (long)z * Dm * TT;
    const long coff = (long)z * TT * Dm;
    const int mBase = blockIdx.y * 128;
    const int nBase = blockIdx.x * 128;

    const int lrow = tid >> 1;
    const uint32_t ssubB = (uint32_t)lrow * ROW_BYTES + (tid & 1) * 16;
    const long gB = (long)(nBase + lrow) * TT + (tid & 1) * 8;
    const int ar0 = tid >> 2, ac0 = (tid & 3) * 4;
    const int ar1 = (tid + 256) >> 2, ac1 = ((tid + 256) & 3) * 4;
    const long gA0 = (long)(mBase + ar0) * TT + ac0;
    const long gA1 = (long)(mBase + ar1) * TT + ac1;
    const uint32_t sA0 = (uint32_t)ar0 * 64 + (tid & 3) * 16;
    const uint32_t sA1 = (uint32_t)ar1 * 64 + ((tid + 256) & 3) * 16;

    const int crow = tid >> 1, ck = (tid & 1) * 8;
    const float cinv = 1.f / __ldg(&rc[(long)z * TT + mBase + crow]);

    float acc[4][4][4];
    #pragma unroll
    for (int i = 0; i < 4; i++)
        #pragma unroll
        for (int j = 0; j < 4; j++)
            #pragma unroll
            for (int r = 0; r < 4; r++) acc[i][j][r] = 0.f;

    const int nStages = TT >> 4;

    auto issue_cp = [&](int s) {
        const uint32_t bsel = (uint32_t)(s & 1);
        const long k0 = (long)s << 4;
        CPASYNC16(sb + PZ_AF(bsel) + sA0, (const char*)(Ab + gA0 + k0));
        CPASYNC16(sb + PZ_AF(bsel) + sA1, (const char*)(Ab + gA1 + k0));
        CPASYNC16(sb + PZ_BH(bsel) + ssubB, (const char*)(Bbh + gB + k0));
        CP_COMMIT();
    };
    auto convert = [&](int s) {
        const uint32_t bsel = (uint32_t)(s & 1);
        const float* af = (const float*)(smem + PZ_AF(bsel) + (uint32_t)crow * 64);
        bf16* ahp = (bf16*)(smem + PZ_AH(bsel) + (uint32_t)crow * ROW_BYTES);
        bf16* alp = (bf16*)(smem + PZ_AL(bsel) + (uint32_t)crow * ROW_BYTES);
        #pragma unroll
        for (int j = 0; j < 8; j += 2) {
            float e0 = __expf(af[ck + j])     * cinv;
            float e1 = __expf(af[ck + j + 1]) * cinv;
            bf16 h0 = __float2bfloat16_rn(e0);
            bf16 h1 = __float2bfloat16_rn(e1);
            bf16 l0 = __float2bfloat16_rn(e0 - __bfloat162float(h0));
            bf16 l1 = __float2bfloat16_rn(e1 - __bfloat162float(h1));
            uint16_t u0 = *(uint16_t*)&h0, u1 = *(uint16_t*)&h1;
            uint16_t v0 = *(uint16_t*)&l0, v1 = *(uint16_t*)&l1;
            *(uint32_t*)(ahp + ck + j) = (uint32_t)u0 | ((uint32_t)u1 << 16);
            *(uint32_t*)(alp + ck + j) = (uint32_t)v0 | ((uint32_t)v1 << 16);
        }
    };

    const uint32_t aoff = (uint32_t)(lane & 15) * ROW_BYTES + (lane >> 4) * 16;
    const int nrow  = (lane & 7) + ((lane >> 4) << 3);
    const int khalf = (lane >> 3) & 1;
    const uint32_t boff = (uint32_t)nrow * ROW_BYTES + khalf * 16;

    issue_cp(0);
    issue_cp(1);
    CP_WAIT1();
    __syncthreads();
    convert(0);
    __syncthreads();

    for (int s = 0; s < nStages; s++) {
        const uint32_t base = (uint32_t)(s & 1);
        uint32_t ah[4][4], al[4][4];
        #pragma unroll
        for (int mi = 0; mi < 4; mi++) {
            uint32_t o = sb + PZ_AH(base) + (uint32_t)(wm * 64 + mi * 16) * ROW_BYTES + aoff;
            LDSM4(ah[mi], o);
            LDSM4(al[mi], o + (PZ_AL(0) - PZ_AH(0)));
        }
        uint32_t bh[2][4];
        #pragma unroll
        for (int p = 0; p < 2; p++) {
            uint32_t o = sb + PZ_BH(base) + (uint32_t)(wn * 32 + p * 16) * ROW_BYTES + boff;
            LDSM4(bh[p], o);
        }
        #pragma unroll
        for (int mi = 0; mi < 4; mi++)
            #pragma unroll
            for (int p = 0; p < 2; p++)
                #pragma unroll
                for (int s2 = 0; s2 < 2; s2++) {
                    const int ni = p * 2 + s2;
                    mma16816(acc[mi][ni], ah[mi], &bh[p][s2 * 2]);
                    mma16816(acc[mi][ni], al[mi], &bh[p][s2 * 2]);
                }
        if (s + 2 < nStages) issue_cp(s + 2);
        if (s + 1 < nStages) {
            if (s + 2 < nStages) { CP_WAIT1(); } else { CP_WAIT0(); }
            __syncthreads();
            convert(s + 1);
            __syncthreads();
        }
    }

    const int er = mBase + wm * 64 + (lane >> 2);
    const int ec = nBase + wn * 32 + (lane & 3) * 2;
    #pragma unroll
    for (int mi = 0; mi < 4; mi++)
        #pragma unroll
        for (int ni = 0; ni < 4; ni++)
            #pragma unroll
            for (int half = 0; half < 2; half++) {
                const int gr = er + mi * 16 + half * 8;
                const int gc = ec + ni * 8;
                float2 f;
                f.x = acc[mi][ni][half * 2 + 0];
                f.y = acc[mi][ni][half * 2 + 1];
                *(float2*)(Cf + coff + (long)gr * Dm + gc) = f;
            }
}

// ---------------- transpose + split ----------------
__global__ void __launch_bounds__(256)
tsplit(const float* __restrict__ in, bf16* __restrict__ oh, bf16* __restrict__ ol,
       int R, int C)
{
    __shared__ float t[32][33];
    const int cb = blockIdx.x * 32, rb = blockIdx.y * 32;
    const int x = threadIdx.x & 31, y = threadIdx.x >> 5;
    #pragma unroll
    for (int i = 0; i < 32; i += 8)
        t[y + i][x] = in[(long)(rb + y + i) * C + cb + x];
    __syncthreads();
    #pragma unroll
    for (int i = 0; i < 32; i += 8) {
        float v = t[x][y + i];
        bf16 h = __float2bfloat16_rn(v);
        long o = (long)(cb + y + i) * R + rb + x;
        oh[o] = h;
        ol[o] = __float2bfloat16_rn(v - __bfloat162float(h));
    }
}

// ---------------- elementwise split ----------------
__global__ void __launch_bounds__(256)
esplit(const float* __restrict__ in, bf16* __restrict__ oh, bf16* __restrict__ ol, int n)
{
    int i = blockIdx.x * 256 + threadIdx.x;
    if (i < n) {
        float v = in[i];
        bf16 h = __float2bfloat16_rn(v);
        oh[i] = h;
        ol[i] = __float2bfloat16_rn(v - __bfloat162float(h));
    }
}

// ---------------- zero kernel ----------------
__global__ void __launch_bounds__(256)
zerok(float* __restrict__ p, int n)
{
    int i = blockIdx.x * 256 + threadIdx.x;
    if (i < n) p[i] = 0.f;
}

// ---------------- vecprep ----------------
__global__ void __launch_bounds__(256)
vecprep(const float* __restrict__ Wk, const float* __restrict__ bq,
        const float* __restrict__ Wo, const float* __restrict__ bv,
        float* __restrict__ w0, float* __restrict__ ccp)
{
    const int bb = blockIdx.x;
    if (bb < 512) {
        const int wid = threadIdx.x >> 5, lane = threadIdx.x & 31;
        const int idx = bb * 8 + wid;
        const int h = idx >> 9, d = idx & 511;
        const float* wr = Wk + (long)h * Dm * Dm + (long)d * Dm;
        const float* bqr = bq + h * Dm;
        float s = 0.f;
        #pragma unroll
        for (int e = lane; e < Dm; e += 32) s += wr[e] * bqr[e];
        #pragma unroll
        for (int o = 16; o; o >>= 1) s += __shfl_xor_sync(0xffffffffu, s, o);
        if (lane == 0) w0[idx] = s;
    } else {
        __shared__ float part[4][64];
        const int ib = bb - 512;
        const int h = ib >> 3, chunk = ib & 7;
        const int e = chunk * 64 + (threadIdx.x & 63);
        const int ms = threadIdx.x >> 6;
        const float* Woh = Wo + (long)h * Dm * Dm;
        const float* bvh = bv + h * Dm;
        float s = 0.f;
        for (int m = ms * 128; m < ms * 128 + 128; m++)
            s += bvh[m] * Woh[(long)m * Dm + e];
        part[ms][threadIdx.x & 63] = s;
        __syncthreads();
        if (threadIdx.x < 64)
            ccp[h * Dm + chunk * 64 + threadIdx.x] =
                part[0][threadIdx.x] + part[1][threadIdx.x] +
                part[2][threadIdx.x] + part[3][threadIdx.x];
    }
}

// ---------------- block reductions ----------------
__device__ __forceinline__ float block_sum(float v, float* sm) {
    #pragma unroll
    for (int o = 16; o; o >>= 1) v += __shfl_xor_sync(0xffffffffu, v, o);
    if ((threadIdx.x & 31) == 0) sm[threadIdx.x >> 5] = v;
    __syncthreads();
    if (threadIdx.x < 8) {
        float s = sm[threadIdx.x];
        #pragma unroll
        for (int o = 4; o; o >>= 1) s += __shfl_xor_sync(0xffu, s, o);
        if (threadIdx.x == 0) sm[0] = s;
    }
    __syncthreads();
    float r = sm[0];
    __syncthreads();
    return r;
}

// ---------------- reduce heads + cc + residual + LN1 -> y1 (fp32 + planes) ----------------
__global__ void __launch_bounds__(256)
reduce_ln1(const float* __restrict__ parts, const float* __restrict__ x,
           const float* __restrict__ ccp, const float* __restrict__ bo,
           const float* __restrict__ g, const float* __restrict__ be,
           float* __restrict__ out, bf16* __restrict__ oh, bf16* __restrict__ ol)
{
    __shared__ float sm[8];
    const long row = blockIdx.x;
    const long b = row >> 10, t0 = row & 1023;
    const int t = threadIdx.x;
    float v0, v1;
    {
        float c0 = bo[t], c1 = bo[t + 256];
        #pragma unroll
        for (int h = 0; h < HH; h++) {
            c0 += ccp[h * Dm + t];
            c1 += ccp[h * Dm + t + 256];
        }
        v0 = x[row * Dm + t] + c0;
        v1 = x[row * Dm + t + 256] + c1;
        #pragma unroll
        for (int h = 0; h < HH; h++) {
            const long pr = (((long)h * BB + b) * TT + t0) * Dm;
            v0 += parts[pr + t];
            v1 += parts[pr + t + 256];
        }
    }
    float mean = block_sum(v0 + v1, sm) * (1.f / Dm);
    float d0 = v0 - mean, d1 = v1 - mean;
    float var = block_sum(d0 * d0 + d1 * d1, sm) * (1.f / Dm);
    float inv = rsqrtf(var + EPSv);
    float o0 = d0 * inv * g[t] + be[t];
    float o1 = d1 * inv * g[t + 256] + be[t + 256];
    out[row * Dm + t] = o0;
    out[row * Dm + t + 256] = o1;
    bf16 h0 = __float2bfloat16_rn(o0), h1 = __float2bfloat16_rn(o1);
    oh[row * Dm + t] = h0;
    oh[row * Dm + t + 256] = h1;
    ol[row * Dm + t] = __float2bfloat16_rn(o0 - __bfloat162float(h0));
    ol[row * Dm + t + 256] = __float2bfloat16_rn(o1 - __bfloat162float(h1));
}

// ---------------- relu + residual + LN2 ----------------
__global__ void __launch_bounds__(256)
add_ln2_kernel(const float* __restrict__ a, const float* __restrict__ res,
               const float* __restrict__ g, const float* __restrict__ be,
               float* __restrict__ out)
{
    __shared__ float sm[8];
    long row = blockIdx.x;
    const float* ap = a + row * Dm;
    const float* rp = res + row * Dm;
    int t = threadIdx.x;
    float v0 = fmaxf(ap[t], 0.f) + rp[t];
    float v1 = fmaxf(ap[t + 256], 0.f) + rp[t + 256];
    float mean = block_sum(v0 + v1, sm) * (1.f / Dm);
    float d0 = v0 - mean, d1 = v1 - mean;
    float var = block_sum(d0 * d0 + d1 * d1, sm) * (1.f / Dm);
    float inv = rsqrtf(var + EPSv);
    out[row * Dm + t]       = d0 * inv * g[t]       + be[t];
    out[row * Dm + t + 256] = d1 * inv * g[t + 256] + be[t + 256];
}

// ---------------- stream / event resources (created at load, before checkpoints) ----------------
struct StreamInit {
    cudaStream_t s1, s2;
    cudaEvent_t eF, eM, eB, eV;
    StreamInit() {
        cudaStreamCreateWithFlags(&s1, cudaStreamNonBlocking);
        cudaStreamCreateWithFlags(&s2, cudaStreamNonBlocking);
        cudaEventCreateWithFlags(&eF, cudaEventDisableTiming);
        cudaEventCreateWithFlags(&eM, cudaEventDisableTiming);
        cudaEventCreateWithFlags(&eB, cudaEventDisableTiming);
        cudaEventCreateWithFlags(&eV, cudaEventDisableTiming);
    }
};
static StreamInit g_si;

// ---------------- launch ----------------
extern "C" void kernel_launch(void* const* d_in, const int* in_sizes, int n_in,
                              void* d_out, int out_size)
{
    const float* x    = (const float*)d_in[0];
    const float* Wq   = (const float*)d_in[1];
    const float* bq   = (const float*)d_in[2];
    const float* Wk   = (const float*)d_in[3];
    const float* Wv   = (const float*)d_in[5];
    const float* bv   = (const float*)d_in[6];
    const float* Wo   = (const float*)d_in[7];
    const float* bo   = (const float*)d_in[8];
    const float* ln1g = (const float*)d_in[9];
    const float* ln1b = (const float*)d_in[10];
    const float* W1   = (const float*)d_in[11];
    const float* b1   = (const float*)d_in[12];
    const float* W2   = (const float*)d_in[13];
    const float* b2   = (const float*)d_in[14];
    const float* ln2g = (const float*)d_in[15];
    const float* ln2b = (const float*)d_in[16];
    float* out = (float*)d_out;

    bf16 *xh, *xl, *Wqh, *Wql, *Wkh, *Wkl, *Wvh, *Wvl, *WoTh, *WoTl;
    bf16 *W1Th, *W1Tl, *W2Th, *W2Tl, *Mth, *Mtl, *Nth, *Ntl;
    bf16 *uh, *ul, *zth, *ztl, *y1h, *y1l, *f1h, *f1l;
    float *w0, *ccp, *ps, *rc, *parts, *py1, *pff2;
    cudaGetSymbolAddress((void**)&xh, g_xh);     cudaGetSymbolAddress((void**)&xl, g_xl);
    cudaGetSymbolAddress((void**)&Wqh, g_Wqh);   cudaGetSymbolAddress((void**)&Wql, g_Wql);
    cudaGetSymbolAddress((void**)&Wkh, g_Wkh);   cudaGetSymbolAddress((void**)&Wkl, g_Wkl);
    cudaGetSymbolAddress((void**)&Wvh, g_Wvh);   cudaGetSymbolAddress((void**)&Wvl, g_Wvl);
    cudaGetSymbolAddress((void**)&WoTh, g_WoTh); cudaGetSymbolAddress((void**)&WoTl, g_WoTl);
    cudaGetSymbolAddress((void**)&W1Th, g_W1Th); cudaGetSymbolAddress((void**)&W1Tl, g_W1Tl);
    cudaGetSymbolAddress((void**)&W2Th, g_W2Th); cudaGetSymbolAddress((void**)&W2Tl, g_W2Tl);
    cudaGetSymbolAddress((void**)&Mth, g_Mth);   cudaGetSymbolAddress((void**)&Mtl, g_Mtl);
    cudaGetSymbolAddress((void**)&Nth, g_Nth);   cudaGetSymbolAddress((void**)&Ntl, g_Ntl);
    cudaGetSymbolAddress((void**)&w0, g_w0);     cudaGetSymbolAddress((void**)&ccp, g_ccp);
    cudaGetSymbolAddress((void**)&uh, g_uh);     cudaGetSymbolAddress((void**)&ul, g_ul);
    cudaGetSymbolAddress((void**)&zth, g_zth);   cudaGetSymbolAddress((void**)&ztl, g_ztl);
    cudaGetSymbolAddress((void**)&ps, g_s);      cudaGetSymbolAddress((void**)&rc, g_rc);
    cudaGetSymbolAddress((void**)&parts, g_parts);
    cudaGetSymbolAddress((void**)&py1, g_y1);
    cudaGetSymbolAddress((void**)&y1h, g_y1h);   cudaGetSymbolAddress((void**)&y1l, g_y1l);
    cudaGetSymbolAddress((void**)&f1h, g_f1h);   cudaGetSymbolAddress((void**)&f1l, g_f1l);
    cudaGetSymbolAddress((void**)&pff2, g_ff2);

    cudaFuncSetAttribute(gemm_pz, cudaFuncAttributeMaxDynamicSharedMemorySize, PZ_SMEM);

    const float inv_sqrt_d = 0.044194173824159216f;
    const long DD = (long)Dm * Dm;

    // detect the capturing (or main) stream
    cudaStream_t cap = cudaStreamLegacy;
    {
        cudaStreamCaptureStatus st = cudaStreamCaptureStatusNone;
        cudaStreamIsCapturing(cudaStreamPerThread, &st);
        if (st == cudaStreamCaptureStatusActive) cap = cudaStreamPerThread;
    }
    cudaStream_t s1 = g_si.s1;
    cudaStream_t s2 = g_si.s2;

    // ---- fork: weight-prep on s1, vecprep on s2, x chain on cap ----
    cudaEventRecord(g_si.eF, cap);
    cudaStreamWaitEvent(s1, g_si.eF, 0);
    cudaStreamWaitEvent(s2, g_si.eF, 0);

    // s2: vecprep (independent; w0 needed by u-GEMM, ccp by reduce_ln1)
    vecprep<<<576, 256, 0, s2>>>(Wk, bq, Wo, bv, w0, ccp);
    cudaEventRecord(g_si.eV, s2);

    // s1: Mt chain first (gates u-GEMM)
    esplit<<<(HH * Dm * Dm + 255) / 256, 256, 0, s1>>>(Wq, Wqh, Wql, HH * Dm * Dm);
    esplit<<<(HH * Dm * Dm + 255) / 256, 256, 0, s1>>>(Wk, Wkh, Wkl, HH * Dm * Dm);
    gemm_mma<2, 0><<<dim3(4, 4, HH), 256, SMEM_BYTES, s1>>>(Wkh, Wkl, Wqh, Wql, nullptr,
        nullptr, Mth, Mtl, Dm, Dm, Dm, Dm, DD, DD, 0, 0L, 1, DD, 0L, 1.f, nullptr, 0L);
    cudaEventRecord(g_si.eM, s1);
    // s1: remaining weight prep
    esplit<<<(HH * Dm * Dm + 255) / 256, 256, 0, s1>>>(Wv, Wvh, Wvl, HH * Dm * Dm);
    tsplit<<<dim3(Dm / 32, (HH * Dm) / 32), 256, 0, s1>>>(Wo, WoTh, WoTl, HH * Dm, Dm);
    gemm_mma<2, 0><<<dim3(4, 4, HH), 256, SMEM_BYTES, s1>>>(WoTh, WoTl, Wvh, Wvl, nullptr,
        nullptr, Nth, Ntl, Dm, HH * Dm, Dm, Dm, (long)Dm, DD, 0, 0L, 1, DD, 0L, 1.f, nullptr, 0L);
    tsplit<<<dim3(DFFm / 32, Dm / 32), 256, 0, s1>>>(W1, W1Th, W1Tl, Dm, DFFm);
    tsplit<<<dim3(Dm / 32, DFFm / 32), 256, 0, s1>>>(W2, W2Th, W2Tl, DFFm, Dm);
    zerok<<<(HH * BB * TT + 255) / 256, 256, 0, s1>>>(rc, HH * BB * TT);
    cudaEventRecord(g_si.eB, s1);

    // cap: x chain
    esplit<<<(BT * Dm + 255) / 256, 256, 0, cap>>>(x, xh, xl, BT * Dm);
    cudaStreamWaitEvent(cap, g_si.eM, 0);
    cudaStreamWaitEvent(cap, g_si.eV, 0);

    // u = x @ M_h + w0_h
    gemm_mma<2, 0><<<dim3(4, BT / 128, HH), 256, SMEM_BYTES, cap>>>(xh, xl, Mth, Mtl, w0,
        nullptr, uh, ul, Dm, Dm, Dm, Dm, 0L, DD, 0, (long)Dm, 1, (long)BT * Dm, 0L, 1.f,
        nullptr, 0L);

    cudaStreamWaitEvent(cap, g_si.eB, 0);

    // z^T = (x @ N_h)^T -> [H,B,D,T] planes
    gemm_mma<4, 0><<<dim3(4, BT / 128, HH), 256, SMEM_BYTES, cap>>>(xh, xl, Nth, Ntl, nullptr,
        nullptr, zth, ztl, Dm, Dm, Dm, 0, 0L, DD, 0, 0L, 1, 0L, 0L, 1.f, nullptr, 0L);

    // scores = u @ x^T * 1/sqrt(D)  (2-term: x-lo dropped) + fused row-sum of exp
    gemm_mma<1, 1><<<dim3(TT / 128, TT / 128, HH * BB), 256, SMEM_BYTES, cap>>>(uh, ul, xh, xl,
        nullptr, ps, nullptr, nullptr, Dm, Dm, Dm, TT,
        (long)TT * Dm, (long)TT * Dm, BB, 0L, 1, (long)TT * TT, 0L, inv_sqrt_d,
        rc, (long)TT);

    // parts = softmax(scores) @ z  (fused exp/Z; 2-term: z-lo dropped)
    gemm_pz<<<dim3(Dm / 128, TT / 128, HH * BB), 256, PZ_SMEM, cap>>>(ps, rc, zth, parts);

    // y1 = LN(sum_h parts + cc + bo + x)
    reduce_ln1<<<BT, 256, 0, cap>>>(parts, x, ccp, bo, ln1g, ln1b, py1, y1h, y1l);

    // FFN1 -> f1 planes (full 3-term: no dilution headroom here)
    gemm_mma<2, 0><<<dim3(DFFm / 128, BT / 128, 1), 256, SMEM_BYTES, cap>>>(y1h, y1l, W1Th, W1Tl,
        b1, nullptr, f1h, f1l, Dm, Dm, Dm, DFFm, 0L, 0L, 0, 0L, 1, 0L, 0L, 1.f, nullptr, 0L);

    // FFN2 -> ff2 fp32
    gemm_mma<1, 0><<<dim3(Dm / 128, BT / 128, 1), 256, SMEM_BYTES, cap>>>(f1h, f1l, W2Th, W2Tl,
        b2, pff2, nullptr, nullptr, DFFm, DFFm, DFFm, Dm, 0L, 0L, 0, 0L, 1, 0L, 0L, 1.f,
        nullptr, 0L);

    // out = LN(relu(ff2) + y1)
    add_ln2_kernel<<<BT, 256, 0, cap>>>(pff2, py1, ln2g, ln2b, out);
}

// round 15
// speedup vs baseline: 3.4290x; 1.3276x over previous
#include <cuda_runtime.h>
#include <cuda_bf16.h>
#include <math.h>
#include <cstdint>

#define HH   8
#define Dm   512
#define DFFm 2048
#define BB   8
#define TT   1024
#define BT   (BB*TT)
#define EPSv 1e-5f

typedef __nv_bfloat16 bf16;

// ---------------- scratch (static __device__, allocation-free) ----------------
__device__ bf16 g_xh[BT*Dm], g_xl[BT*Dm];
__device__ bf16 g_Wqh[HH*Dm*Dm], g_Wql[HH*Dm*Dm];
__device__ bf16 g_Wkh[HH*Dm*Dm], g_Wkl[HH*Dm*Dm];
__device__ bf16 g_Wvh[HH*Dm*Dm], g_Wvl[HH*Dm*Dm];
__device__ bf16 g_WoTh[Dm*HH*Dm], g_WoTl[Dm*HH*Dm];
__device__ bf16 g_W1Th[DFFm*Dm], g_W1Tl[DFFm*Dm];
__device__ bf16 g_W2Th[Dm*DFFm], g_W2Tl[Dm*DFFm];
__device__ bf16 g_Mth[HH*Dm*Dm], g_Mtl[HH*Dm*Dm];
__device__ bf16 g_Nth[HH*Dm*Dm], g_Ntl[HH*Dm*Dm];
__device__ float g_w0[HH*Dm];
__device__ float g_ccp[HH*Dm];
__device__ bf16 g_uh[HH*BT*Dm];                       // u hi only (1-term scores)
__device__ bf16 g_zth[HH*BT*Dm];                      // z^T hi only [H,B,D,T]
__device__ float g_s[(size_t)HH*BB*TT*TT];            // 256 MB scores (fp32)
__device__ float g_rc[HH*BB*TT];                      // per-row Z = sum exp(s)
__device__ float g_parts[(size_t)HH*BT*Dm];
__device__ float g_y1[BT*Dm];
__device__ bf16 g_y1h[BT*Dm], g_y1l[BT*Dm];
__device__ bf16 g_f1h[BT*DFFm], g_f1l[BT*DFFm];
__device__ float g_ff2[BT*Dm];

// ---------------- helpers ----------------
__device__ __forceinline__ uint32_t smem_u32(const void* p) {
    uint32_t a;
    asm("{ .reg .u64 t; cvta.to.shared.u64 t, %1; cvt.u32.u64 %0, t; }" : "=r"(a) : "l"(p));
    return a;
}

#define CPASYNC16(sa, ga) \
    asm volatile("cp.async.ca.shared.global [%0], [%1], 16;" :: "r"(sa), "l"(ga) : "memory")
#define CP_COMMIT() asm volatile("cp.async.commit_group;" ::: "memory")
#define CP_WAIT1()  asm volatile("cp.async.wait_group 1;" ::: "memory")
#define CP_WAIT0()  asm volatile("cp.async.wait_group 0;" ::: "memory")

#define LDSM4(r, addr) \
    asm volatile("ldmatrix.sync.aligned.m8n8.x4.shared.b16 {%0,%1,%2,%3}, [%4];" \
        : "=r"((r)[0]), "=r"((r)[1]), "=r"((r)[2]), "=r"((r)[3]) : "r"(addr))

__device__ __forceinline__ void mma16816(float* c, const uint32_t* a, const uint32_t* b) {
    asm volatile("mma.sync.aligned.m16n8k16.row.col.f32.bf16.bf16.f32 "
        "{%0,%1,%2,%3}, {%4,%5,%6,%7}, {%8,%9}, {%0,%1,%2,%3};"
        : "+f"(c[0]), "+f"(c[1]), "+f"(c[2]), "+f"(c[3])
        : "r"(a[0]), "r"(a[1]), "r"(a[2]), "r"(a[3]), "r"(b[0]), "r"(b[1]));
}

#define STAGE_BYTES 24576
#define PLANE_BYTES 6144
#define ROW_BYTES   48
#define SMEM_BYTES  49152

// ============ universal bf16 split GEMM: C = alpha*(A @ B^T) + bias ============
// NT = number of MMA product terms: 3 = ah*bh+al*bh+ah*bl, 2 = ah*bh+al*bh, 1 = ah*bh.
// EPI: 1 = fp32 C (optional fused row-sum of exp via rowZ), 2 = bf16 hi/lo planes,
//      4 = transposed write [z,B,D,T].  HIONLY: skip lo-plane stores (EPI 2/4).
template<int EPI, int NT, int HIONLY>
__global__ void __launch_bounds__(256)
gemm_mma(const bf16* __restrict__ Ah, const bf16* __restrict__ Al,
         const bf16* __restrict__ Bh, const bf16* __restrict__ Bl,
         const float* __restrict__ bias,
         float* __restrict__ Cf, bf16* __restrict__ Ch, bf16* __restrict__ Cl,
         int K, int lda, int ldb, int ldc,
         long sA, long sB, int modB, long sBias,
         int innerB, long sC_outer, long sC_inner, float alpha,
         float* __restrict__ rowZ, long sZ)
{
    extern __shared__ char smem[];
    const uint32_t sb = smem_u32(smem);

    const int tid = threadIdx.x, lane = tid & 31, wid = tid >> 5;
    const int wm = wid >> 2, wn = wid & 3;
    const int z = blockIdx.z;

    const bf16* Abh = Ah + (long)z * sA;
    const bf16* Abl = Al + (long)z * sA;
    const long bOff = (modB > 0 ? (long)(z % modB) : (long)z) * sB;
    const bf16* Bbh = Bh + bOff;
    const bf16* Bbl = Bl + bOff;
    const float* biasb = bias ? (bias + (long)z * sBias) : nullptr;
    long coff = (innerB > 1) ? (long)(z / innerB) * sC_outer + (long)(z % innerB) * sC_inner
                             : (long)z * sC_outer;

    const int mBase = blockIdx.y * 128;
    const int nBase = blockIdx.x * 128;

    const int lrow = tid >> 1;
    const int lco  = (tid & 1) * 8;
    const uint32_t ssub = (uint32_t)lrow * ROW_BYTES + (tid & 1) * 16;
    const long gA = (long)(mBase + lrow) * lda + lco;
    const long gB = (long)(nBase + lrow) * ldb + lco;

    float acc[4][4][4];
    #pragma unroll
    for (int i = 0; i < 4; i++)
        #pragma unroll
        for (int j = 0; j < 4; j++)
            #pragma unroll
            for (int r = 0; r < 4; r++) acc[i][j][r] = 0.f;

    const int nStages = K >> 4;

    {
        uint32_t base = sb;
        CPASYNC16(base + ssub,                   (const char*)(Abh + gA));
        if (NT >= 2) CPASYNC16(base + PLANE_BYTES + ssub, (const char*)(Abl + gA));
        CPASYNC16(base + 2*PLANE_BYTES + ssub,   (const char*)(Bbh + gB));
        if (NT >= 3) CPASYNC16(base + 3*PLANE_BYTES + ssub, (const char*)(Bbl + gB));
        CP_COMMIT();
    }

    const uint32_t aoff = (uint32_t)(lane & 15) * ROW_BYTES + (lane >> 4) * 16;
    const int nrow  = (lane & 7) + ((lane >> 4) << 3);
    const int khalf = (lane >> 3) & 1;
    const uint32_t boff = (uint32_t)nrow * ROW_BYTES + khalf * 16;

    for (int s = 0; s < nStages; s++) {
        if (s + 1 < nStages) {
            uint32_t base = sb + ((s + 1) & 1) * STAGE_BYTES;
            long k0 = (long)(s + 1) << 4;
            CPASYNC16(base + ssub,                 (const char*)(Abh + gA + k0));
            if (NT >= 2) CPASYNC16(base + PLANE_BYTES + ssub, (const char*)(Abl + gA + k0));
            CPASYNC16(base + 2*PLANE_BYTES + ssub, (const char*)(Bbh + gB + k0));
            if (NT >= 3) CPASYNC16(base + 3*PLANE_BYTES + ssub, (const char*)(Bbl + gB + k0));
            CP_COMMIT();
            CP_WAIT1();
        } else {
            CP_WAIT0();
        }
        __syncthreads();

        const uint32_t base = sb + (s & 1) * STAGE_BYTES;
        uint32_t ah[4][4], al[4][4];
        #pragma unroll
        for (int mi = 0; mi < 4; mi++) {
            uint32_t o = base + (uint32_t)(wm * 64 + mi * 16) * ROW_BYTES + aoff;
            LDSM4(ah[mi], o);
            if (NT >= 2) LDSM4(al[mi], o + PLANE_BYTES);
        }
        uint32_t bh[2][4], bl[2][4];
        #pragma unroll
        for (int p = 0; p < 2; p++) {
            uint32_t o = base + 2*PLANE_BYTES + (uint32_t)(wn * 32 + p * 16) * ROW_BYTES + boff;
            LDSM4(bh[p], o);
            if (NT >= 3) LDSM4(bl[p], o + PLANE_BYTES);
        }
        #pragma unroll
        for (int mi = 0; mi < 4; mi++)
            #pragma unroll
            for (int p = 0; p < 2; p++)
                #pragma unroll
                for (int s2 = 0; s2 < 2; s2++) {
                    const int ni = p * 2 + s2;
                    mma16816(acc[mi][ni], ah[mi], &bh[p][s2 * 2]);
                    if (NT >= 2) mma16816(acc[mi][ni], al[mi], &bh[p][s2 * 2]);
                    if (NT >= 3) mma16816(acc[mi][ni], ah[mi], &bl[p][s2 * 2]);
                }
        __syncthreads();
    }

    const int er = mBase + wm * 64 + (lane >> 2);
    const int ec = nBase + wn * 32 + (lane & 3) * 2;

    float zac[4][2];
    if (EPI == 1 && rowZ) {
        #pragma unroll
        for (int mi = 0; mi < 4; mi++) { zac[mi][0] = 0.f; zac[mi][1] = 0.f; }
    }

    #pragma unroll
    for (int mi = 0; mi < 4; mi++) {
        #pragma unroll
        for (int ni = 0; ni < 4; ni++) {
            const int gc = ec + ni * 8;
            float b0 = 0.f, b1 = 0.f;
            if (biasb) { b0 = __ldg(&biasb[gc]); b1 = __ldg(&biasb[gc + 1]); }
            #pragma unroll
            for (int half = 0; half < 2; half++) {
                const int gr = er + mi * 16 + half * 8;
                float v0 = acc[mi][ni][half * 2 + 0] * alpha + b0;
                float v1 = acc[mi][ni][half * 2 + 1] * alpha + b1;
                if (EPI == 4) {
                    const long zb = (long)z * ((long)BB * Dm * TT)
                                  + (long)(gr >> 10) * ((long)Dm * TT);
                    const long t = gr & 1023;
                    long a0 = zb + (long)gc * TT + t;
                    long a1 = zb + (long)(gc + 1) * TT + t;
                    bf16 h0 = __float2bfloat16_rn(v0);
                    bf16 h1 = __float2bfloat16_rn(v1);
                    Ch[a0] = h0;
                    Ch[a1] = h1;
                    if (!HIONLY) {
                        Cl[a0] = __float2bfloat16_rn(v0 - __bfloat162float(h0));
                        Cl[a1] = __float2bfloat16_rn(v1 - __bfloat162float(h1));
                    }
                } else {
                    const long baseo = coff + (long)gr * ldc + gc;
                    if (EPI & 1) {
                        float2 f; f.x = v0; f.y = v1;
                        *(float2*)(Cf + baseo) = f;
                        if (rowZ) zac[mi][half] += __expf(v0) + __expf(v1);
                    }
                    if (EPI & 2) {
                        bf16 h0 = __float2bfloat16_rn(v0);
                        bf16 h1 = __float2bfloat16_rn(v1);
                        uint16_t a16 = *(uint16_t*)&h0, b16v = *(uint16_t*)&h1;
                        *(uint32_t*)(Ch + baseo) = (uint32_t)a16 | ((uint32_t)b16v << 16);
                        if (!HIONLY) {
                            bf16 l0 = __float2bfloat16_rn(v0 - __bfloat162float(h0));
                            bf16 l1 = __float2bfloat16_rn(v1 - __bfloat162float(h1));
                            uint16_t c16 = *(uint16_t*)&l0, d16 = *(uint16_t*)&l1;
                            *(uint32_t*)(Cl + baseo) = (uint32_t)c16 | ((uint32_t)d16 << 16);
                        }
                    }
                }
            }
        }
    }

    if (EPI == 1 && rowZ) {
        #pragma unroll
        for (int mi = 0; mi < 4; mi++)
            #pragma unroll
            for (int half = 0; half < 2; half++) {
                float ssum = zac[mi][half];
                ssum += __shfl_xor_sync(0xffffffffu, ssum, 1);
                ssum += __shfl_xor_sync(0xffffffffu, ssum, 2);
                if ((lane & 3) == 0)
                    atomicAdd(&rowZ[(long)z * sZ + er + mi * 16 + half * 8], ssum);
            }
    }
}

// ============ fused softmax + P@z GEMM, 1-term: ph*zh ============
#define PZ_AF(s)   ((uint32_t)((s) * 8192))
#define PZ_AH(s)   ((uint32_t)(16384 + (s) * PLANE_BYTES))
#define PZ_BH(s)   ((uint32_t)(28672 + (s) * PLANE_BYTES))
#define PZ_SMEM    40960

__global__ void __launch_bounds__(256)
gemm_pz(const float* __restrict__ S, const float* __restrict__ rc,
        const bf16* __restrict__ Bh,
        float* __restrict__ Cf)
{
    extern __shared__ char smem[];
    const uint32_t sb = smem_u32(smem);
    const int tid = threadIdx.x, lane = tid & 31, wid = tid >> 5;
    const int wm = wid >> 2, wn = wid & 3;
    const int z = blockIdx.z;

    const float* Ab = S + (long)z * TT * TT;
    const bf16* Bbh = Bh + (long)z * Dm * TT;
    const long coff = (long)z * TT * Dm;
    const int mBase = blockIdx.y * 128;
    const int nBase = blockIdx.x * 128;

    const int lrow = tid >> 1;
    const uint32_t ssubB = (uint32_t)lrow * ROW_BYTES + (tid & 1) * 16;
    const long gB = (long)(nBase + lrow) * TT + (tid & 1) * 8;
    const int ar0 = tid >> 2, ac0 = (tid & 3) * 4;
    const int ar1 = (tid + 256) >> 2, ac1 = ((tid + 256) & 3) * 4;
    const long gA0 = (long)(mBase + ar0) * TT + ac0;
    const long gA1 = (long)(mBase + ar1) * TT + ac1;
    const uint32_t sA0 = (uint32_t)ar0 * 64 + (tid & 3) * 16;
    const uint32_t sA1 = (uint32_t)ar1 * 64 + ((tid + 256) & 3) * 16;

    const int crow = tid >> 1, ck = (tid & 1) * 8;
    const float cinv = 1.f / __ldg(&rc[(long)z * TT + mBase + crow]);

    float acc[4][4][4];
    #pragma unroll
    for (int i = 0; i < 4; i++)
        #pragma unroll
        for (int j = 0; j < 4; j++)
            #pragma unroll
            for (int r = 0; r < 4; r++) acc[i][j][r] = 0.f;

    const int nStages = TT >> 4;

    auto issue_cp = [&](int s) {
        const uint32_t bsel = (uint32_t)(s & 1);
        const long k0 = (long)s << 4;
        CPASYNC16(sb + PZ_AF(bsel) + sA0, (const char*)(Ab + gA0 + k0));
        CPASYNC16(sb + PZ_AF(bsel) + sA1, (const char*)(Ab + gA1 + k0));
        CPASYNC16(sb + PZ_BH(bsel) + ssubB, (const char*)(Bbh + gB + k0));
        CP_COMMIT();
    };
    auto convert = [&](int s) {
        const uint32_t bsel = (uint32_t)(s & 1);
        const float* af = (const float*)(smem + PZ_AF(bsel) + (uint32_t)crow * 64);
        bf16* ahp = (bf16*)(smem + PZ_AH(bsel) + (uint32_t)crow * ROW_BYTES);
        #pragma unroll
        for (int j = 0; j < 8; j += 2) {
            float e0 = __expf(af[ck + j])     * cinv;
            float e1 = __expf(af[ck + j + 1]) * cinv;
            bf16 h0 = __float2bfloat16_rn(e0);
            bf16 h1 = __float2bfloat16_rn(e1);
            uint16_t u0 = *(uint16_t*)&h0, u1 = *(uint16_t*)&h1;
            *(uint32_t*)(ahp + ck + j) = (uint32_t)u0 | ((uint32_t)u1 << 16);
        }
    };

    const uint32_t aoff = (uint32_t)(lane & 15) * ROW_BYTES + (lane >> 4) * 16;
    const int nrow  = (lane & 7) + ((lane >> 4) << 3);
    const int khalf = (lane >> 3) & 1;
    const uint32_t boff = (uint32_t)nrow * ROW_BYTES + khalf * 16;

    issue_cp(0);
    issue_cp(1);
    CP_WAIT1();
    __syncthreads();
    convert(0);
    __syncthreads();

    for (int s = 0; s < nStages; s++) {
        const uint32_t base = (uint32_t)(s & 1);
        uint32_t ah[4][4];
        #pragma unroll
        for (int mi = 0; mi < 4; mi++) {
            uint32_t o = sb + PZ_AH(base) + (uint32_t)(wm * 64 + mi * 16) * ROW_BYTES + aoff;
            LDSM4(ah[mi], o);
        }
        uint32_t bh[2][4];
        #pragma unroll
        for (int p = 0; p < 2; p++) {
            uint32_t o = sb + PZ_BH(base) + (uint32_t)(wn * 32 + p * 16) * ROW_BYTES + boff;
            LDSM4(bh[p], o);
        }
        #pragma unroll
        for (int mi = 0; mi < 4; mi++)
            #pragma unroll
            for (int p = 0; p < 2; p++)
                #pragma unroll
                for (int s2 = 0; s2 < 2; s2++) {
                    const int ni = p * 2 + s2;
                    mma16816(acc[mi][ni], ah[mi], &bh[p][s2 * 2]);
                }
        if (s + 2 < nStages) issue_cp(s + 2);
        if (s + 1 < nStages) {
            if (s + 2 < nStages) { CP_WAIT1(); } else { CP_WAIT0(); }
            __syncthreads();
            convert(s + 1);
            __syncthreads();
        }
    }

    const int er = mBase + wm * 64 + (lane >> 2);
    const int ec = nBase + wn * 32 + (lane & 3) * 2;
    #pragma unroll
    for (int mi = 0; mi < 4; mi++)
        #pragma unroll
        for (int ni = 0; ni < 4; ni++)
            #pragma unroll
            for (int half = 0; half < 2; half++) {
                const int gr = er + mi * 16 + half * 8;
                const int gc = ec + ni * 8;
                float2 f;
                f.x = acc[mi][ni][half * 2 + 0];
                f.y = acc[mi][ni][half * 2 + 1];
                *(float2*)(Cf + coff + (long)gr * Dm + gc) = f;
            }
}

// ---------------- transpose + split ----------------
__global__ void __launch_bounds__(256)
tsplit(const float* __restrict__ in, bf16* __restrict__ oh, bf16* __restrict__ ol,
       int R, int C)
{
    __shared__ float t[32][33];
    const int cb = blockIdx.x * 32, rb = blockIdx.y * 32;
    const int x = threadIdx.x & 31, y = threadIdx.x >> 5;
    #pragma unroll
    for (int i = 0; i < 32; i += 8)
        t[y + i][x] = in[(long)(rb + y + i) * C + cb + x];
    __syncthreads();
    #pragma unroll
    for (int i = 0; i < 32; i += 8) {
        float v = t[x][y + i];
        bf16 h = __float2bfloat16_rn(v);
        long o = (long)(cb + y + i) * R + rb + x;
        oh[o] = h;
        ol[o] = __float2bfloat16_rn(v - __bfloat162float(h));
    }
}

// ---------------- elementwise split ----------------
__global__ void __launch_bounds__(256)
esplit(const float* __restrict__ in, bf16* __restrict__ oh, bf16* __restrict__ ol, int n)
{
    int i = blockIdx.x * 256 + threadIdx.x;
    if (i < n) {
        float v = in[i];
        bf16 h = __float2bfloat16_rn(v);
        oh[i] = h;
        ol[i] = __float2bfloat16_rn(v - __bfloat162float(h));
    }
}

// ---------------- zero kernel ----------------
__global__ void __launch_bounds__(256)
zerok(float* __restrict__ p, int n)
{
    int i = blockIdx.x * 256 + threadIdx.x;
    if (i < n) p[i] = 0.f;
}

// ---------------- vecprep ----------------
__global__ void __launch_bounds__(256)
vecprep(const float* __restrict__ Wk, const float* __restrict__ bq,
        const float* __restrict__ Wo, const float* __restrict__ bv,
        float* __restrict__ w0, float* __restrict__ ccp)
{
    const int bb = blockIdx.x;
    if (bb < 512) {
        const int wid = threadIdx.x >> 5, lane = threadIdx.x & 31;
        const int idx = bb * 8 + wid;
        const int h = idx >> 9, d = idx & 511;
        const float* wr = Wk + (long)h * Dm * Dm + (long)d * Dm;
        const float* bqr = bq + h * Dm;
        float s = 0.f;
        #pragma unroll
        for (int e = lane; e < Dm; e += 32) s += wr[e] * bqr[e];
        #pragma unroll
        for (int o = 16; o; o >>= 1) s += __shfl_xor_sync(0xffffffffu, s, o);
        if (lane == 0) w0[idx] = s;
    } else {
        __shared__ float part[4][64];
        const int ib = bb - 512;
        const int h = ib >> 3, chunk = ib & 7;
        const int e = chunk * 64 + (threadIdx.x & 63);
        const int ms = threadIdx.x >> 6;
        const float* Woh = Wo + (long)h * Dm * Dm;
        const float* bvh = bv + h * Dm;
        float s = 0.f;
        for (int m = ms * 128; m < ms * 128 + 128; m++)
            s += bvh[m] * Woh[(long)m * Dm + e];
        part[ms][threadIdx.x & 63] = s;
        __syncthreads();
        if (threadIdx.x < 64)
            ccp[h * Dm + chunk * 64 + threadIdx.x] =
                part[0][threadIdx.x] + part[1][threadIdx.x] +
                part[2][threadIdx.x] + part[3][threadIdx.x];
    }
}

// ---------------- block reductions ----------------
__device__ __forceinline__ float block_sum(float v, float* sm) {
    #pragma unroll
    for (int o = 16; o; o >>= 1) v += __shfl_xor_sync(0xffffffffu, v, o);
    if ((threadIdx.x & 31) == 0) sm[threadIdx.x >> 5] = v;
    __syncthreads();
    if (threadIdx.x < 8) {
        float s = sm[threadIdx.x];
        #pragma unroll
        for (int o = 4; o; o >>= 1) s += __shfl_xor_sync(0xffu, s, o);
        if (threadIdx.x == 0) sm[0] = s;
    }
    __syncthreads();
    float r = sm[0];
    __syncthreads();
    return r;
}

// ---------------- reduce heads + cc + residual + LN1 -> y1 (fp32 + planes) ----------------
__global__ void __launch_bounds__(256)
reduce_ln1(const float* __restrict__ parts, const float* __restrict__ x,
           const float* __restrict__ ccp, const float* __restrict__ bo,
           const float* __restrict__ g, const float* __restrict__ be,
           float* __restrict__ out, bf16* __restrict__ oh, bf16* __restrict__ ol)
{
    __shared__ float sm[8];
    const long row = blockIdx.x;
    const long b = row >> 10, t0 = row & 1023;
    const int t = threadIdx.x;
    float v0, v1;
    {
        float c0 = bo[t], c1 = bo[t + 256];
        #pragma unroll
        for (int h = 0; h < HH; h++) {
            c0 += ccp[h * Dm + t];
            c1 += ccp[h * Dm + t + 256];
        }
        v0 = x[row * Dm + t] + c0;
        v1 = x[row * Dm + t + 256] + c1;
        #pragma unroll
        for (int h = 0; h < HH; h++) {
            const long pr = (((long)h * BB + b) * TT + t0) * Dm;
            v0 += parts[pr + t];
            v1 += parts[pr + t + 256];
        }
    }
    float mean = block_sum(v0 + v1, sm) * (1.f / Dm);
    float d0 = v0 - mean, d1 = v1 - mean;
    float var = block_sum(d0 * d0 + d1 * d1, sm) * (1.f / Dm);
    float inv = rsqrtf(var + EPSv);
    float o0 = d0 * inv * g[t] + be[t];
    float o1 = d1 * inv * g[t + 256] + be[t + 256];
    out[row * Dm + t] = o0;
    out[row * Dm + t + 256] = o1;
    bf16 h0 = __float2bfloat16_rn(o0), h1 = __float2bfloat16_rn(o1);
    oh[row * Dm + t] = h0;
    oh[row * Dm + t + 256] = h1;
    ol[row * Dm + t] = __float2bfloat16_rn(o0 - __bfloat162float(h0));
    ol[row * Dm + t + 256] = __float2bfloat16_rn(o1 - __bfloat162float(h1));
}

// ---------------- relu + residual + LN2 ----------------
__global__ void __launch_bounds__(256)
add_ln2_kernel(const float* __restrict__ a, const float* __restrict__ res,
               const float* __restrict__ g, const float* __restrict__ be,
               float* __restrict__ out)
{
    __shared__ float sm[8];
    long row = blockIdx.x;
    const float* ap = a + row * Dm;
    const float* rp = res + row * Dm;
    int t = threadIdx.x;
    float v0 = fmaxf(ap[t], 0.f) + rp[t];
    float v1 = fmaxf(ap[t + 256], 0.f) + rp[t + 256];
    float mean = block_sum(v0 + v1, sm) * (1.f / Dm);
    float d0 = v0 - mean, d1 = v1 - mean;
    float var = block_sum(d0 * d0 + d1 * d1, sm) * (1.f / Dm);
    float inv = rsqrtf(var + EPSv);
    out[row * Dm + t]       = d0 * inv * g[t]       + be[t];
    out[row * Dm + t + 256] = d1 * inv * g[t + 256] + be[t + 256];
}

// ---------------- stream / event resources (created at load, before checkpoints) ----------------
struct StreamInit {
    cudaStream_t s1, s2;
    cudaEvent_t eF, eM, eB, eV;
    StreamInit() {
        cudaStreamCreateWithFlags(&s1, cudaStreamNonBlocking);
        cudaStreamCreateWithFlags(&s2, cudaStreamNonBlocking);
        cudaEventCreateWithFlags(&eF, cudaEventDisableTiming);
        cudaEventCreateWithFlags(&eM, cudaEventDisableTiming);
        cudaEventCreateWithFlags(&eB, cudaEventDisableTiming);
        cudaEventCreateWithFlags(&eV, cudaEventDisableTiming);
    }
};
static StreamInit g_si;

// ---------------- launch ----------------
extern "C" void kernel_launch(void* const* d_in, const int* in_sizes, int n_in,
                              void* d_out, int out_size)
{
    const float* x    = (const float*)d_in[0];
    const float* Wq   = (const float*)d_in[1];
    const float* bq   = (const float*)d_in[2];
    const float* Wk   = (const float*)d_in[3];
    const float* Wv   = (const float*)d_in[5];
    const float* bv   = (const float*)d_in[6];
    const float* Wo   = (const float*)d_in[7];
    const float* bo   = (const float*)d_in[8];
    const float* ln1g = (const float*)d_in[9];
    const float* ln1b = (const float*)d_in[10];
    const float* W1   = (const float*)d_in[11];
    const float* b1   = (const float*)d_in[12];
    const float* W2   = (const float*)d_in[13];
    const float* b2   = (const float*)d_in[14];
    const float* ln2g = (const float*)d_in[15];
    const float* ln2b = (const float*)d_in[16];
    float* out = (float*)d_out;

    bf16 *xh, *xl, *Wqh, *Wql, *Wkh, *Wkl, *Wvh, *Wvl, *WoTh, *WoTl;
    bf16 *W1Th, *W1Tl, *W2Th, *W2Tl, *Mth, *Mtl, *Nth, *Ntl;
    bf16 *uh, *zth, *y1h, *y1l, *f1h, *f1l;
    float *w0, *ccp, *ps, *rc, *parts, *py1, *pff2;
    cudaGetSymbolAddress((void**)&xh, g_xh);     cudaGetSymbolAddress((void**)&xl, g_xl);
    cudaGetSymbolAddress((void**)&Wqh, g_Wqh);   cudaGetSymbolAddress((void**)&Wql, g_Wql);
    cudaGetSymbolAddress((void**)&Wkh, g_Wkh);   cudaGetSymbolAddress((void**)&Wkl, g_Wkl);
    cudaGetSymbolAddress((void**)&Wvh, g_Wvh);   cudaGetSymbolAddress((void**)&Wvl, g_Wvl);
    cudaGetSymbolAddress((void**)&WoTh, g_WoTh); cudaGetSymbolAddress((void**)&WoTl, g_WoTl);
    cudaGetSymbolAddress((void**)&W1Th, g_W1Th); cudaGetSymbolAddress((void**)&W1Tl, g_W1Tl);
    cudaGetSymbolAddress((void**)&W2Th, g_W2Th); cudaGetSymbolAddress((void**)&W2Tl, g_W2Tl);
    cudaGetSymbolAddress((void**)&Mth, g_Mth);   cudaGetSymbolAddress((void**)&Mtl, g_Mtl);
    cudaGetSymbolAddress((void**)&Nth, g_Nth);   cudaGetSymbolAddress((void**)&Ntl, g_Ntl);
    cudaGetSymbolAddress((void**)&w0, g_w0);     cudaGetSymbolAddress((void**)&ccp, g_ccp);
    cudaGetSymbolAddress((void**)&uh, g_uh);
    cudaGetSymbolAddress((void**)&zth, g_zth);
    cudaGetSymbolAddress((void**)&ps, g_s);      cudaGetSymbolAddress((void**)&rc, g_rc);
    cudaGetSymbolAddress((void**)&parts, g_parts);
    cudaGetSymbolAddress((void**)&py1, g_y1);
    cudaGetSymbolAddress((void**)&y1h, g_y1h);   cudaGetSymbolAddress((void**)&y1l, g_y1l);
    cudaGetSymbolAddress((void**)&f1h, g_f1h);   cudaGetSymbolAddress((void**)&f1l, g_f1l);
    cudaGetSymbolAddress((void**)&pff2, g_ff2);

    cudaFuncSetAttribute(gemm_pz, cudaFuncAttributeMaxDynamicSharedMemorySize, PZ_SMEM);

    const float inv_sqrt_d = 0.044194173824159216f;
    const long DD = (long)Dm * Dm;

    // detect the capturing (or main) stream
    cudaStream_t cap = cudaStreamLegacy;
    {
        cudaStreamCaptureStatus st = cudaStreamCaptureStatusNone;
        cudaStreamIsCapturing(cudaStreamPerThread, &st);
        if (st == cudaStreamCaptureStatusActive) cap = cudaStreamPerThread;
    }
    cudaStream_t s1 = g_si.s1;
    cudaStream_t s2 = g_si.s2;

    // ---- fork: weight-prep on s1, vecprep on s2, x chain on cap ----
    cudaEventRecord(g_si.eF, cap);
    cudaStreamWaitEvent(s1, g_si.eF, 0);
    cudaStreamWaitEvent(s2, g_si.eF, 0);

    // s2: vecprep
    vecprep<<<576, 256, 0, s2>>>(Wk, bq, Wo, bv, w0, ccp);
    cudaEventRecord(g_si.eV, s2);

    // s1: Mt chain first (gates u-GEMM)
    esplit<<<(HH * Dm * Dm + 255) / 256, 256, 0, s1>>>(Wq, Wqh, Wql, HH * Dm * Dm);
    esplit<<<(HH * Dm * Dm + 255) / 256, 256, 0, s1>>>(Wk, Wkh, Wkl, HH * Dm * Dm);
    gemm_mma<2, 3, 0><<<dim3(4, 4, HH), 256, SMEM_BYTES, s1>>>(Wkh, Wkl, Wqh, Wql, nullptr,
        nullptr, Mth, Mtl, Dm, Dm, Dm, Dm, DD, DD, 0, 0L, 1, DD, 0L, 1.f, nullptr, 0L);
    cudaEventRecord(g_si.eM, s1);
    // s1: remaining weight prep
    esplit<<<(HH * Dm * Dm + 255) / 256, 256, 0, s1>>>(Wv, Wvh, Wvl, HH * Dm * Dm);
    tsplit<<<dim3(Dm / 32, (HH * Dm) / 32), 256, 0, s1>>>(Wo, WoTh, WoTl, HH * Dm, Dm);
    gemm_mma<2, 3, 0><<<dim3(4, 4, HH), 256, SMEM_BYTES, s1>>>(WoTh, WoTl, Wvh, Wvl, nullptr,
        nullptr, Nth, Ntl, Dm, HH * Dm, Dm, Dm, (long)Dm, DD, 0, 0L, 1, DD, 0L, 1.f, nullptr, 0L);
    tsplit<<<dim3(DFFm / 32, Dm / 32), 256, 0, s1>>>(W1, W1Th, W1Tl, Dm, DFFm);
    tsplit<<<dim3(Dm / 32, DFFm / 32), 256, 0, s1>>>(W2, W2Th, W2Tl, DFFm, Dm);
    zerok<<<(HH * BB * TT + 255) / 256, 256, 0, s1>>>(rc, HH * BB * TT);
    cudaEventRecord(g_si.eB, s1);

    // cap: x chain
    esplit<<<(BT * Dm + 255) / 256, 256, 0, cap>>>(x, xh, xl, BT * Dm);
    cudaStreamWaitEvent(cap, g_si.eM, 0);
    cudaStreamWaitEvent(cap, g_si.eV, 0);

    // u = x @ M_h + w0_h  (2-term: Mt-lo dropped; hi-only output)
    gemm_mma<2, 2, 1><<<dim3(4, BT / 128, HH), 256, SMEM_BYTES, cap>>>(xh, xl, Mth, Mtl, w0,
        nullptr, uh, nullptr, Dm, Dm, Dm, Dm, 0L, DD, 0, (long)Dm, 1, (long)BT * Dm, 0L, 1.f,
        nullptr, 0L);

    cudaStreamWaitEvent(cap, g_si.eB, 0);

    // z^T = (x @ N_h)^T -> [H,B,D,T]  (2-term: Nt-lo dropped; hi-only output)
    gemm_mma<4, 2, 1><<<dim3(4, BT / 128, HH), 256, SMEM_BYTES, cap>>>(xh, xl, Nth, Ntl, nullptr,
        nullptr, zth, nullptr, Dm, Dm, Dm, 0, 0L, DD, 0, 0L, 1, 0L, 0L, 1.f, nullptr, 0L);

    // scores = u @ x^T * 1/sqrt(D)  (1-term: uh*xh) + fused row-sum of exp
    gemm_mma<1, 1, 0><<<dim3(TT / 128, TT / 128, HH * BB), 256, SMEM_BYTES, cap>>>(uh, nullptr,
        xh, nullptr, nullptr, ps, nullptr, nullptr, Dm, Dm, Dm, TT,
        (long)TT * Dm, (long)TT * Dm, BB, 0L, 1, (long)TT * TT, 0L, inv_sqrt_d,
        rc, (long)TT);

    // parts = softmax(scores) @ z  (fused exp/Z; 1-term ph*zh)
    gemm_pz<<<dim3(Dm / 128, TT / 128, HH * BB), 256, PZ_SMEM, cap>>>(ps, rc, zth, parts);

    // y1 = LN(sum_h parts + cc + bo + x)
    reduce_ln1<<<BT, 256, 0, cap>>>(parts, x, ccp, bo, ln1g, ln1b, py1, y1h, y1l);

    // FFN1 -> f1 planes (full 3-term)
    gemm_mma<2, 3, 0><<<dim3(DFFm / 128, BT / 128, 1), 256, SMEM_BYTES, cap>>>(y1h, y1l, W1Th, W1Tl,
        b1, nullptr, f1h, f1l, Dm, Dm, Dm, DFFm, 0L, 0L, 0, 0L, 1, 0L, 0L, 1.f, nullptr, 0L);

    // FFN2 -> ff2 fp32 (full 3-term)
    gemm_mma<1, 3, 0><<<dim3(Dm / 128, BT / 128, 1), 256, SMEM_BYTES, cap>>>(f1h, f1l, W2Th, W2Tl,
        b2, pff2, nullptr, nullptr, DFFm, DFFm, DFFm, Dm, 0L, 0L, 0, 0L, 1, 0L, 0L, 1.f,
        nullptr, 0L);

    // out = LN(relu(ff2) + y1)
    add_ln2_kernel<<<BT, 256, 0, cap>>>(pff2, py1, ln2g, ln2b, out);
}

// round 17
// speedup vs baseline: 3.8306x; 1.1171x over previous
#include <cuda_runtime.h>
#include <cuda_bf16.h>
#include <math.h>
#include <cstdint>

#define HH   8
#define Dm   512
#define DFFm 2048
#define BB   8
#define TT   1024
#define BT   (BB*TT)
#define EPSv 1e-5f

typedef __nv_bfloat16 bf16;

// ---------------- scratch (static __device__, allocation-free) ----------------
__device__ bf16 g_xh[BT*Dm];
__device__ bf16 g_Wqh[HH*Dm*Dm], g_Wql[HH*Dm*Dm];
__device__ bf16 g_Wkh[HH*Dm*Dm], g_Wkl[HH*Dm*Dm];
__device__ bf16 g_Wvh[HH*Dm*Dm], g_Wvl[HH*Dm*Dm];
__device__ bf16 g_WoTh[Dm*HH*Dm], g_WoTl[Dm*HH*Dm];
__device__ bf16 g_W1Th[DFFm*Dm], g_W1Tl[DFFm*Dm];
__device__ bf16 g_W2Th[Dm*DFFm], g_W2Tl[Dm*DFFm];
__device__ bf16 g_Mth[HH*Dm*Dm];                      // hi only (1-term u)
__device__ bf16 g_Nth[HH*Dm*Dm];                      // hi only (1-term z)
__device__ float g_w0[HH*Dm];
__device__ float g_ccp[HH*Dm];
__device__ bf16 g_uh[HH*BT*Dm];                       // u hi only
__device__ bf16 g_zth[HH*BT*Dm];                      // z^T hi only [H,B,D,T]
__device__ float g_s[(size_t)HH*BB*TT*TT];            // 256 MB scores (fp32)
__device__ float g_rc[HH*BB*TT];                      // per-row Z = sum exp(s)
__device__ float g_parts[(size_t)HH*BT*Dm];
__device__ float g_y1[BT*Dm];
__device__ bf16 g_y1h[BT*Dm], g_y1l[BT*Dm];
__device__ bf16 g_f1h[BT*DFFm], g_f1l[BT*DFFm];
__device__ float g_ff2[BT*Dm];

// ---------------- helpers ----------------
__device__ __forceinline__ uint32_t smem_u32(const void* p) {
    uint32_t a;
    asm("{ .reg .u64 t; cvta.to.shared.u64 t, %1; cvt.u32.u64 %0, t; }" : "=r"(a) : "l"(p));
    return a;
}

#define CPASYNC16(sa, ga) \
    asm volatile("cp.async.ca.shared.global [%0], [%1], 16;" :: "r"(sa), "l"(ga) : "memory")
#define CP_COMMIT() asm volatile("cp.async.commit_group;" ::: "memory")
#define CP_WAIT1()  asm volatile("cp.async.wait_group 1;" ::: "memory")
#define CP_WAIT0()  asm volatile("cp.async.wait_group 0;" ::: "memory")

#define LDSM4(r, addr) \
    asm volatile("ldmatrix.sync.aligned.m8n8.x4.shared.b16 {%0,%1,%2,%3}, [%4];" \
        : "=r"((r)[0]), "=r"((r)[1]), "=r"((r)[2]), "=r"((r)[3]) : "r"(addr))

__device__ __forceinline__ void mma16816(float* c, const uint32_t* a, const uint32_t* b) {
    asm volatile("mma.sync.aligned.m16n8k16.row.col.f32.bf16.bf16.f32 "
        "{%0,%1,%2,%3}, {%4,%5,%6,%7}, {%8,%9}, {%0,%1,%2,%3};"
        : "+f"(c[0]), "+f"(c[1]), "+f"(c[2]), "+f"(c[3])
        : "r"(a[0]), "r"(a[1]), "r"(a[2]), "r"(a[3]), "r"(b[0]), "r"(b[1]));
}

#define STAGE_BYTES 24576
#define PLANE_BYTES 6144
#define ROW_BYTES   48
#define SMEM_BYTES  49152

// ============ universal bf16 split GEMM: C = alpha*(A @ B^T) + bias ============
// NT terms: 3 = ah*bh+al*bh+ah*bl, 2 = ah*bh+al*bh, 1 = ah*bh.
// EPI: 1 = fp32 C (optional fused row-sum of exp via rowZ), 2 = bf16 hi/lo planes,
//      4 = transposed write [z,B,D,T].  HIONLY: skip lo-plane stores (EPI 2/4).
template<int EPI, int NT, int HIONLY>
__global__ void __launch_bounds__(256)
gemm_mma(const bf16* __restrict__ Ah, const bf16* __restrict__ Al,
         const bf16* __restrict__ Bh, const bf16* __restrict__ Bl,
         const float* __restrict__ bias,
         float* __restrict__ Cf, bf16* __restrict__ Ch, bf16* __restrict__ Cl,
         int K, int lda, int ldb, int ldc,
         long sA, long sB, int modB, long sBias,
         int innerB, long sC_outer, long sC_inner, float alpha,
         float* __restrict__ rowZ, long sZ)
{
    extern __shared__ char smem[];
    const uint32_t sb = smem_u32(smem);

    const int tid = threadIdx.x, lane = tid & 31, wid = tid >> 5;
    const int wm = wid >> 2, wn = wid & 3;
    const int z = blockIdx.z;

    const bf16* Abh = Ah + (long)z * sA;
    const bf16* Abl = Al + (long)z * sA;
    const long bOff = (modB > 0 ? (long)(z % modB) : (long)z) * sB;
    const bf16* Bbh = Bh + bOff;
    const bf16* Bbl = Bl + bOff;
    const float* biasb = bias ? (bias + (long)z * sBias) : nullptr;
    long coff = (innerB > 1) ? (long)(z / innerB) * sC_outer + (long)(z % innerB) * sC_inner
                             : (long)z * sC_outer;

    const int mBase = blockIdx.y * 128;
    const int nBase = blockIdx.x * 128;

    const int lrow = tid >> 1;
    const int lco  = (tid & 1) * 8;
    const uint32_t ssub = (uint32_t)lrow * ROW_BYTES + (tid & 1) * 16;
    const long gA = (long)(mBase + lrow) * lda + lco;
    const long gB = (long)(nBase + lrow) * ldb + lco;

    float acc[4][4][4];
    #pragma unroll
    for (int i = 0; i < 4; i++)
        #pragma unroll
        for (int j = 0; j < 4; j++)
            #pragma unroll
            for (int r = 0; r < 4; r++) acc[i][j][r] = 0.f;

    const int nStages = K >> 4;

    {
        uint32_t base = sb;
        CPASYNC16(base + ssub,                   (const char*)(Abh + gA));
        if (NT >= 2) CPASYNC16(base + PLANE_BYTES + ssub, (const char*)(Abl + gA));
        CPASYNC16(base + 2*PLANE_BYTES + ssub,   (const char*)(Bbh + gB));
        if (NT >= 3) CPASYNC16(base + 3*PLANE_BYTES + ssub, (const char*)(Bbl + gB));
        CP_COMMIT();
    }

    const uint32_t aoff = (uint32_t)(lane & 15) * ROW_BYTES + (lane >> 4) * 16;
    const int nrow  = (lane & 7) + ((lane >> 4) << 3);
    const int khalf = (lane >> 3) & 1;
    const uint32_t boff = (uint32_t)nrow * ROW_BYTES + khalf * 16;

    for (int s = 0; s < nStages; s++) {
        if (s + 1 < nStages) {
            uint32_t base = sb + ((s + 1) & 1) * STAGE_BYTES;
            long k0 = (long)(s + 1) << 4;
            CPASYNC16(base + ssub,                 (const char*)(Abh + gA + k0));
            if (NT >= 2) CPASYNC16(base + PLANE_BYTES + ssub, (const char*)(Abl + gA + k0));
            CPASYNC16(base + 2*PLANE_BYTES + ssub, (const char*)(Bbh + gB + k0));
            if (NT >= 3) CPASYNC16(base + 3*PLANE_BYTES + ssub, (const char*)(Bbl + gB + k0));
            CP_COMMIT();
            CP_WAIT1();
        } else {
            CP_WAIT0();
        }
        __syncthreads();

        const uint32_t base = sb + (s & 1) * STAGE_BYTES;
        uint32_t ah[4][4], al[4][4];
        #pragma unroll
        for (int mi = 0; mi < 4; mi++) {
            uint32_t o = base + (uint32_t)(wm * 64 + mi * 16) * ROW_BYTES + aoff;
            LDSM4(ah[mi], o);
            if (NT >= 2) LDSM4(al[mi], o + PLANE_BYTES);
        }
        uint32_t bh[2][4], bl[2][4];
        #pragma unroll
        for (int p = 0; p < 2; p++) {
            uint32_t o = base + 2*PLANE_BYTES + (uint32_t)(wn * 32 + p * 16) * ROW_BYTES + boff;
            LDSM4(bh[p], o);
            if (NT >= 3) LDSM4(bl[p], o + PLANE_BYTES);
        }
        #pragma unroll
        for (int mi = 0; mi < 4; mi++)
            #pragma unroll
            for (int p = 0; p < 2; p++)
                #pragma unroll
                for (int s2 = 0; s2 < 2; s2++) {
                    const int ni = p * 2 + s2;
                    mma16816(acc[mi][ni], ah[mi], &bh[p][s2 * 2]);
                    if (NT >= 2) mma16816(acc[mi][ni], al[mi], &bh[p][s2 * 2]);
                    if (NT >= 3) mma16816(acc[mi][ni], ah[mi], &bl[p][s2 * 2]);
                }
        __syncthreads();
    }

    const int er = mBase + wm * 64 + (lane >> 2);
    const int ec = nBase + wn * 32 + (lane & 3) * 2;

    float zac[4][2];
    if (EPI == 1 && rowZ) {
        #pragma unroll
        for (int mi = 0; mi < 4; mi++) { zac[mi][0] = 0.f; zac[mi][1] = 0.f; }
    }

    #pragma unroll
    for (int mi = 0; mi < 4; mi++) {
        #pragma unroll
        for (int ni = 0; ni < 4; ni++) {
            const int gc = ec + ni * 8;
            float b0 = 0.f, b1 = 0.f;
            if (biasb) { b0 = __ldg(&biasb[gc]); b1 = __ldg(&biasb[gc + 1]); }
            #pragma unroll
            for (int half = 0; half < 2; half++) {
                const int gr = er + mi * 16 + half * 8;
                float v0 = acc[mi][ni][half * 2 + 0] * alpha + b0;
                float v1 = acc[mi][ni][half * 2 + 1] * alpha + b1;
                if (EPI == 4) {
                    const long zb = (long)z * ((long)BB * Dm * TT)
                                  + (long)(gr >> 10) * ((long)Dm * TT);
                    const long t = gr & 1023;
                    long a0 = zb + (long)gc * TT + t;
                    long a1 = zb + (long)(gc + 1) * TT + t;
                    bf16 h0 = __float2bfloat16_rn(v0);
                    bf16 h1 = __float2bfloat16_rn(v1);
                    Ch[a0] = h0;
                    Ch[a1] = h1;
                    if (!HIONLY) {
                        Cl[a0] = __float2bfloat16_rn(v0 - __bfloat162float(h0));
                        Cl[a1] = __float2bfloat16_rn(v1 - __bfloat162float(h1));
                    }
                } else {
                    const long baseo = coff + (long)gr * ldc + gc;
                    if (EPI & 1) {
                        float2 f; f.x = v0; f.y = v1;
                        *(float2*)(Cf + baseo) = f;
                        if (rowZ) zac[mi][half] += __expf(v0) + __expf(v1);
                    }
                    if (EPI & 2) {
                        bf16 h0 = __float2bfloat16_rn(v0);
                        bf16 h1 = __float2bfloat16_rn(v1);
                        uint16_t a16 = *(uint16_t*)&h0, b16v = *(uint16_t*)&h1;
                        *(uint32_t*)(Ch + baseo) = (uint32_t)a16 | ((uint32_t)b16v << 16);
                        if (!HIONLY) {
                            bf16 l0 = __float2bfloat16_rn(v0 - __bfloat162float(h0));
                            bf16 l1 = __float2bfloat16_rn(v1 - __bfloat162float(h1));
                            uint16_t c16 = *(uint16_t*)&l0, d16 = *(uint16_t*)&l1;
                            *(uint32_t*)(Cl + baseo) = (uint32_t)c16 | ((uint32_t)d16 << 16);
                        }
                    }
                }
            }
        }
    }

    if (EPI == 1 && rowZ) {
        #pragma unroll
        for (int mi = 0; mi < 4; mi++)
            #pragma unroll
            for (int half = 0; half < 2; half++) {
                float ssum = zac[mi][half];
                ssum += __shfl_xor_sync(0xffffffffu, ssum, 1);
                ssum += __shfl_xor_sync(0xffffffffu, ssum, 2);
                if ((lane & 3) == 0)
                    atomicAdd(&rowZ[(long)z * sZ + er + mi * 16 + half * 8], ssum);
            }
    }
}

// ============ fused softmax + P@z GEMM, 1-term: ph*zh ============
#define PZ_AF(s)   ((uint32_t)((s) * 8192))
#define PZ_AH(s)   ((uint32_t)(16384 + (s) * PLANE_BYTES))
#define PZ_BH(s)   ((uint32_t)(28672 + (s) * PLANE_BYTES))
#define PZ_SMEM    40960

__global__ void __launch_bounds__(256)
gemm_pz(const float* __restrict__ S, const float* __restrict__ rc,
        const bf16* __restrict__ Bh,
        float* __restrict__ Cf)
{
    extern __shared__ char smem[];
    const uint32_t sb = smem_u32(smem);
    const int tid = threadIdx.x, lane = tid & 31, wid = tid >> 5;
    const int wm = wid >> 2, wn = wid & 3;
    const int z = blockIdx.z;

    const float* Ab = S + (long)z * TT * TT;
    const bf16* Bbh = Bh + (long)z * Dm * TT;
    const long coff = (long)z * TT * Dm;
    const int mBase = blockIdx.y * 128;
    const int nBase = blockIdx.x * 128;

    const int lrow = tid >> 1;
    const uint32_t ssubB = (uint32_t)lrow * ROW_BYTES + (tid & 1) * 16;
    const long gB = (long)(nBase + lrow) * TT + (tid & 1) * 8;
    const int ar0 = tid >> 2, ac0 = (tid & 3) * 4;
    const int ar1 = (tid + 256) >> 2, ac1 = ((tid + 256) & 3) * 4;
    const long gA0 = (long)(mBase + ar0) * TT + ac0;
    const long gA1 = (long)(mBase + ar1) * TT + ac1;
    const uint32_t sA0 = (uint32_t)ar0 * 64 + (tid & 3) * 16;
    const uint32_t sA1 = (uint32_t)ar1 * 64 + ((tid + 256) & 3) * 16;

    const int crow = tid >> 1, ck = (tid & 1) * 8;
    const float cinv = 1.f / __ldg(&rc[(long)z * TT + mBase + crow]);

    float acc[4][4][4];
    #pragma unroll
    for (int i = 0; i < 4; i++)
        #pragma unroll
        for (int j = 0; j < 4; j++)
            #pragma unroll
            for (int r = 0; r < 4; r++) acc[i][j][r] = 0.f;

    const int nStages = TT >> 4;

    auto issue_cp = [&](int s) {
        const uint32_t bsel = (uint32_t)(s & 1);
        const long k0 = (long)s << 4;
        CPASYNC16(sb + PZ_AF(bsel) + sA0, (const char*)(Ab + gA0 + k0));
        CPASYNC16(sb + PZ_AF(bsel) + sA1, (const char*)(Ab + gA1 + k0));
        CPASYNC16(sb + PZ_BH(bsel) + ssubB, (const char*)(Bbh + gB + k0));
        CP_COMMIT();
    };
    auto convert = [&](int s) {
        const uint32_t bsel = (uint32_t)(s & 1);
        const float* af = (const float*)(smem + PZ_AF(bsel) + (uint32_t)crow * 64);
        bf16* ahp = (bf16*)(smem + PZ_AH(bsel) + (uint32_t)crow * ROW_BYTES);
        #pragma unroll
        for (int j = 0; j < 8; j += 2) {
            float e0 = __expf(af[ck + j])     * cinv;
            float e1 = __expf(af[ck + j + 1]) * cinv;
            bf16 h0 = __float2bfloat16_rn(e0);
            bf16 h1 = __float2bfloat16_rn(e1);
            uint16_t u0 = *(uint16_t*)&h0, u1 = *(uint16_t*)&h1;
            *(uint32_t*)(ahp + ck + j) = (uint32_t)u0 | ((uint32_t)u1 << 16);
        }
    };

    const uint32_t aoff = (uint32_t)(lane & 15) * ROW_BYTES + (lane >> 4) * 16;
    const int nrow  = (lane & 7) + ((lane >> 4) << 3);
    const int khalf = (lane >> 3) & 1;
    const uint32_t boff = (uint32_t)nrow * ROW_BYTES + khalf * 16;

    issue_cp(0);
    issue_cp(1);
    CP_WAIT1();
    __syncthreads();
    convert(0);
    __syncthreads();

    for (int s = 0; s < nStages; s++) {
        const uint32_t base = (uint32_t)(s & 1);
        uint32_t ah[4][4];
        #pragma unroll
        for (int mi = 0; mi < 4; mi++) {
            uint32_t o = sb + PZ_AH(base) + (uint32_t)(wm * 64 + mi * 16) * ROW_BYTES + aoff;
            LDSM4(ah[mi], o);
        }
        uint32_t bh[2][4];
        #pragma unroll
        for (int p = 0; p < 2; p++) {
            uint32_t o = sb + PZ_BH(base) + (uint32_t)(wn * 32 + p * 16) * ROW_BYTES + boff;
            LDSM4(bh[p], o);
        }
        #pragma unroll
        for (int mi = 0; mi < 4; mi++)
            #pragma unroll
            for (int p = 0; p < 2; p++)
                #pragma unroll
                for (int s2 = 0; s2 < 2; s2++) {
                    const int ni = p * 2 + s2;
                    mma16816(acc[mi][ni], ah[mi], &bh[p][s2 * 2]);
                }
        if (s + 2 < nStages) issue_cp(s + 2);
        if (s + 1 < nStages) {
            if (s + 2 < nStages) { CP_WAIT1(); } else { CP_WAIT0(); }
            __syncthreads();
            convert(s + 1);
            __syncthreads();
        }
    }

    const int er = mBase + wm * 64 + (lane >> 2);
    const int ec = nBase + wn * 32 + (lane & 3) * 2;
    #pragma unroll
    for (int mi = 0; mi < 4; mi++)
        #pragma unroll
        for (int ni = 0; ni < 4; ni++)
            #pragma unroll
            for (int half = 0; half < 2; half++) {
                const int gr = er + mi * 16 + half * 8;
                const int gc = ec + ni * 8;
                float2 f;
                f.x = acc[mi][ni][half * 2 + 0];
                f.y = acc[mi][ni][half * 2 + 1];
                *(float2*)(Cf + coff + (long)gr * Dm + gc) = f;
            }
}

// ---------------- transpose + split ----------------
__global__ void __launch_bounds__(256)
tsplit(const float* __restrict__ in, bf16* __restrict__ oh, bf16* __restrict__ ol,
       int R, int C)
{
    __shared__ float t[32][33];
    const int cb = blockIdx.x * 32, rb = blockIdx.y * 32;
    const int x = threadIdx.x & 31, y = threadIdx.x >> 5;
    #pragma unroll
    for (int i = 0; i < 32; i += 8)
        t[y + i][x] = in[(long)(rb + y + i) * C + cb + x];
    __syncthreads();
    #pragma unroll
    for (int i = 0; i < 32; i += 8) {
        float v = t[x][y + i];
        bf16 h = __float2bfloat16_rn(v);
        long o = (long)(cb + y + i) * R + rb + x;
        oh[o] = h;
        ol[o] = __float2bfloat16_rn(v - __bfloat162float(h));
    }
}

// ---------------- elementwise split ----------------
__global__ void __launch_bounds__(256)
esplit(const float* __restrict__ in, bf16* __restrict__ oh, bf16* __restrict__ ol, int n)
{
    int i = blockIdx.x * 256 + threadIdx.x;
    if (i < n) {
        float v = in[i];
        bf16 h = __float2bfloat16_rn(v);
        oh[i] = h;
        ol[i] = __float2bfloat16_rn(v - __bfloat162float(h));
    }
}

// ---------------- elementwise hi-only convert (x -> xh) ----------------
__global__ void __launch_bounds__(256)
ehalf(const float* __restrict__ in, bf16* __restrict__ oh, int n)
{
    int i = (blockIdx.x * 256 + threadIdx.x) * 4;
    if (i < n) {
        float4 v = *(const float4*)(in + i);
        bf16 h0 = __float2bfloat16_rn(v.x), h1 = __float2bfloat16_rn(v.y);
        bf16 h2 = __float2bfloat16_rn(v.z), h3 = __float2bfloat16_rn(v.w);
        uint16_t a = *(uint16_t*)&h0, b = *(uint16_t*)&h1;
        uint16_t c = *(uint16_t*)&h2, d = *(uint16_t*)&h3;
        uint2 p;
        p.x = (uint32_t)a | ((uint32_t)b << 16);
        p.y = (uint32_t)c | ((uint32_t)d << 16);
        *(uint2*)(oh + i) = p;
    }
}

// ---------------- zero kernel ----------------
__global__ void __launch_bounds__(256)
zerok(float* __restrict__ p, int n)
{
    int i = blockIdx.x * 256 + threadIdx.x;
    if (i < n) p[i] = 0.f;
}

// ---------------- vecprep ----------------
__global__ void __launch_bounds__(256)
vecprep(const float* __restrict__ Wk, const float* __restrict__ bq,
        const float* __restrict__ Wo, const float* __restrict__ bv,
        float* __restrict__ w0, float* __restrict__ ccp)
{
    const int bb = blockIdx.x;
    if (bb < 512) {
        const int wid = threadIdx.x >> 5, lane = threadIdx.x & 31;
        const int idx = bb * 8 + wid;
        const int h = idx >> 9, d = idx & 511;
        const float* wr = Wk + (long)h * Dm * Dm + (long)d * Dm;
        const float* bqr = bq + h * Dm;
        float s = 0.f;
        #pragma unroll
        for (int e = lane; e < Dm; e += 32) s += wr[e] * bqr[e];
        #pragma unroll
        for (int o = 16; o; o >>= 1) s += __shfl_xor_sync(0xffffffffu, s, o);
        if (lane == 0) w0[idx] = s;
    } else {
        __shared__ float part[4][64];
        const int ib = bb - 512;
        const int h = ib >> 3, chunk = ib & 7;
        const int e = chunk * 64 + (threadIdx.x & 63);
        const int ms = threadIdx.x >> 6;
        const float* Woh = Wo + (long)h * Dm * Dm;
        const float* bvh = bv + h * Dm;
        float s = 0.f;
        for (int m = ms * 128; m < ms * 128 + 128; m++)
            s += bvh[m] * Woh[(long)m * Dm + e];
        part[ms][threadIdx.x & 63] = s;
        __syncthreads();
        if (threadIdx.x < 64)
            ccp[h * Dm + chunk * 64 + threadIdx.x] =
                part[0][threadIdx.x] + part[1][threadIdx.x] +
                part[2][threadIdx.x] + part[3][threadIdx.x];
    }
}

// ---------------- block reductions ----------------
__device__ __forceinline__ float block_sum(float v, float* sm) {
    #pragma unroll
    for (int o = 16; o; o >>= 1) v += __shfl_xor_sync(0xffffffffu, v, o);
    if ((threadIdx.x & 31) == 0) sm[threadIdx.x >> 5] = v;
    __syncthreads();
    if (threadIdx.x < 8) {
        float s = sm[threadIdx.x];
        #pragma unroll
        for (int o = 4; o; o >>= 1) s += __shfl_xor_sync(0xffu, s, o);
        if (threadIdx.x == 0) sm[0] = s;
    }
    __syncthreads();
    float r = sm[0];
    __syncthreads();
    return r;
}

// ---------------- reduce heads + cc + residual + LN1 -> y1 (fp32 + planes) ----------------
__global__ void __launch_bounds__(256)
reduce_ln1(const float* __restrict__ parts, const float* __restrict__ x,
           const float* __restrict__ ccp, const float* __restrict__ bo,
           const float* __restrict__ g, const float* __restrict__ be,
           float* __restrict__ out, bf16* __restrict__ oh, bf16* __restrict__ ol)
{
    __shared__ float sm[8];
    const long row = blockIdx.x;
    const long b = row >> 10, t0 = row & 1023;
    const int t = threadIdx.x;
    float v0, v1;
    {
        float c0 = bo[t], c1 = bo[t + 256];
        #pragma unroll
        for (int h = 0; h < HH; h++) {
            c0 += ccp[h * Dm + t];
            c1 += ccp[h * Dm + t + 256];
        }
        v0 = x[row * Dm + t] + c0;
        v1 = x[row * Dm + t + 256] + c1;
        #pragma unroll
        for (int h = 0; h < HH; h++) {
            const long pr = (((long)h * BB + b) * TT + t0) * Dm;
            v0 += parts[pr + t];
            v1 += parts[pr + t + 256];
        }
    }
    float mean = block_sum(v0 + v1, sm) * (1.f / Dm);
    float d0 = v0 - mean, d1 = v1 - mean;
    float var = block_sum(d0 * d0 + d1 * d1, sm) * (1.f / Dm);
    float inv = rsqrtf(var + EPSv);
    float o0 = d0 * inv * g[t] + be[t];
    float o1 = d1 * inv * g[t + 256] + be[t + 256];
    out[row * Dm + t] = o0;
    out[row * Dm + t + 256] = o1;
    bf16 h0 = __float2bfloat16_rn(o0), h1 = __float2bfloat16_rn(o1);
    oh[row * Dm + t] = h0;
    oh[row * Dm + t + 256] = h1;
    ol[row * Dm + t] = __float2bfloat16_rn(o0 - __bfloat162float(h0));
    ol[row * Dm + t + 256] = __float2bfloat16_rn(o1 - __bfloat162float(h1));
}

// ---------------- relu + residual + LN2 ----------------
__global__ void __launch_bounds__(256)
add_ln2_kernel(const float* __restrict__ a, const float* __restrict__ res,
               const float* __restrict__ g, const float* __restrict__ be,
               float* __restrict__ out)
{
    __shared__ float sm[8];
    long row = blockIdx.x;
    const float* ap = a + row * Dm;
    const float* rp = res + row * Dm;
    int t = threadIdx.x;
    float v0 = fmaxf(ap[t], 0.f) + rp[t];
    float v1 = fmaxf(ap[t + 256], 0.f) + rp[t + 256];
    float mean = block_sum(v0 + v1, sm) * (1.f / Dm);
    float d0 = v0 - mean, d1 = v1 - mean;
    float var = block_sum(d0 * d0 + d1 * d1, sm) * (1.f / Dm);
    float inv = rsqrtf(var + EPSv);
    out[row * Dm + t]       = d0 * inv * g[t]       + be[t];
    out[row * Dm + t + 256] = d1 * inv * g[t + 256] + be[t + 256];
}

// ---------------- stream / event resources (created at load, before checkpoints) ----------------
struct StreamInit {
    cudaStream_t s1, s2;
    cudaEvent_t eF, eM, eB, eV;
    StreamInit() {
        cudaStreamCreateWithFlags(&s1, cudaStreamNonBlocking);
        cudaStreamCreateWithFlags(&s2, cudaStreamNonBlocking);
        cudaEventCreateWithFlags(&eF, cudaEventDisableTiming);
        cudaEventCreateWithFlags(&eM, cudaEventDisableTiming);
        cudaEventCreateWithFlags(&eB, cudaEventDisableTiming);
        cudaEventCreateWithFlags(&eV, cudaEventDisableTiming);
    }
};
static StreamInit g_si;

// ---------------- launch ----------------
extern "C" void kernel_launch(void* const* d_in, const int* in_sizes, int n_in,
                              void* d_out, int out_size)
{
    const float* x    = (const float*)d_in[0];
    const float* Wq   = (const float*)d_in[1];
    const float* bq   = (const float*)d_in[2];
    const float* Wk   = (const float*)d_in[3];
    const float* Wv   = (const float*)d_in[5];
    const float* bv   = (const float*)d_in[6];
    const float* Wo   = (const float*)d_in[7];
    const float* bo   = (const float*)d_in[8];
    const float* ln1g = (const float*)d_in[9];
    const float* ln1b = (const float*)d_in[10];
    const float* W1   = (const float*)d_in[11];
    const float* b1   = (const float*)d_in[12];
    const float* W2   = (const float*)d_in[13];
    const float* b2   = (const float*)d_in[14];
    const float* ln2g = (const float*)d_in[15];
    const float* ln2b = (const float*)d_in[16];
    float* out = (float*)d_out;

    bf16 *xh, *Wqh, *Wql, *Wkh, *Wkl, *Wvh, *Wvl, *WoTh, *WoTl;
    bf16 *W1Th, *W1Tl, *W2Th, *W2Tl, *Mth, *Nth;
    bf16 *uh, *zth, *y1h, *y1l, *f1h, *f1l;
    float *w0, *ccp, *ps, *rc, *parts, *py1, *pff2;
    cudaGetSymbolAddress((void**)&xh, g_xh);
    cudaGetSymbolAddress((void**)&Wqh, g_Wqh);   cudaGetSymbolAddress((void**)&Wql, g_Wql);
    cudaGetSymbolAddress((void**)&Wkh, g_Wkh);   cudaGetSymbolAddress((void**)&Wkl, g_Wkl);
    cudaGetSymbolAddress((void**)&Wvh, g_Wvh);   cudaGetSymbolAddress((void**)&Wvl, g_Wvl);
    cudaGetSymbolAddress((void**)&WoTh, g_WoTh); cudaGetSymbolAddress((void**)&WoTl, g_WoTl);
    cudaGetSymbolAddress((void**)&W1Th, g_W1Th); cudaGetSymbolAddress((void**)&W1Tl, g_W1Tl);
    cudaGetSymbolAddress((void**)&W2Th, g_W2Th); cudaGetSymbolAddress((void**)&W2Tl, g_W2Tl);
    cudaGetSymbolAddress((void**)&Mth, g_Mth);
    cudaGetSymbolAddress((void**)&Nth, g_Nth);
    cudaGetSymbolAddress((void**)&w0, g_w0);     cudaGetSymbolAddress((void**)&ccp, g_ccp);
    cudaGetSymbolAddress((void**)&uh, g_uh);
    cudaGetSymbolAddress((void**)&zth, g_zth);
    cudaGetSymbolAddress((void**)&ps, g_s);      cudaGetSymbolAddress((void**)&rc, g_rc);
    cudaGetSymbolAddress((void**)&parts, g_parts);
    cudaGetSymbolAddress((void**)&py1, g_y1);
    cudaGetSymbolAddress((void**)&y1h, g_y1h);   cudaGetSymbolAddress((void**)&y1l, g_y1l);
    cudaGetSymbolAddress((void**)&f1h, g_f1h);   cudaGetSymbolAddress((void**)&f1l, g_f1l);
    cudaGetSymbolAddress((void**)&pff2, g_ff2);

    cudaFuncSetAttribute(gemm_pz, cudaFuncAttributeMaxDynamicSharedMemorySize, PZ_SMEM);

    const float inv_sqrt_d = 0.044194173824159216f;
    const long DD = (long)Dm * Dm;

    // detect the capturing (or main) stream
    cudaStream_t cap = cudaStreamLegacy;
    {
        cudaStreamCaptureStatus st = cudaStreamCaptureStatusNone;
        cudaStreamIsCapturing(cudaStreamPerThread, &st);
        if (st == cudaStreamCaptureStatusActive) cap = cudaStreamPerThread;
    }
    cudaStream_t s1 = g_si.s1;
    cudaStream_t s2 = g_si.s2;

    // ---- fork: weight-prep on s1, vecprep on s2, x chain on cap ----
    cudaEventRecord(g_si.eF, cap);
    cudaStreamWaitEvent(s1, g_si.eF, 0);
    cudaStreamWaitEvent(s2, g_si.eF, 0);

    // s2: vecprep
    vecprep<<<576, 256, 0, s2>>>(Wk, bq, Wo, bv, w0, ccp);
    cudaEventRecord(g_si.eV, s2);

    // s1: Mt chain first (gates u-GEMM)
    esplit<<<(HH * Dm * Dm + 255) / 256, 256, 0, s1>>>(Wq, Wqh, Wql, HH * Dm * Dm);
    esplit<<<(HH * Dm * Dm + 255) / 256, 256, 0, s1>>>(Wk, Wkh, Wkl, HH * Dm * Dm);
    gemm_mma<2, 3, 1><<<dim3(4, 4, HH), 256, SMEM_BYTES, s1>>>(Wkh, Wkl, Wqh, Wql, nullptr,
        nullptr, Mth, nullptr, Dm, Dm, Dm, Dm, DD, DD, 0, 0L, 1, DD, 0L, 1.f, nullptr, 0L);
    cudaEventRecord(g_si.eM, s1);
    // s1: remaining weight prep
    esplit<<<(HH * Dm * Dm + 255) / 256, 256, 0, s1>>>(Wv, Wvh, Wvl, HH * Dm * Dm);
    tsplit<<<dim3(Dm / 32, (HH * Dm) / 32), 256, 0, s1>>>(Wo, WoTh, WoTl, HH * Dm, Dm);
    gemm_mma<2, 3, 1><<<dim3(4, 4, HH), 256, SMEM_BYTES, s1>>>(WoTh, WoTl, Wvh, Wvl, nullptr,
        nullptr, Nth, nullptr, Dm, HH * Dm, Dm, Dm, (long)Dm, DD, 0, 0L, 1, DD, 0L, 1.f, nullptr, 0L);
    tsplit<<<dim3(DFFm / 32, Dm / 32), 256, 0, s1>>>(W1, W1Th, W1Tl, Dm, DFFm);
    tsplit<<<dim3(Dm / 32, DFFm / 32), 256, 0, s1>>>(W2, W2Th, W2Tl, DFFm, Dm);
    zerok<<<(HH * BB * TT + 255) / 256, 256, 0, s1>>>(rc, HH * BB * TT);
    cudaEventRecord(g_si.eB, s1);

    // cap: x chain (hi-only convert; xl is never consumed anymore)
    ehalf<<<(BT * Dm / 4 + 255) / 256, 256, 0, cap>>>(x, xh, BT * Dm);
    cudaStreamWaitEvent(cap, g_si.eM, 0);
    cudaStreamWaitEvent(cap, g_si.eV, 0);

    // u = x @ M_h + w0_h  (1-term: xh*Mth; hi-only output)
    gemm_mma<2, 1, 1><<<dim3(4, BT / 128, HH), 256, SMEM_BYTES, cap>>>(xh, nullptr, Mth, nullptr,
        w0, nullptr, uh, nullptr, Dm, Dm, Dm, Dm, 0L, DD, 0, (long)Dm, 1, (long)BT * Dm, 0L, 1.f,
        nullptr, 0L);

    cudaStreamWaitEvent(cap, g_si.eB, 0);

    // z^T = (x @ N_h)^T -> [H,B,D,T]  (1-term: xh*Nth; hi-only output)
    gemm_mma<4, 1, 1><<<dim3(4, BT / 128, HH), 256, SMEM_BYTES, cap>>>(xh, nullptr, Nth, nullptr,
        nullptr, nullptr, zth, nullptr, Dm, Dm, Dm, 0, 0L, DD, 0, 0L, 1, 0L, 0L, 1.f, nullptr, 0L);

    // scores = u @ x^T * 1/sqrt(D)  (1-term: uh*xh) + fused row-sum of exp
    gemm_mma<1, 1, 0><<<dim3(TT / 128, TT / 128, HH * BB), 256, SMEM_BYTES, cap>>>(uh, nullptr,
        xh, nullptr, nullptr, ps, nullptr, nullptr, Dm, Dm, Dm, TT,
        (long)TT * Dm, (long)TT * Dm, BB, 0L, 1, (long)TT * TT, 0L, inv_sqrt_d,
        rc, (long)TT);

    // parts = softmax(scores) @ z  (fused exp/Z; 1-term ph*zh)
    gemm_pz<<<dim3(Dm / 128, TT / 128, HH * BB), 256, PZ_SMEM, cap>>>(ps, rc, zth, parts);

    // y1 = LN(sum_h parts + cc + bo + x)
    reduce_ln1<<<BT, 256, 0, cap>>>(parts, x, ccp, bo, ln1g, ln1b, py1, y1h, y1l);

    // FFN1 -> f1 planes (full 3-term)
    gemm_mma<2, 3, 0><<<dim3(DFFm / 128, BT / 128, 1), 256, SMEM_BYTES, cap>>>(y1h, y1l, W1Th, W1Tl,
        b1, nullptr, f1h, f1l, Dm, Dm, Dm, DFFm, 0L, 0L, 0, 0L, 1, 0L, 0L, 1.f, nullptr, 0L);

    // FFN2 -> ff2 fp32 (full 3-term)
    gemm_mma<1, 3, 0><<<dim3(Dm / 128, BT / 128, 1), 256, SMEM_BYTES, cap>>>(f1h, f1l, W2Th, W2Tl,
        b2, pff2, nullptr, nullptr, DFFm, DFFm, DFFm, Dm, 0L, 0L, 0, 0L, 1, 0L, 0L, 1.f,
        nullptr, 0L);

    // out = LN(relu(ff2) + y1)
    add_ln2_kernel<<<BT, 256, 0, cap>>>(pff2, py1, ln2g, ln2b, out);
}